// round 1
// baseline (speedup 1.0000x reference)
#include <cuda_runtime.h>
#include <math.h>

// Problem constants
#define Bsz   4
#define Lseq  4096
#define Dmod  1024
#define Hn    16
#define HDim  64
#define CH    128
#define NCH   32
#define Mrows (Bsz*Lseq)          // 16384
#define EPSC  1e-12f

// Scratch (device globals — allocation-free per harness rules)
__device__ float g_q[(size_t)Bsz*Hn*Lseq*HDim];     // (b,h,l,d) 64 MB
__device__ float g_k[(size_t)Bsz*Hn*Lseq*HDim];
__device__ float g_v[(size_t)Bsz*Hn*Lseq*HDim];
__device__ float g_attn[(size_t)Bsz*Lseq*Dmod];     // (b,l,D) row-major, feeds Wo GEMM

// ---------------------------------------------------------------------------
// SGEMM: C[m][n] = sum_k A[m][k] * W[n][k]   (both row-major, K=1024)
// 128x128 tile, BK=8, 256 threads, 8x8 per thread.
// ---------------------------------------------------------------------------
#define BM 128
#define BN 128
#define BKK 8

__global__ __launch_bounds__(256) void sgemm_qkv(const float* __restrict__ X,
                                                 const float* __restrict__ Wq,
                                                 const float* __restrict__ Wk,
                                                 const float* __restrict__ Wv) {
    __shared__ __align__(16) float As[BKK][BM + 4];
    __shared__ __align__(16) float Bs[BKK][BN + 4];

    const int w = blockIdx.z;
    const float* Wm = (w == 0) ? Wq : (w == 1) ? Wk : Wv;
    float* outp     = (w == 0) ? g_q : (w == 1) ? g_k : g_v;

    const int tid = threadIdx.x;
    const int rowBase = blockIdx.y * BM;
    const int colBase = blockIdx.x * BN;
    const int tr = tid >> 4;          // 0..15
    const int tc = tid & 15;          // 0..15
    const int lr = tid >> 1;          // 0..127
    const int lc = (tid & 1) * 4;     // 0 or 4

    const float* Ap = X  + (size_t)(rowBase + lr) * Dmod + lc;
    const float* Bp = Wm + (size_t)(colBase + lr) * Dmod + lc;

    float acc[8][8];
    #pragma unroll
    for (int i = 0; i < 8; ++i)
        #pragma unroll
        for (int j = 0; j < 8; ++j) acc[i][j] = 0.f;

    for (int kt = 0; kt < Dmod; kt += BKK) {
        float4 a4 = *(const float4*)(Ap + kt);
        float4 b4 = *(const float4*)(Bp + kt);
        As[lc + 0][lr] = a4.x; As[lc + 1][lr] = a4.y;
        As[lc + 2][lr] = a4.z; As[lc + 3][lr] = a4.w;
        Bs[lc + 0][lr] = b4.x; Bs[lc + 1][lr] = b4.y;
        Bs[lc + 2][lr] = b4.z; Bs[lc + 3][lr] = b4.w;
        __syncthreads();
        #pragma unroll
        for (int k = 0; k < BKK; ++k) {
            float ra[8], rb[8];
            *(float4*)&ra[0] = *(const float4*)&As[k][tr * 8];
            *(float4*)&ra[4] = *(const float4*)&As[k][tr * 8 + 4];
            *(float4*)&rb[0] = *(const float4*)&Bs[k][tc * 8];
            *(float4*)&rb[4] = *(const float4*)&Bs[k][tc * 8 + 4];
            #pragma unroll
            for (int i = 0; i < 8; ++i)
                #pragma unroll
                for (int j = 0; j < 8; ++j) acc[i][j] += ra[i] * rb[j];
        }
        __syncthreads();
    }

    // Epilogue: write to (b,h,l,d) layout; elu(x)+1 for q,k.
    const int n0 = colBase + tc * 8;         // 8 consecutive n, never cross h (64) boundary
    const int hh = n0 >> 6;
    const int dd = n0 & 63;
    #pragma unroll
    for (int i = 0; i < 8; ++i) {
        const int m  = rowBase + tr * 8 + i;
        const int bb = m >> 12;              // /Lseq
        const int ll = m & (Lseq - 1);
        float* dst = outp + (((size_t)(bb * Hn + hh) * Lseq + ll) * HDim + dd);
        #pragma unroll
        for (int j = 0; j < 8; ++j) {
            float v = acc[i][j];
            if (w < 2) v = (v > 0.f) ? (v + 1.f) : expf(v);  // elu(x)+1
            dst[j] = v;
        }
    }
}

__global__ __launch_bounds__(256) void sgemm_out(const float* __restrict__ Wo,
                                                 float* __restrict__ Out) {
    __shared__ __align__(16) float As[BKK][BM + 4];
    __shared__ __align__(16) float Bs[BKK][BN + 4];

    const int tid = threadIdx.x;
    const int rowBase = blockIdx.y * BM;
    const int colBase = blockIdx.x * BN;
    const int tr = tid >> 4;
    const int tc = tid & 15;
    const int lr = tid >> 1;
    const int lc = (tid & 1) * 4;

    const float* Ap = g_attn + (size_t)(rowBase + lr) * Dmod + lc;
    const float* Bp = Wo     + (size_t)(colBase + lr) * Dmod + lc;

    float acc[8][8];
    #pragma unroll
    for (int i = 0; i < 8; ++i)
        #pragma unroll
        for (int j = 0; j < 8; ++j) acc[i][j] = 0.f;

    for (int kt = 0; kt < Dmod; kt += BKK) {
        float4 a4 = *(const float4*)(Ap + kt);
        float4 b4 = *(const float4*)(Bp + kt);
        As[lc + 0][lr] = a4.x; As[lc + 1][lr] = a4.y;
        As[lc + 2][lr] = a4.z; As[lc + 3][lr] = a4.w;
        Bs[lc + 0][lr] = b4.x; Bs[lc + 1][lr] = b4.y;
        Bs[lc + 2][lr] = b4.z; Bs[lc + 3][lr] = b4.w;
        __syncthreads();
        #pragma unroll
        for (int k = 0; k < BKK; ++k) {
            float ra[8], rb[8];
            *(float4*)&ra[0] = *(const float4*)&As[k][tr * 8];
            *(float4*)&ra[4] = *(const float4*)&As[k][tr * 8 + 4];
            *(float4*)&rb[0] = *(const float4*)&Bs[k][tc * 8];
            *(float4*)&rb[4] = *(const float4*)&Bs[k][tc * 8 + 4];
            #pragma unroll
            for (int i = 0; i < 8; ++i)
                #pragma unroll
                for (int j = 0; j < 8; ++j) acc[i][j] += ra[i] * rb[j];
        }
        __syncthreads();
    }

    #pragma unroll
    for (int i = 0; i < 8; ++i) {
        const int m = rowBase + tr * 8 + i;
        float* dst = Out + (size_t)m * Dmod + colBase + tc * 8;
        *(float4*)dst       = make_float4(acc[i][0], acc[i][1], acc[i][2], acc[i][3]);
        *(float4*)(dst + 4) = make_float4(acc[i][4], acc[i][5], acc[i][6], acc[i][7]);
    }
}

// ---------------------------------------------------------------------------
// Chunked causal linear attention.
// One block per (b,h). 128 threads, thread t = query row t within the chunk.
// S (64x64) + z (64) carried in SMEM across 32 chunks.
// ---------------------------------------------------------------------------
#define PAD 68
#define ATTN_SMEM_FLOATS (64*PAD + 64 + 3*128*PAD)
#define ATTN_SMEM_BYTES  (ATTN_SMEM_FLOATS * 4)

__global__ __launch_bounds__(128) void attn_kernel() {
    extern __shared__ __align__(16) float sm[];
    float* S  = sm;                     // 64*68
    float* z  = sm + 64 * PAD;          // 64
    float* qb = z + 64;                 // 128*68
    float* kb = qb + 128 * PAD;
    float* vb = kb + 128 * PAD;

    const int tid = threadIdx.x;        // 0..127
    const int bh  = blockIdx.x;         // 0..63

    // zero S and z
    for (int i = tid; i < 64 * PAD + 64; i += 128) sm[i] = 0.f;

    const float* gq = g_q + (size_t)bh * Lseq * HDim;
    const float* gk = g_k + (size_t)bh * Lseq * HDim;
    const float* gv = g_v + (size_t)bh * Lseq * HDim;
    float* ga = g_attn + (size_t)(bh >> 4) * Lseq * Dmod + (size_t)(bh & 15) * HDim;

    for (int c = 0; c < NCH; ++c) {
        __syncthreads();   // covers S/z init, prior-iter kb/vb readers, S update visibility
        // cooperative coalesced loads of q/k/v chunk (128x64 each)
        {
            const float4* q4 = (const float4*)(gq + (size_t)c * CH * HDim);
            const float4* k4 = (const float4*)(gk + (size_t)c * CH * HDim);
            const float4* v4 = (const float4*)(gv + (size_t)c * CH * HDim);
            #pragma unroll
            for (int it = 0; it < 16; ++it) {
                int idx = tid + 128 * it;          // float4 index, 0..2047
                int row = idx >> 4;
                int col = (idx & 15) << 2;
                *(float4*)(qb + row * PAD + col) = q4[idx];
                *(float4*)(kb + row * PAD + col) = k4[idx];
                *(float4*)(vb + row * PAD + col) = v4[idx];
            }
        }
        __syncthreads();

        // q row into registers
        float qreg[64];
        {
            const float4* qrow = (const float4*)(qb + tid * PAD);
            #pragma unroll
            for (int j = 0; j < 16; ++j) {
                float4 t4 = qrow[j];
                qreg[4*j+0] = t4.x; qreg[4*j+1] = t4.y;
                qreg[4*j+2] = t4.z; qreg[4*j+3] = t4.w;
            }
        }

        float den = 0.f;
        #pragma unroll
        for (int d = 0; d < 64; ++d) den += qreg[d] * z[d];

        float num[64];
        #pragma unroll
        for (int e = 0; e < 64; ++e) num[e] = 0.f;

        // num += q @ S  (S is carry from previous chunks)
        #pragma unroll 4
        for (int d = 0; d < 64; ++d) {
            const float qd = qreg[d];
            const float4* Sr = (const float4*)(S + d * PAD);
            #pragma unroll
            for (int j = 0; j < 16; ++j) {
                float4 s4 = Sr[j];
                num[4*j+0] += qd * s4.x; num[4*j+1] += qd * s4.y;
                num[4*j+2] += qd * s4.z; num[4*j+3] += qd * s4.w;
            }
        }

        // in-chunk causal scores
        for (int s = 0; s < CH; ++s) {
            if (s > tid) break;
            const float4* kr = (const float4*)(kb + s * PAD);
            float sc = 0.f;
            #pragma unroll
            for (int j = 0; j < 16; ++j) {
                float4 k4 = kr[j];
                sc += qreg[4*j+0]*k4.x + qreg[4*j+1]*k4.y
                    + qreg[4*j+2]*k4.z + qreg[4*j+3]*k4.w;
            }
            den += sc;
            const float4* vr = (const float4*)(vb + s * PAD);
            #pragma unroll
            for (int j = 0; j < 16; ++j) {
                float4 v4 = vr[j];
                num[4*j+0] += sc * v4.x; num[4*j+1] += sc * v4.y;
                num[4*j+2] += sc * v4.z; num[4*j+3] += sc * v4.w;
            }
        }

        // out = num/den + eps -> g_attn (b, l, h*64+e)
        {
            const float inv = 1.f / den;
            float* dst = ga + (size_t)(c * CH + tid) * Dmod;
            #pragma unroll
            for (int j = 0; j < 16; ++j) {
                float4 o;
                o.x = num[4*j+0] * inv + EPSC;
                o.y = num[4*j+1] * inv + EPSC;
                o.z = num[4*j+2] * inv + EPSC;
                o.w = num[4*j+3] * inv + EPSC;
                ((float4*)dst)[j] = o;
            }
        }

        __syncthreads();   // all S/z readers done before update

        // S += kb^T @ vb : thread handles d = tid/2, e in [ (tid&1)*32, +32 )
        {
            const int d  = tid >> 1;
            const int e0 = (tid & 1) * 32;
            float a2[32];
            #pragma unroll
            for (int j = 0; j < 32; ++j) a2[j] = 0.f;
            for (int s = 0; s < CH; ++s) {
                const float kd = kb[s * PAD + d];
                const float4* vr = (const float4*)(vb + s * PAD + e0);
                #pragma unroll
                for (int j = 0; j < 8; ++j) {
                    float4 v4 = vr[j];
                    a2[4*j+0] += kd * v4.x; a2[4*j+1] += kd * v4.y;
                    a2[4*j+2] += kd * v4.z; a2[4*j+3] += kd * v4.w;
                }
            }
            float* Srow = S + d * PAD + e0;
            #pragma unroll
            for (int j = 0; j < 32; ++j) Srow[j] += a2[j];
        }

        // z += column sums of kb
        if (tid < 64) {
            float zs = 0.f;
            for (int s = 0; s < CH; ++s) zs += kb[s * PAD + tid];
            z[tid] += zs;
        }
    }
}

// ---------------------------------------------------------------------------
extern "C" void kernel_launch(void* const* d_in, const int* in_sizes, int n_in,
                              void* d_out, int out_size) {
    const float* x  = (const float*)d_in[0];
    const float* Wq = (const float*)d_in[1];
    const float* Wk = (const float*)d_in[2];
    const float* Wv = (const float*)d_in[3];
    const float* Wo = (const float*)d_in[4];
    float* out = (float*)d_out;

    cudaFuncSetAttribute(attn_kernel, cudaFuncAttributeMaxDynamicSharedMemorySize,
                         ATTN_SMEM_BYTES);

    // 1) Q/K/V projections + elu+1 feature map + (b,h,l,d) relayout
    sgemm_qkv<<<dim3(Dmod / BN, Mrows / BM, 3), 256>>>(x, Wq, Wk, Wv);
    // 2) chunked causal linear attention -> g_attn (b,l,D)
    attn_kernel<<<Bsz * Hn, 128, ATTN_SMEM_BYTES>>>();
    // 3) output projection
    sgemm_out<<<dim3(Dmod / BN, Mrows / BM, 1), 256>>>(Wo, out);
}

// round 3
// speedup vs baseline: 1.9431x; 1.9431x over previous
#include <cuda_runtime.h>
#include <math.h>
#include <stdint.h>

// Problem constants
#define Bsz   4
#define Lseq  4096
#define Dmod  1024
#define Hn    16
#define HDim  64
#define CH    128
#define NCH   32
#define Mrows (Bsz*Lseq)          // 16384
#define EPSC  1e-12f

// Scratch (device globals — allocation-free per harness rules)
__device__ float g_q[(size_t)Bsz*Hn*Lseq*HDim];     // (b,h,l,d)
__device__ float g_k[(size_t)Bsz*Hn*Lseq*HDim];
__device__ float g_v[(size_t)Bsz*Hn*Lseq*HDim];
__device__ float g_attn[(size_t)Bsz*Lseq*Dmod];     // (b,l,D) row-major

// ---------------------------------------------------------------------------
// PTX helpers (portable sm_80+ path: cp.async + mma.sync tf32)
// ---------------------------------------------------------------------------
__device__ __forceinline__ uint32_t smem_u32(const void* p) {
    uint32_t a;
    asm("{ .reg .u64 t; cvta.to.shared.u64 t, %1; cvt.u32.u64 %0, t; }" : "=r"(a) : "l"(p));
    return a;
}
__device__ __forceinline__ uint32_t f2tf32(float x) {
    uint32_t r;
    asm("cvt.rna.tf32.f32 %0, %1;" : "=r"(r) : "f"(x));
    return r;
}
__device__ __forceinline__ void cp_async16(uint32_t smem, const void* g) {
    asm volatile("cp.async.cg.shared.global [%0], [%1], 16;" :: "r"(smem), "l"(g));
}
#define CP_COMMIT() asm volatile("cp.async.commit_group;" ::: "memory")
#define CP_WAIT1()  asm volatile("cp.async.wait_group 1;" ::: "memory")

__device__ __forceinline__ void mma_tf32(float& c0, float& c1, float& c2, float& c3,
                                         uint32_t a0, uint32_t a1, uint32_t a2, uint32_t a3,
                                         uint32_t b0, uint32_t b1) {
    asm volatile(
        "mma.sync.aligned.m16n8k8.row.col.f32.tf32.tf32.f32 "
        "{%0,%1,%2,%3}, {%4,%5,%6,%7}, {%8,%9}, {%0,%1,%2,%3};"
        : "+f"(c0), "+f"(c1), "+f"(c2), "+f"(c3)
        : "r"(a0), "r"(a1), "r"(a2), "r"(a3), "r"(b0), "r"(b1));
}

// ---------------------------------------------------------------------------
// tf32 mma.sync GEMM: C[m][n] = sum_k A[m][k] * W[n][k]
// CTA 128x128, BK=32, 8 warps (2x4 -> 64x32 warp tiles), double-buffered cp.async.
// mode 0: out -> g_q/g_k/g_v per blockIdx.z (elu+1 on q,k; (b,h,l,d) layout)
// mode 1: out -> OutPlain row-major [Mrows, Dmod], A = g_attn
// ---------------------------------------------------------------------------
#define BK 32
#define LDP 36                      // row stride in floats (pad 4)
#define TILE_FLOATS (128 * LDP)     // 4608
#define STAGE_FLOATS (2 * TILE_FLOATS)
#define GEMM_SMEM_BYTES (2 * STAGE_FLOATS * 4)   // 73728

__global__ __launch_bounds__(256) void mma_gemm(const float* __restrict__ Ain,
                                                const float* __restrict__ Wq,
                                                const float* __restrict__ Wk,
                                                const float* __restrict__ Wv,
                                                float* __restrict__ OutPlain,
                                                int mode) {
    extern __shared__ __align__(16) float smf[];

    const int tid  = threadIdx.x;
    const int wid  = tid >> 5;
    const int lane = tid & 31;
    const int g    = lane >> 2;     // group row 0..7
    const int t    = lane & 3;      // thread-in-group 0..3

    const int w = blockIdx.z;
    const float* A  = (mode == 1) ? g_attn : Ain;
    const float* Wm = (w == 0) ? Wq : (w == 1) ? Wk : Wv;
    float* outp     = (w == 0) ? g_q : (w == 1) ? g_k : g_v;

    const int rowBase = blockIdx.y * 128;
    const int colBase = blockIdx.x * 128;

    // warp tiling: 2 rows x 4 cols of 64x32
    const int mBase = (wid >> 2) * 64;
    const int nBase = (wid & 3) * 32;

    // cp.async assignment: 4 float4 per thread per matrix per stage
    const int ldRow = tid >> 3;          // 0..31
    const int ldC4  = tid & 7;           // 16B group in the 128B (=32 float) row
    const uint32_t smb = smem_u32(smf);
    const float* aG = A  + (size_t)(rowBase + ldRow) * Dmod + ldC4 * 4;
    const float* bG = Wm + (size_t)(colBase + ldRow) * Dmod + ldC4 * 4;

    float acc[4][4][4];
    #pragma unroll
    for (int mi = 0; mi < 4; ++mi)
        #pragma unroll
        for (int ni = 0; ni < 4; ++ni)
            #pragma unroll
            for (int j = 0; j < 4; ++j) acc[mi][ni][j] = 0.f;

    // ---- stage loader ----
    auto load_stage = [&](int stage, int kt) {
        uint32_t sA = smb + (uint32_t)(stage * STAGE_FLOATS) * 4;
        uint32_t sB = sA + (uint32_t)TILE_FLOATS * 4;
        const float* ag = aG + kt * BK;
        const float* bg = bG + kt * BK;
        #pragma unroll
        for (int i = 0; i < 4; ++i) {
            uint32_t soff = ((uint32_t)(ldRow + 32 * i) * LDP + ldC4 * 4) * 4;
            cp_async16(sA + soff, ag + (size_t)(32 * i) * Dmod);
            cp_async16(sB + soff, bg + (size_t)(32 * i) * Dmod);
        }
    };

    load_stage(0, 0);
    CP_COMMIT();

    const int NKT = Dmod / BK;  // 32
    for (int kt = 0; kt < NKT; ++kt) {
        const int cur = kt & 1;
        if (kt + 1 < NKT) load_stage(cur ^ 1, kt + 1);
        CP_COMMIT();
        CP_WAIT1();
        __syncthreads();

        const float* As = smf + cur * STAGE_FLOATS;
        const float* Bs = As + TILE_FLOATS;

        #pragma unroll
        for (int k8 = 0; k8 < 4; ++k8) {
            const int kk = k8 * 8;
            uint32_t af[4][4], bf[4][2];
            #pragma unroll
            for (int mi = 0; mi < 4; ++mi) {
                const float* ar = As + (mBase + mi * 16 + g) * LDP + kk + t;
                af[mi][0] = f2tf32(ar[0]);
                af[mi][2] = f2tf32(ar[4]);
                af[mi][1] = f2tf32(ar[8 * LDP]);
                af[mi][3] = f2tf32(ar[8 * LDP + 4]);
            }
            #pragma unroll
            for (int ni = 0; ni < 4; ++ni) {
                const float* br = Bs + (nBase + ni * 8 + g) * LDP + kk + t;
                bf[ni][0] = f2tf32(br[0]);
                bf[ni][1] = f2tf32(br[4]);
            }
            #pragma unroll
            for (int mi = 0; mi < 4; ++mi)
                #pragma unroll
                for (int ni = 0; ni < 4; ++ni)
                    mma_tf32(acc[mi][ni][0], acc[mi][ni][1], acc[mi][ni][2], acc[mi][ni][3],
                             af[mi][0], af[mi][1], af[mi][2], af[mi][3],
                             bf[ni][0], bf[ni][1]);
        }
        __syncthreads();
    }

    // ---- epilogue ----
    const bool do_elu = (mode == 0) && (w < 2);
    #pragma unroll
    for (int mi = 0; mi < 4; ++mi) {
        #pragma unroll
        for (int ni = 0; ni < 4; ++ni) {
            const int m0 = rowBase + mBase + mi * 16 + g;
            const int n  = colBase + nBase + ni * 8 + 2 * t;
            #pragma unroll
            for (int half = 0; half < 2; ++half) {
                const int m = m0 + half * 8;
                float v0 = acc[mi][ni][2 * half + 0];
                float v1 = acc[mi][ni][2 * half + 1];
                if (do_elu) {
                    v0 = (v0 > 0.f) ? (v0 + 1.f) : expf(v0);
                    v1 = (v1 > 0.f) ? (v1 + 1.f) : expf(v1);
                }
                if (mode == 0) {
                    const int hh = n >> 6;
                    const int dd = n & 63;
                    const int bb = m >> 12;
                    const int ll = m & (Lseq - 1);
                    float* dst = outp + (((size_t)(bb * Hn + hh) * Lseq + ll) * HDim + dd);
                    *(float2*)dst = make_float2(v0, v1);
                } else {
                    float* dst = OutPlain + (size_t)m * Dmod + n;
                    *(float2*)dst = make_float2(v0, v1);
                }
            }
        }
    }
}

// ---------------------------------------------------------------------------
// Chunked causal linear attention, e-split over 2 blocks per (b,h).
// grid = 128 blocks: bh = blockIdx.x & 63, eh = blockIdx.x >> 6 (e half).
// ---------------------------------------------------------------------------
#define PAD 68
#define SP  36
#define ATTN_SMEM_FLOATS (64*SP + 64 + 2*128*PAD + 128*SP)
#define ATTN_SMEM_BYTES  (ATTN_SMEM_FLOATS * 4)

__global__ __launch_bounds__(128) void attn_kernel() {
    extern __shared__ __align__(16) float sm[];
    float* S  = sm;                      // 64 x 36 (this block's 32 e-cols)
    float* z  = S + 64 * SP;             // 64
    float* qb = z + 64;                  // 128 x 68
    float* kb = qb + 128 * PAD;          // 128 x 68
    float* vb = kb + 128 * PAD;          // 128 x 36 (32 e-cols)

    const int tid = threadIdx.x;
    const int bh  = blockIdx.x & 63;
    const int eh  = blockIdx.x >> 6;     // 0 or 1
    const int e0  = eh * 32;

    for (int i = tid; i < 64 * SP + 64; i += 128) sm[i] = 0.f;

    const float* gq = g_q + (size_t)bh * Lseq * HDim;
    const float* gk = g_k + (size_t)bh * Lseq * HDim;
    const float* gv = g_v + (size_t)bh * Lseq * HDim;
    float* ga = g_attn + (size_t)(bh >> 4) * Lseq * Dmod + (size_t)(bh & 15) * HDim + e0;

    for (int c = 0; c < NCH; ++c) {
        __syncthreads();
        {
            const float4* q4 = (const float4*)(gq + (size_t)c * CH * HDim);
            const float4* k4 = (const float4*)(gk + (size_t)c * CH * HDim);
            #pragma unroll
            for (int it = 0; it < 16; ++it) {
                int idx = tid + 128 * it;          // 0..2047
                int row = idx >> 4;
                int col = (idx & 15) << 2;
                *(float4*)(qb + row * PAD + col) = q4[idx];
                *(float4*)(kb + row * PAD + col) = k4[idx];
            }
            #pragma unroll
            for (int it = 0; it < 8; ++it) {
                int idx = tid + 128 * it;          // 0..1023
                int row = idx >> 3;
                int j   = (idx & 7) << 2;
                *(float4*)(vb + row * SP + j) =
                    *(const float4*)(gv + ((size_t)c * CH + row) * HDim + e0 + j);
            }
        }
        __syncthreads();

        float qreg[64];
        {
            const float4* qrow = (const float4*)(qb + tid * PAD);
            #pragma unroll
            for (int j = 0; j < 16; ++j) {
                float4 t4 = qrow[j];
                qreg[4*j+0] = t4.x; qreg[4*j+1] = t4.y;
                qreg[4*j+2] = t4.z; qreg[4*j+3] = t4.w;
            }
        }

        float den = 0.f;
        #pragma unroll
        for (int d = 0; d < 64; ++d) den += qreg[d] * z[d];

        float num[32];
        #pragma unroll
        for (int e = 0; e < 32; ++e) num[e] = 0.f;

        // num += q @ S
        #pragma unroll 4
        for (int d = 0; d < 64; ++d) {
            const float qd = qreg[d];
            const float4* Sr = (const float4*)(S + d * SP);
            #pragma unroll
            for (int j = 0; j < 8; ++j) {
                float4 s4 = Sr[j];
                num[4*j+0] += qd * s4.x; num[4*j+1] += qd * s4.y;
                num[4*j+2] += qd * s4.z; num[4*j+3] += qd * s4.w;
            }
        }

        // in-chunk causal scores
        for (int s = 0; s < CH; ++s) {
            if (s > tid) break;
            const float4* kr = (const float4*)(kb + s * PAD);
            float sc = 0.f;
            #pragma unroll
            for (int j = 0; j < 16; ++j) {
                float4 k4 = kr[j];
                sc += qreg[4*j+0]*k4.x + qreg[4*j+1]*k4.y
                    + qreg[4*j+2]*k4.z + qreg[4*j+3]*k4.w;
            }
            den += sc;
            const float4* vr = (const float4*)(vb + s * SP);
            #pragma unroll
            for (int j = 0; j < 8; ++j) {
                float4 v4 = vr[j];
                num[4*j+0] += sc * v4.x; num[4*j+1] += sc * v4.y;
                num[4*j+2] += sc * v4.z; num[4*j+3] += sc * v4.w;
            }
        }

        {
            const float inv = 1.f / den;
            float* dst = ga + (size_t)(c * CH + tid) * Dmod;
            #pragma unroll
            for (int j = 0; j < 8; ++j) {
                float4 o;
                o.x = num[4*j+0] * inv + EPSC;
                o.y = num[4*j+1] * inv + EPSC;
                o.z = num[4*j+2] * inv + EPSC;
                o.w = num[4*j+3] * inv + EPSC;
                ((float4*)dst)[j] = o;
            }
        }

        __syncthreads();

        // S += k^T v (this block's 32 e-cols): thread -> d = tid/2, 16 e each
        {
            const int d  = tid >> 1;
            const int el = (tid & 1) * 16;
            float a2[16];
            #pragma unroll
            for (int j = 0; j < 16; ++j) a2[j] = 0.f;
            for (int s = 0; s < CH; ++s) {
                const float kd = kb[s * PAD + d];
                const float4* vr = (const float4*)(vb + s * SP + el);
                #pragma unroll
                for (int j = 0; j < 4; ++j) {
                    float4 v4 = vr[j];
                    a2[4*j+0] += kd * v4.x; a2[4*j+1] += kd * v4.y;
                    a2[4*j+2] += kd * v4.z; a2[4*j+3] += kd * v4.w;
                }
            }
            float* Srow = S + d * SP + el;
            #pragma unroll
            for (int j = 0; j < 16; ++j) Srow[j] += a2[j];
        }

        if (tid < 64) {
            float zs = 0.f;
            for (int s = 0; s < CH; ++s) zs += kb[s * PAD + tid];
            z[tid] += zs;
        }
    }
}

// ---------------------------------------------------------------------------
extern "C" void kernel_launch(void* const* d_in, const int* in_sizes, int n_in,
                              void* d_out, int out_size) {
    const float* x  = (const float*)d_in[0];
    const float* Wq = (const float*)d_in[1];
    const float* Wk = (const float*)d_in[2];
    const float* Wv = (const float*)d_in[3];
    const float* Wo = (const float*)d_in[4];
    float* out = (float*)d_out;

    cudaFuncSetAttribute(mma_gemm, cudaFuncAttributeMaxDynamicSharedMemorySize,
                         GEMM_SMEM_BYTES);
    cudaFuncSetAttribute(attn_kernel, cudaFuncAttributeMaxDynamicSharedMemorySize,
                         ATTN_SMEM_BYTES);

    // 1) Q/K/V projections (tf32 mma.sync) + elu+1 + (b,h,l,d) relayout
    mma_gemm<<<dim3(Dmod / 128, Mrows / 128, 3), 256, GEMM_SMEM_BYTES>>>(
        x, Wq, Wk, Wv, nullptr, 0);
    // 2) chunked causal linear attention (e-split, 128 blocks)
    attn_kernel<<<2 * Bsz * Hn, 128, ATTN_SMEM_BYTES>>>();
    // 3) output projection (tf32 mma.sync)
    mma_gemm<<<dim3(Dmod / 128, Mrows / 128, 1), 256, GEMM_SMEM_BYTES>>>(
        nullptr, Wo, Wo, Wo, out, 1);
}

// round 4
// speedup vs baseline: 3.4562x; 1.7787x over previous
#include <cuda_runtime.h>
#include <math.h>
#include <stdint.h>

// Problem constants
#define Bsz   4
#define Lseq  4096
#define Dmod  1024
#define Hn    16
#define HDim  64
#define CH    128
#define NCH   32
#define Mrows (Bsz*Lseq)          // 16384
#define NBH   (Bsz*Hn)            // 64
#define EPSC  1e-12f

// Scratch (device globals — allocation-free per harness rules)
__device__ float g_q[(size_t)NBH*Lseq*HDim];        // (b,h,l,d)
__device__ float g_k[(size_t)NBH*Lseq*HDim];
__device__ float g_v[(size_t)NBH*Lseq*HDim];
__device__ float g_attn[(size_t)Bsz*Lseq*Dmod];     // (b,l,D) row-major
// chunk-scan state
__device__ float g_Sloc[(size_t)NBH*NCH*HDim*HDim]; // per-chunk local K^T V
__device__ float g_Spre[(size_t)NBH*NCH*HDim*HDim]; // exclusive prefix
__device__ float g_zloc[(size_t)NBH*NCH*HDim];
__device__ float g_zpre[(size_t)NBH*NCH*HDim];

// ---------------------------------------------------------------------------
// PTX helpers (portable sm_80+ path: cp.async + mma.sync tf32)
// ---------------------------------------------------------------------------
__device__ __forceinline__ uint32_t smem_u32(const void* p) {
    uint32_t a;
    asm("{ .reg .u64 t; cvta.to.shared.u64 t, %1; cvt.u32.u64 %0, t; }" : "=r"(a) : "l"(p));
    return a;
}
__device__ __forceinline__ uint32_t f2tf32(float x) {
    uint32_t r;
    asm("cvt.rna.tf32.f32 %0, %1;" : "=r"(r) : "f"(x));
    return r;
}
__device__ __forceinline__ void cp_async16(uint32_t smem, const void* g) {
    asm volatile("cp.async.cg.shared.global [%0], [%1], 16;" :: "r"(smem), "l"(g));
}
#define CP_COMMIT() asm volatile("cp.async.commit_group;" ::: "memory")
#define CP_WAIT1()  asm volatile("cp.async.wait_group 1;" ::: "memory")

__device__ __forceinline__ void mma_tf32(float& c0, float& c1, float& c2, float& c3,
                                         uint32_t a0, uint32_t a1, uint32_t a2, uint32_t a3,
                                         uint32_t b0, uint32_t b1) {
    asm volatile(
        "mma.sync.aligned.m16n8k8.row.col.f32.tf32.tf32.f32 "
        "{%0,%1,%2,%3}, {%4,%5,%6,%7}, {%8,%9}, {%0,%1,%2,%3};"
        : "+f"(c0), "+f"(c1), "+f"(c2), "+f"(c3)
        : "r"(a0), "r"(a1), "r"(a2), "r"(a3), "r"(b0), "r"(b1));
}

// ---------------------------------------------------------------------------
// tf32 mma.sync GEMM: C[m][n] = sum_k A[m][k] * W[n][k]
// CTA 128x128, BK=32, 8 warps (2x4 -> 64x32 warp tiles), double-buffered cp.async.
// ---------------------------------------------------------------------------
#define BK 32
#define LDP 36
#define TILE_FLOATS (128 * LDP)
#define STAGE_FLOATS (2 * TILE_FLOATS)
#define GEMM_SMEM_BYTES (2 * STAGE_FLOATS * 4)   // 73728

__global__ __launch_bounds__(256) void mma_gemm(const float* __restrict__ Ain,
                                                const float* __restrict__ Wq,
                                                const float* __restrict__ Wk,
                                                const float* __restrict__ Wv,
                                                float* __restrict__ OutPlain,
                                                int mode) {
    extern __shared__ __align__(16) float smf[];

    const int tid  = threadIdx.x;
    const int wid  = tid >> 5;
    const int lane = tid & 31;
    const int g    = lane >> 2;
    const int t    = lane & 3;

    const int w = blockIdx.z;
    const float* A  = (mode == 1) ? g_attn : Ain;
    const float* Wm = (w == 0) ? Wq : (w == 1) ? Wk : Wv;
    float* outp     = (w == 0) ? g_q : (w == 1) ? g_k : g_v;

    const int rowBase = blockIdx.y * 128;
    const int colBase = blockIdx.x * 128;
    const int mBase = (wid >> 2) * 64;
    const int nBase = (wid & 3) * 32;

    const int ldRow = tid >> 3;
    const int ldC4  = tid & 7;
    const uint32_t smb = smem_u32(smf);
    const float* aG = A  + (size_t)(rowBase + ldRow) * Dmod + ldC4 * 4;
    const float* bG = Wm + (size_t)(colBase + ldRow) * Dmod + ldC4 * 4;

    float acc[4][4][4];
    #pragma unroll
    for (int mi = 0; mi < 4; ++mi)
        #pragma unroll
        for (int ni = 0; ni < 4; ++ni)
            #pragma unroll
            for (int j = 0; j < 4; ++j) acc[mi][ni][j] = 0.f;

    auto load_stage = [&](int stage, int kt) {
        uint32_t sA = smb + (uint32_t)(stage * STAGE_FLOATS) * 4;
        uint32_t sB = sA + (uint32_t)TILE_FLOATS * 4;
        const float* ag = aG + kt * BK;
        const float* bg = bG + kt * BK;
        #pragma unroll
        for (int i = 0; i < 4; ++i) {
            uint32_t soff = ((uint32_t)(ldRow + 32 * i) * LDP + ldC4 * 4) * 4;
            cp_async16(sA + soff, ag + (size_t)(32 * i) * Dmod);
            cp_async16(sB + soff, bg + (size_t)(32 * i) * Dmod);
        }
    };

    load_stage(0, 0);
    CP_COMMIT();

    const int NKT = Dmod / BK;
    for (int kt = 0; kt < NKT; ++kt) {
        const int cur = kt & 1;
        if (kt + 1 < NKT) load_stage(cur ^ 1, kt + 1);
        CP_COMMIT();
        CP_WAIT1();
        __syncthreads();

        const float* As = smf + cur * STAGE_FLOATS;
        const float* Bs = As + TILE_FLOATS;

        #pragma unroll
        for (int k8 = 0; k8 < 4; ++k8) {
            const int kk = k8 * 8;
            uint32_t af[4][4], bf[4][2];
            #pragma unroll
            for (int mi = 0; mi < 4; ++mi) {
                const float* ar = As + (mBase + mi * 16 + g) * LDP + kk + t;
                af[mi][0] = f2tf32(ar[0]);
                af[mi][2] = f2tf32(ar[4]);
                af[mi][1] = f2tf32(ar[8 * LDP]);
                af[mi][3] = f2tf32(ar[8 * LDP + 4]);
            }
            #pragma unroll
            for (int ni = 0; ni < 4; ++ni) {
                const float* br = Bs + (nBase + ni * 8 + g) * LDP + kk + t;
                bf[ni][0] = f2tf32(br[0]);
                bf[ni][1] = f2tf32(br[4]);
            }
            #pragma unroll
            for (int mi = 0; mi < 4; ++mi)
                #pragma unroll
                for (int ni = 0; ni < 4; ++ni)
                    mma_tf32(acc[mi][ni][0], acc[mi][ni][1], acc[mi][ni][2], acc[mi][ni][3],
                             af[mi][0], af[mi][1], af[mi][2], af[mi][3],
                             bf[ni][0], bf[ni][1]);
        }
        __syncthreads();
    }

    const bool do_elu = (mode == 0) && (w < 2);
    #pragma unroll
    for (int mi = 0; mi < 4; ++mi) {
        #pragma unroll
        for (int ni = 0; ni < 4; ++ni) {
            const int m0 = rowBase + mBase + mi * 16 + g;
            const int n  = colBase + nBase + ni * 8 + 2 * t;
            #pragma unroll
            for (int half = 0; half < 2; ++half) {
                const int m = m0 + half * 8;
                float v0 = acc[mi][ni][2 * half + 0];
                float v1 = acc[mi][ni][2 * half + 1];
                if (do_elu) {
                    v0 = (v0 > 0.f) ? (v0 + 1.f) : expf(v0);
                    v1 = (v1 > 0.f) ? (v1 + 1.f) : expf(v1);
                }
                if (mode == 0) {
                    const int hh = n >> 6;
                    const int dd = n & 63;
                    const int bb = m >> 12;
                    const int ll = m & (Lseq - 1);
                    float* dst = outp + (((size_t)(bb * Hn + hh) * Lseq + ll) * HDim + dd);
                    *(float2*)dst = make_float2(v0, v1);
                } else {
                    float* dst = OutPlain + (size_t)m * Dmod + n;
                    *(float2*)dst = make_float2(v0, v1);
                }
            }
        }
    }
}

// ---------------------------------------------------------------------------
// Pass 1: per-(bh,chunk) local state:  Sloc = K^T V (64x64),  zloc = sum_s k_s
// grid = 2048 blocks (bh*32+c), 128 threads.
// ---------------------------------------------------------------------------
#define P1_SMEM_BYTES (2 * CH * HDim * 4)   // k + v, 64 KB

__global__ __launch_bounds__(128) void attn_local() {
    extern __shared__ __align__(16) float sm[];
    float* kb = sm;                 // 128 x 64
    float* vb = sm + CH * HDim;     // 128 x 64

    const int tid = threadIdx.x;
    const int bc  = blockIdx.x;     // bh*32 + c
    const int bh  = bc >> 5;
    const int c   = bc & 31;

    const float* gk = g_k + ((size_t)bh * Lseq + (size_t)c * CH) * HDim;
    const float* gv = g_v + ((size_t)bh * Lseq + (size_t)c * CH) * HDim;

    #pragma unroll
    for (int it = 0; it < 16; ++it) {
        int idx = tid + 128 * it;               // float4 index 0..2047
        ((float4*)kb)[idx] = ((const float4*)gk)[idx];
        ((float4*)vb)[idx] = ((const float4*)gv)[idx];
    }
    __syncthreads();

    const int d  = tid >> 1;
    const int e0 = (tid & 1) * 32;
    float a[32];
    #pragma unroll
    for (int j = 0; j < 32; ++j) a[j] = 0.f;
    float zs = 0.f;

    for (int s = 0; s < CH; ++s) {
        const float kd = kb[s * HDim + d];
        zs += kd;
        const float4* vr = (const float4*)(vb + s * HDim + e0);
        #pragma unroll
        for (int j = 0; j < 8; ++j) {
            float4 v4 = vr[j];
            a[4*j+0] += kd * v4.x; a[4*j+1] += kd * v4.y;
            a[4*j+2] += kd * v4.z; a[4*j+3] += kd * v4.w;
        }
    }

    float* So = g_Sloc + (size_t)bc * HDim * HDim + d * HDim + e0;
    #pragma unroll
    for (int j = 0; j < 8; ++j)
        ((float4*)So)[j] = make_float4(a[4*j+0], a[4*j+1], a[4*j+2], a[4*j+3]);
    if ((tid & 1) == 0) g_zloc[(size_t)bc * HDim + d] = zs;
}

// ---------------------------------------------------------------------------
// Pass 2: exclusive prefix over the 32 chunks of each bh.
// grid = 64 blocks, 256 threads.
// ---------------------------------------------------------------------------
__global__ __launch_bounds__(256) void attn_scan() {
    const int tid = threadIdx.x;
    const int bh  = blockIdx.x;

    float acc[16];
    #pragma unroll
    for (int j = 0; j < 16; ++j) acc[j] = 0.f;
    float accz = 0.f;

    for (int c = 0; c < NCH; ++c) {
        const size_t base = ((size_t)bh * NCH + c) * (HDim * HDim);
        #pragma unroll
        for (int j = 0; j < 16; ++j) g_Spre[base + tid + 256 * j] = acc[j];
        if (tid < HDim) g_zpre[((size_t)bh * NCH + c) * HDim + tid] = accz;
        #pragma unroll
        for (int j = 0; j < 16; ++j) acc[j] += g_Sloc[base + tid + 256 * j];
        if (tid < HDim) accz += g_zloc[((size_t)bh * NCH + c) * HDim + tid];
    }
}

// ---------------------------------------------------------------------------
// Pass 3: per-(bh,chunk) output.  No carried state — fully parallel.
// out_t = (q_t S_pre + sum_{s<=t} (q_t.k_s) v_s) / (q_t z_pre + rowsum) + eps
// grid = 2048 blocks, 128 threads (thread = query row).
// All in-loop shared reads are warp-uniform (broadcast) -> no padding needed.
// ---------------------------------------------------------------------------
#define P3_SMEM_FLOATS (2 * CH * HDim + HDim * HDim + HDim)
#define P3_SMEM_BYTES  (P3_SMEM_FLOATS * 4)   // 82,176 B

__global__ __launch_bounds__(128) void attn_out() {
    extern __shared__ __align__(16) float sm[];
    float* kb = sm;                       // 128 x 64
    float* vb = kb + CH * HDim;           // 128 x 64
    float* Sb = vb + CH * HDim;           // 64 x 64
    float* zb = Sb + HDim * HDim;         // 64

    const int tid = threadIdx.x;
    const int bc  = blockIdx.x;
    const int bh  = bc >> 5;
    const int c   = bc & 31;

    const float* gq = g_q + ((size_t)bh * Lseq + (size_t)c * CH) * HDim;
    const float* gk = g_k + ((size_t)bh * Lseq + (size_t)c * CH) * HDim;
    const float* gv = g_v + ((size_t)bh * Lseq + (size_t)c * CH) * HDim;
    const float* Sp = g_Spre + (size_t)bc * HDim * HDim;
    const float* zp = g_zpre + (size_t)bc * HDim;
    float* ga = g_attn + (size_t)(bh >> 4) * Lseq * Dmod
                       + ((size_t)c * CH) * Dmod + (size_t)(bh & 15) * HDim;

    // stage k, v, S_pre, z_pre (coalesced float4)
    #pragma unroll
    for (int it = 0; it < 16; ++it) {
        int idx = tid + 128 * it;
        ((float4*)kb)[idx] = ((const float4*)gk)[idx];
        ((float4*)vb)[idx] = ((const float4*)gv)[idx];
    }
    #pragma unroll
    for (int it = 0; it < 8; ++it) {
        int idx = tid + 128 * it;
        ((float4*)Sb)[idx] = ((const float4*)Sp)[idx];
    }
    if (tid < HDim) zb[tid] = zp[tid];

    // own q row into registers (L1-served, 2 lines/thread)
    float qreg[64];
    {
        const float4* qr = (const float4*)(gq + (size_t)tid * HDim);
        #pragma unroll
        for (int j = 0; j < 16; ++j) {
            float4 t4 = __ldg(qr + j);
            qreg[4*j+0] = t4.x; qreg[4*j+1] = t4.y;
            qreg[4*j+2] = t4.z; qreg[4*j+3] = t4.w;
        }
    }
    __syncthreads();

    float den = 0.f;
    #pragma unroll
    for (int d = 0; d < 64; ++d) den += qreg[d] * zb[d];

    float num[64];
    #pragma unroll
    for (int e = 0; e < 64; ++e) num[e] = 0.f;

    // num += q @ S_pre   (Sb row reads are warp-uniform broadcasts)
    #pragma unroll 4
    for (int d = 0; d < 64; ++d) {
        const float qd = qreg[d];
        const float4* Sr = (const float4*)(Sb + d * HDim);
        #pragma unroll
        for (int j = 0; j < 16; ++j) {
            float4 s4 = Sr[j];
            num[4*j+0] += qd * s4.x; num[4*j+1] += qd * s4.y;
            num[4*j+2] += qd * s4.z; num[4*j+3] += qd * s4.w;
        }
    }

    // in-chunk causal part (kb/vb row reads are warp-uniform broadcasts)
    for (int s = 0; s < CH; ++s) {
        if (s > tid) break;
        const float4* kr = (const float4*)(kb + s * HDim);
        float sc = 0.f;
        #pragma unroll
        for (int j = 0; j < 16; ++j) {
            float4 k4 = kr[j];
            sc += qreg[4*j+0]*k4.x + qreg[4*j+1]*k4.y
                + qreg[4*j+2]*k4.z + qreg[4*j+3]*k4.w;
        }
        den += sc;
        const float4* vr = (const float4*)(vb + s * HDim);
        #pragma unroll
        for (int j = 0; j < 16; ++j) {
            float4 v4 = vr[j];
            num[4*j+0] += sc * v4.x; num[4*j+1] += sc * v4.y;
            num[4*j+2] += sc * v4.z; num[4*j+3] += sc * v4.w;
        }
    }

    // write (b, l, h*64+e)
    {
        const float inv = 1.f / den;
        float* dst = ga + (size_t)tid * Dmod;
        #pragma unroll
        for (int j = 0; j < 16; ++j) {
            float4 o;
            o.x = num[4*j+0] * inv + EPSC;
            o.y = num[4*j+1] * inv + EPSC;
            o.z = num[4*j+2] * inv + EPSC;
            o.w = num[4*j+3] * inv + EPSC;
            ((float4*)dst)[j] = o;
        }
    }
}

// ---------------------------------------------------------------------------
extern "C" void kernel_launch(void* const* d_in, const int* in_sizes, int n_in,
                              void* d_out, int out_size) {
    const float* x  = (const float*)d_in[0];
    const float* Wq = (const float*)d_in[1];
    const float* Wk = (const float*)d_in[2];
    const float* Wv = (const float*)d_in[3];
    const float* Wo = (const float*)d_in[4];
    float* out = (float*)d_out;

    cudaFuncSetAttribute(mma_gemm, cudaFuncAttributeMaxDynamicSharedMemorySize,
                         GEMM_SMEM_BYTES);
    cudaFuncSetAttribute(attn_local, cudaFuncAttributeMaxDynamicSharedMemorySize,
                         P1_SMEM_BYTES);
    cudaFuncSetAttribute(attn_out, cudaFuncAttributeMaxDynamicSharedMemorySize,
                         P3_SMEM_BYTES);

    // 1) Q/K/V projections (tf32 mma.sync) + elu+1 + (b,h,l,d) relayout
    mma_gemm<<<dim3(Dmod / 128, Mrows / 128, 3), 256, GEMM_SMEM_BYTES>>>(
        x, Wq, Wk, Wv, nullptr, 0);
    // 2) attention: local chunk states -> prefix scan -> outputs
    attn_local<<<NBH * NCH, 128, P1_SMEM_BYTES>>>();
    attn_scan<<<NBH, 256>>>();
    attn_out<<<NBH * NCH, 128, P3_SMEM_BYTES>>>();
    // 3) output projection (tf32 mma.sync)
    mma_gemm<<<dim3(Dmod / 128, Mrows / 128, 1), 256, GEMM_SMEM_BYTES>>>(
        nullptr, Wo, Wo, Wo, out, 1);
}

// round 6
// speedup vs baseline: 4.2474x; 1.2289x over previous
#include <cuda_runtime.h>
#include <math.h>
#include <stdint.h>

// Problem constants
#define Bsz   4
#define Lseq  4096
#define Dmod  1024
#define Hn    16
#define HDim  64
#define CH    128
#define NCH   32
#define Mrows (Bsz*Lseq)          // 16384
#define NBH   (Bsz*Hn)            // 64
#define EPSC  1e-12f

// Scratch (device globals — allocation-free per harness rules)
__device__ float g_q[(size_t)NBH*Lseq*HDim];        // (b,h,l,d)
__device__ float g_k[(size_t)NBH*Lseq*HDim];
__device__ float g_v[(size_t)NBH*Lseq*HDim];
__device__ float g_attn[(size_t)Bsz*Lseq*Dmod];     // (b,l,D) row-major
// chunk-scan state (stored TRANSPOSED, e-major: S^T[e][d])
__device__ float g_Sloc[(size_t)NBH*NCH*HDim*HDim];
__device__ float g_Spre[(size_t)NBH*NCH*HDim*HDim];
__device__ float g_zloc[(size_t)NBH*NCH*HDim];
__device__ float g_zpre[(size_t)NBH*NCH*HDim];

// ---------------------------------------------------------------------------
// PTX helpers
// ---------------------------------------------------------------------------
__device__ __forceinline__ uint32_t f2tf32(float x) {
    uint32_t r;
    asm("cvt.rna.tf32.f32 %0, %1;" : "=r"(r) : "f"(x));
    return r;
}
__device__ __forceinline__ void mma_tf32(float& c0, float& c1, float& c2, float& c3,
                                         uint32_t a0, uint32_t a1, uint32_t a2, uint32_t a3,
                                         uint32_t b0, uint32_t b1) {
    asm volatile(
        "mma.sync.aligned.m16n8k8.row.col.f32.tf32.tf32.f32 "
        "{%0,%1,%2,%3}, {%4,%5,%6,%7}, {%8,%9}, {%0,%1,%2,%3};"
        : "+f"(c0), "+f"(c1), "+f"(c2), "+f"(c3)
        : "r"(a0), "r"(a1), "r"(a2), "r"(a3), "r"(b0), "r"(b1));
}

// ---------------------------------------------------------------------------
// tf32 mma.sync GEMM: C[m][n] = sum_k A[m][k] * W[n][k]
// CTA 128x128, BK=32, 8 warps (2x4 -> 64x32 warp tiles).
// Convert-on-store: smem holds tf32 bits; inner loop is pure LDS + HMMA.
// Double buffered via LDG register prefetch; ONE __syncthreads per K-tile.
// ---------------------------------------------------------------------------
#define BK 32
#define LDP 36
#define TILE_FLOATS (128 * LDP)
#define STAGE_FLOATS (2 * TILE_FLOATS)
#define GEMM_SMEM_BYTES (2 * STAGE_FLOATS * 4)   // 73728

__global__ __launch_bounds__(256, 2) void mma_gemm(const float* __restrict__ Ain,
                                                   const float* __restrict__ Wq,
                                                   const float* __restrict__ Wk,
                                                   const float* __restrict__ Wv,
                                                   float* __restrict__ OutPlain,
                                                   int mode) {
    extern __shared__ __align__(16) uint32_t smu[];

    const int tid  = threadIdx.x;
    const int wid  = tid >> 5;
    const int lane = tid & 31;
    const int g    = lane >> 2;
    const int t    = lane & 3;

    const int w = blockIdx.z;
    const float* A  = (mode == 1) ? g_attn : Ain;
    const float* Wm = (w == 0) ? Wq : (w == 1) ? Wk : Wv;
    float* outp     = (w == 0) ? g_q : (w == 1) ? g_k : g_v;

    const int rowBase = blockIdx.y * 128;
    const int colBase = blockIdx.x * 128;
    const int mBase = (wid >> 2) * 64;
    const int nBase = (wid & 3) * 32;

    const int ldRow = tid >> 3;
    const int ldC4  = tid & 7;
    const float* aG = A  + (size_t)(rowBase + ldRow) * Dmod + ldC4 * 4;
    const float* bG = Wm + (size_t)(colBase + ldRow) * Dmod + ldC4 * 4;

    float acc[4][4][4];
    #pragma unroll
    for (int mi = 0; mi < 4; ++mi)
        #pragma unroll
        for (int ni = 0; ni < 4; ++ni)
            #pragma unroll
            for (int j = 0; j < 4; ++j) acc[mi][ni][j] = 0.f;

    float4 pA[4], pB[4];
    #pragma unroll
    for (int i = 0; i < 4; ++i) {
        pA[i] = __ldg((const float4*)(aG + (size_t)(32 * i) * Dmod));
        pB[i] = __ldg((const float4*)(bG + (size_t)(32 * i) * Dmod));
    }

    const int NKT = Dmod / BK;
    for (int kt = 0; kt < NKT; ++kt) {
        const int cur = kt & 1;
        uint32_t* stA = smu + cur * STAGE_FLOATS;
        uint32_t* stB = stA + TILE_FLOATS;

        #pragma unroll
        for (int i = 0; i < 4; ++i) {
            const uint32_t soff = (uint32_t)(ldRow + 32 * i) * LDP + ldC4 * 4;
            *(uint4*)(stA + soff) = make_uint4(f2tf32(pA[i].x), f2tf32(pA[i].y),
                                               f2tf32(pA[i].z), f2tf32(pA[i].w));
            *(uint4*)(stB + soff) = make_uint4(f2tf32(pB[i].x), f2tf32(pB[i].y),
                                               f2tf32(pB[i].z), f2tf32(pB[i].w));
        }
        if (kt + 1 < NKT) {
            #pragma unroll
            for (int i = 0; i < 4; ++i) {
                pA[i] = __ldg((const float4*)(aG + (size_t)(32 * i) * Dmod + (kt + 1) * BK));
                pB[i] = __ldg((const float4*)(bG + (size_t)(32 * i) * Dmod + (kt + 1) * BK));
            }
        }
        __syncthreads();

        const uint32_t* As = smu + cur * STAGE_FLOATS;
        const uint32_t* Bs = As + TILE_FLOATS;

        #pragma unroll
        for (int k8 = 0; k8 < 4; ++k8) {
            const int kk = k8 * 8;
            uint32_t af[4][4], bf[4][2];
            #pragma unroll
            for (int mi = 0; mi < 4; ++mi) {
                const uint32_t* ar = As + (mBase + mi * 16 + g) * LDP + kk + t;
                af[mi][0] = ar[0];
                af[mi][2] = ar[4];
                af[mi][1] = ar[8 * LDP];
                af[mi][3] = ar[8 * LDP + 4];
            }
            #pragma unroll
            for (int ni = 0; ni < 4; ++ni) {
                const uint32_t* br = Bs + (nBase + ni * 8 + g) * LDP + kk + t;
                bf[ni][0] = br[0];
                bf[ni][1] = br[4];
            }
            #pragma unroll
            for (int mi = 0; mi < 4; ++mi)
                #pragma unroll
                for (int ni = 0; ni < 4; ++ni)
                    mma_tf32(acc[mi][ni][0], acc[mi][ni][1], acc[mi][ni][2], acc[mi][ni][3],
                             af[mi][0], af[mi][1], af[mi][2], af[mi][3],
                             bf[ni][0], bf[ni][1]);
        }
    }

    const bool do_elu = (mode == 0) && (w < 2);
    #pragma unroll
    for (int mi = 0; mi < 4; ++mi) {
        #pragma unroll
        for (int ni = 0; ni < 4; ++ni) {
            const int m0 = rowBase + mBase + mi * 16 + g;
            const int n  = colBase + nBase + ni * 8 + 2 * t;
            #pragma unroll
            for (int half = 0; half < 2; ++half) {
                const int m = m0 + half * 8;
                float v0 = acc[mi][ni][2 * half + 0];
                float v1 = acc[mi][ni][2 * half + 1];
                if (do_elu) {
                    v0 = (v0 > 0.f) ? (v0 + 1.f) : expf(v0);
                    v1 = (v1 > 0.f) ? (v1 + 1.f) : expf(v1);
                }
                if (mode == 0) {
                    const int hh = n >> 6;
                    const int dd = n & 63;
                    const int bb = m >> 12;
                    const int ll = m & (Lseq - 1);
                    float* dst = outp + (((size_t)(bb * Hn + hh) * Lseq + ll) * HDim + dd);
                    *(float2*)dst = make_float2(v0, v1);
                } else {
                    float* dst = OutPlain + (size_t)m * Dmod + n;
                    *(float2*)dst = make_float2(v0, v1);
                }
            }
        }
    }
}

// ---------------------------------------------------------------------------
// Pass 1: per-(bh,chunk) local state, TRANSPOSED:
//   Sloc^T[e][d] = sum_s V[s,e] K[s,d],   zloc[d] = sum_s K[s,d]
// ---------------------------------------------------------------------------
#define P1_SMEM_BYTES (2 * CH * HDim * 4)   // 64 KB

__global__ __launch_bounds__(128) void attn_local() {
    extern __shared__ __align__(16) float sm[];
    float* kb = sm;                 // 128 x 64
    float* vb = sm + CH * HDim;     // 128 x 64

    const int tid = threadIdx.x;
    const int bc  = blockIdx.x;
    const int bh  = bc >> 5;
    const int c   = bc & 31;

    const float* gk = g_k + ((size_t)bh * Lseq + (size_t)c * CH) * HDim;
    const float* gv = g_v + ((size_t)bh * Lseq + (size_t)c * CH) * HDim;

    #pragma unroll
    for (int it = 0; it < 16; ++it) {
        int idx = tid + 128 * it;
        ((float4*)kb)[idx] = ((const float4*)gk)[idx];
        ((float4*)vb)[idx] = ((const float4*)gv)[idx];
    }
    __syncthreads();

    const int e  = tid >> 1;
    const int d0 = (tid & 1) * 32;
    float a[32];
    #pragma unroll
    for (int j = 0; j < 32; ++j) a[j] = 0.f;

    for (int s = 0; s < CH; ++s) {
        const float ve = vb[s * HDim + e];
        const float4* kr = (const float4*)(kb + s * HDim + d0);
        #pragma unroll
        for (int j = 0; j < 8; ++j) {
            float4 k4 = kr[j];
            a[4*j+0] += ve * k4.x; a[4*j+1] += ve * k4.y;
            a[4*j+2] += ve * k4.z; a[4*j+3] += ve * k4.w;
        }
    }

    float* So = g_Sloc + (size_t)bc * HDim * HDim + e * HDim + d0;
    #pragma unroll
    for (int j = 0; j < 8; ++j)
        ((float4*)So)[j] = make_float4(a[4*j+0], a[4*j+1], a[4*j+2], a[4*j+3]);

    if (tid < HDim) {
        float zs = 0.f;
        for (int s = 0; s < CH; ++s) zs += kb[s * HDim + tid];
        g_zloc[(size_t)bc * HDim + tid] = zs;
    }
}

// ---------------------------------------------------------------------------
// Pass 2: exclusive prefix over the 32 chunks of each bh (layout-agnostic).
// ---------------------------------------------------------------------------
__global__ __launch_bounds__(256) void attn_scan() {
    const int tid = threadIdx.x;
    const int bh  = blockIdx.x;

    float acc[16];
    #pragma unroll
    for (int j = 0; j < 16; ++j) acc[j] = 0.f;
    float accz = 0.f;

    for (int c = 0; c < NCH; ++c) {
        const size_t base = ((size_t)bh * NCH + c) * (HDim * HDim);
        #pragma unroll
        for (int j = 0; j < 16; ++j) g_Spre[base + tid + 256 * j] = acc[j];
        if (tid < HDim) g_zpre[((size_t)bh * NCH + c) * HDim + tid] = accz;
        #pragma unroll
        for (int j = 0; j < 16; ++j) acc[j] += g_Sloc[base + tid + 256 * j];
        if (tid < HDim) accz += g_zloc[((size_t)bh * NCH + c) * HDim + tid];
    }
}

// ---------------------------------------------------------------------------
// Pass 3: per-(bh,chunk) output on tensor cores (tf32 mma.sync).
//   scores = causal(Q K^T); out = (Q S_pre + scores V) / (Q z_pre + rowsum) + eps
// 256 threads = 8 warps; warp w owns output rows [16w, 16w+16).
// ---------------------------------------------------------------------------
#define LQK 68
#define LSV 132
#define AOQ  0
#define AOK  (AOQ + 128*LQK)     // 8704
#define AOS  (AOK + 128*LQK)     // 17408
#define AOV  (AOS + 128*LSV)     // 34304
#define AOP  (AOV + 64*LSV)      // 42752
#define AOZ  (AOP + 64*LQK)      // 47104
#define AODN (AOZ + 64)          // 47168
#define AO_FLOATS (AODN + 128)   // 47296
#define AO_SMEM_BYTES (AO_FLOATS * 4)   // 189184

__global__ __launch_bounds__(256) void attn_out() {
    extern __shared__ __align__(16) uint32_t smu[];
    float* smf = (float*)smu;

    const int tid  = threadIdx.x;
    const int w    = tid >> 5;
    const int lane = tid & 31;
    const int g    = lane >> 2;
    const int t    = lane & 3;

    const int bc = blockIdx.x;
    const int bh = bc >> 5;
    const int c  = bc & 31;

    const float* gq = g_q + ((size_t)bh * Lseq + (size_t)c * CH) * HDim;
    const float* gk = g_k + ((size_t)bh * Lseq + (size_t)c * CH) * HDim;
    const float* gv = g_v + ((size_t)bh * Lseq + (size_t)c * CH) * HDim;
    const float* Sp = g_Spre + (size_t)bc * HDim * HDim;   // S^T: [e][d]
    const float* zp = g_zpre + (size_t)bc * HDim;
    float* ga = g_attn + (size_t)(bh >> 4) * Lseq * Dmod
                       + ((size_t)c * CH) * Dmod + (size_t)(bh & 15) * HDim;

    // ---- load + tf32-convert into smem ----
    #pragma unroll
    for (int it = 0; it < 8; ++it) {
        int idx = tid + 256 * it;            // float4 idx 0..2047
        int row = idx >> 4, c4 = idx & 15;
        float4 a = __ldg((const float4*)gq + idx);
        float4 b = __ldg((const float4*)gk + idx);
        *(uint4*)(smu + AOQ + row * LQK + c4 * 4) =
            make_uint4(f2tf32(a.x), f2tf32(a.y), f2tf32(a.z), f2tf32(a.w));
        *(uint4*)(smu + AOK + row * LQK + c4 * 4) =
            make_uint4(f2tf32(b.x), f2tf32(b.y), f2tf32(b.z), f2tf32(b.w));
    }
    // V transposed: Vt[e][s]  — 64 e x 32 s4-groups = 2048 tasks
    #pragma unroll
    for (int it = 0; it < 8; ++it) {
        int task = tid + 256 * it;           // 0..2047
        int e = task & 63, s4 = task >> 6;   // s4: 0..31
        uint32_t v0 = f2tf32(__ldg(gv + (size_t)(s4 * 4 + 0) * HDim + e));
        uint32_t v1 = f2tf32(__ldg(gv + (size_t)(s4 * 4 + 1) * HDim + e));
        uint32_t v2 = f2tf32(__ldg(gv + (size_t)(s4 * 4 + 2) * HDim + e));
        uint32_t v3 = f2tf32(__ldg(gv + (size_t)(s4 * 4 + 3) * HDim + e));
        *(uint4*)(smu + AOV + e * LSV + s4 * 4) = make_uint4(v0, v1, v2, v3);
    }
    // S_pre^T rows (already e-major in global)
    #pragma unroll
    for (int it = 0; it < 4; ++it) {
        int idx = tid + 256 * it;            // float4 idx 0..1023
        int row = idx >> 4, c4 = idx & 15;
        float4 p = __ldg((const float4*)Sp + idx);
        *(uint4*)(smu + AOP + row * LQK + c4 * 4) =
            make_uint4(f2tf32(p.x), f2tf32(p.y), f2tf32(p.z), f2tf32(p.w));
    }
    if (tid < HDim) smf[AOZ + tid] = __ldg(zp + tid);
    __syncthreads();

    // ---- qz = q . z_pre (partial den), 2 threads per row ----
    {
        const int r = tid >> 1, hf = tid & 1;
        const float* qrow = smf + AOQ + r * LQK + hf * 32;
        const float* zz   = smf + AOZ + hf * 32;
        float s = 0.f;
        #pragma unroll
        for (int d = 0; d < 32; ++d) s += qrow[d] * zz[d];
        s += __shfl_xor_sync(0xffffffffu, s, 1);
        if (hf == 0) smf[AODN + r] = s;
    }

    const int r0 = w * 16 + g;
    const int r1 = r0 + 8;

    // ---- A fragments from Q (reused by mma1 and mma-pre) ----
    uint32_t aq[8][4];
    #pragma unroll
    for (int k8 = 0; k8 < 8; ++k8) {
        const uint32_t* p = smu + AOQ + r0 * LQK + k8 * 8 + t;
        aq[k8][0] = p[0];
        aq[k8][2] = p[4];
        aq[k8][1] = p[8 * LQK];
        aq[k8][3] = p[8 * LQK + 4];
    }

    // ---- mma1: scores = Q K^T (16 x 128 per warp) ----
    float acc1[16][4];
    #pragma unroll
    for (int ni = 0; ni < 16; ++ni)
        #pragma unroll
        for (int j = 0; j < 4; ++j) acc1[ni][j] = 0.f;

    #pragma unroll
    for (int k8 = 0; k8 < 8; ++k8) {
        #pragma unroll
        for (int ni = 0; ni < 16; ++ni) {
            const uint32_t* p = smu + AOK + (ni * 8 + g) * LQK + k8 * 8 + t;
            mma_tf32(acc1[ni][0], acc1[ni][1], acc1[ni][2], acc1[ni][3],
                     aq[k8][0], aq[k8][1], aq[k8][2], aq[k8][3], p[0], p[4]);
        }
    }

    // ---- mask (col <= row), rowsum, store tf32 scores ----
    float rs0 = 0.f, rs1 = 0.f;
    #pragma unroll
    for (int ni = 0; ni < 16; ++ni) {
        const int cb = ni * 8 + 2 * t;
        float m0 = (cb     <= r0) ? acc1[ni][0] : 0.f;
        float m1 = (cb + 1 <= r0) ? acc1[ni][1] : 0.f;
        float m2 = (cb     <= r1) ? acc1[ni][2] : 0.f;
        float m3 = (cb + 1 <= r1) ? acc1[ni][3] : 0.f;
        rs0 += m0 + m1;
        rs1 += m2 + m3;
        *(uint2*)(smu + AOS + r0 * LSV + cb) = make_uint2(f2tf32(m0), f2tf32(m1));
        *(uint2*)(smu + AOS + r1 * LSV + cb) = make_uint2(f2tf32(m2), f2tf32(m3));
    }
    rs0 += __shfl_xor_sync(0xffffffffu, rs0, 1);
    rs0 += __shfl_xor_sync(0xffffffffu, rs0, 2);
    rs1 += __shfl_xor_sync(0xffffffffu, rs1, 1);
    rs1 += __shfl_xor_sync(0xffffffffu, rs1, 2);
    __syncwarp();
    if (t == 0) {
        smf[AODN + r0] = 1.f / (smf[AODN + r0] + rs0);
        smf[AODN + r1] = 1.f / (smf[AODN + r1] + rs1);
    }
    __syncwarp();
    const float inv0 = smf[AODN + r0];
    const float inv1 = smf[AODN + r1];

    // ---- mma-pre: accO = Q S_pre (16 x 64 per warp) ----
    float accO[8][4];
    #pragma unroll
    for (int ni = 0; ni < 8; ++ni)
        #pragma unroll
        for (int j = 0; j < 4; ++j) accO[ni][j] = 0.f;

    #pragma unroll
    for (int k8 = 0; k8 < 8; ++k8) {
        #pragma unroll
        for (int ni = 0; ni < 8; ++ni) {
            const uint32_t* p = smu + AOP + (ni * 8 + g) * LQK + k8 * 8 + t;
            mma_tf32(accO[ni][0], accO[ni][1], accO[ni][2], accO[ni][3],
                     aq[k8][0], aq[k8][1], aq[k8][2], aq[k8][3], p[0], p[4]);
        }
    }

    // ---- mma2: accO += scores V (k = 128) ----
    #pragma unroll
    for (int k8 = 0; k8 < 16; ++k8) {
        uint32_t as[4];
        const uint32_t* ap = smu + AOS + r0 * LSV + k8 * 8 + t;
        as[0] = ap[0];
        as[2] = ap[4];
        as[1] = ap[8 * LSV];
        as[3] = ap[8 * LSV + 4];
        #pragma unroll
        for (int ni = 0; ni < 8; ++ni) {
            const uint32_t* p = smu + AOV + (ni * 8 + g) * LSV + k8 * 8 + t;
            mma_tf32(accO[ni][0], accO[ni][1], accO[ni][2], accO[ni][3],
                     as[0], as[1], as[2], as[3], p[0], p[4]);
        }
    }

    // ---- epilogue ----
    #pragma unroll
    for (int ni = 0; ni < 8; ++ni) {
        const int e0 = ni * 8 + 2 * t;
        float2 o0 = make_float2(accO[ni][0] * inv0 + EPSC, accO[ni][1] * inv0 + EPSC);
        float2 o1 = make_float2(accO[ni][2] * inv1 + EPSC, accO[ni][3] * inv1 + EPSC);
        *(float2*)(ga + (size_t)r0 * Dmod + e0) = o0;
        *(float2*)(ga + (size_t)r1 * Dmod + e0) = o1;
    }
}

// ---------------------------------------------------------------------------
extern "C" void kernel_launch(void* const* d_in, const int* in_sizes, int n_in,
                              void* d_out, int out_size) {
    const float* x  = (const float*)d_in[0];
    const float* Wq = (const float*)d_in[1];
    const float* Wk = (const float*)d_in[2];
    const float* Wv = (const float*)d_in[3];
    const float* Wo = (const float*)d_in[4];
    float* out = (float*)d_out;

    cudaFuncSetAttribute(mma_gemm, cudaFuncAttributeMaxDynamicSharedMemorySize,
                         GEMM_SMEM_BYTES);
    cudaFuncSetAttribute(attn_local, cudaFuncAttributeMaxDynamicSharedMemorySize,
                         P1_SMEM_BYTES);
    cudaFuncSetAttribute(attn_out, cudaFuncAttributeMaxDynamicSharedMemorySize,
                         AO_SMEM_BYTES);

    // 1) Q/K/V projections (tf32 mma.sync, convert-on-store) + elu+1 + relayout
    mma_gemm<<<dim3(Dmod / 128, Mrows / 128, 3), 256, GEMM_SMEM_BYTES>>>(
        x, Wq, Wk, Wv, nullptr, 0);
    // 2) attention: local transposed states -> prefix scan -> tensor-core outputs
    attn_local<<<NBH * NCH, 128, P1_SMEM_BYTES>>>();
    attn_scan<<<NBH, 256>>>();
    attn_out<<<NBH * NCH, 256, AO_SMEM_BYTES>>>();
    // 3) output projection
    mma_gemm<<<dim3(Dmod / 128, Mrows / 128, 1), 256, GEMM_SMEM_BYTES>>>(
        nullptr, Wo, Wo, Wo, out, 1);
}

// round 7
// speedup vs baseline: 4.5793x; 1.0781x over previous
#include <cuda_runtime.h>
#include <math.h>
#include <stdint.h>

// Problem constants
#define Bsz   4
#define Lseq  4096
#define Dmod  1024
#define Hn    16
#define HDim  64
#define CH    128
#define NCH   32
#define Mrows (Bsz*Lseq)          // 16384
#define NBH   (Bsz*Hn)            // 64
#define EPSC  1e-12f

// Scratch (device globals — allocation-free per harness rules)
__device__ float g_q[(size_t)NBH*Lseq*HDim];        // (b,h,l,d) fp32
__device__ float g_k[(size_t)NBH*Lseq*HDim];
__device__ float g_v[(size_t)NBH*Lseq*HDim];
__device__ float g_attn[(size_t)Bsz*Lseq*Dmod];     // (b,l,D), tf32-rounded values
__device__ float g_xt[(size_t)Mrows*Dmod];          // X pre-rounded to tf32
__device__ float g_wt[(size_t)4*Dmod*Dmod];         // Wq,Wk,Wv,Wo tf32
// chunk-scan state (stored TRANSPOSED, e-major: S^T[e][d])
__device__ float g_Sloc[(size_t)NBH*NCH*HDim*HDim];
__device__ float g_Spre[(size_t)NBH*NCH*HDim*HDim];
__device__ float g_zloc[(size_t)NBH*NCH*HDim];
__device__ float g_zpre[(size_t)NBH*NCH*HDim];

// ---------------------------------------------------------------------------
// PTX helpers
// ---------------------------------------------------------------------------
__device__ __forceinline__ uint32_t f2tf32(float x) {
    uint32_t r;
    asm("cvt.rna.tf32.f32 %0, %1;" : "=r"(r) : "f"(x));
    return r;
}
__device__ __forceinline__ void mma_tf32(float& c0, float& c1, float& c2, float& c3,
                                         uint32_t a0, uint32_t a1, uint32_t a2, uint32_t a3,
                                         uint32_t b0, uint32_t b1) {
    asm volatile(
        "mma.sync.aligned.m16n8k8.row.col.f32.tf32.tf32.f32 "
        "{%0,%1,%2,%3}, {%4,%5,%6,%7}, {%8,%9}, {%0,%1,%2,%3};"
        : "+f"(c0), "+f"(c1), "+f"(c2), "+f"(c3)
        : "r"(a0), "r"(a1), "r"(a2), "r"(a3), "r"(b0), "r"(b1));
}

// ---------------------------------------------------------------------------
// One-time tf32 conversion of X and the four weight matrices.
// ---------------------------------------------------------------------------
#define XN4 (Mrows*Dmod/4)        // 4,194,304
#define WN4 (Dmod*Dmod/4)         // 262,144 (= 2^18)
#define TOTN4 (XN4 + 4*WN4)

__global__ __launch_bounds__(256) void conv_tf32(const float4* __restrict__ x,
                                                 const float4* __restrict__ wq,
                                                 const float4* __restrict__ wk,
                                                 const float4* __restrict__ wv,
                                                 const float4* __restrict__ wo) {
    const int stride = gridDim.x * blockDim.x;
    for (int i = blockIdx.x * blockDim.x + threadIdx.x; i < TOTN4; i += stride) {
        float4 v;
        uint4* dst;
        if (i < XN4) {
            v = __ldg(x + i);
            dst = (uint4*)g_xt + i;
        } else {
            const int r = i - XN4;
            const int w = r >> 18;
            const int off = r & (WN4 - 1);
            const float4* src = (w == 0) ? wq : (w == 1) ? wk : (w == 2) ? wv : wo;
            v = __ldg(src + off);
            dst = (uint4*)g_wt + (size_t)w * WN4 + off;
        }
        *dst = make_uint4(f2tf32(v.x), f2tf32(v.y), f2tf32(v.z), f2tf32(v.w));
    }
}

// ---------------------------------------------------------------------------
// tf32 mma.sync GEMM: C[m][n] = sum_k A[m][k] * W[n][k]
// Inputs are PRE-ROUNDED tf32 bits -> mainloop is pure LDG/STS/LDS/HMMA.
// CTA 128x128, BK=32, 8 warps (2x4 -> 64x32 warp tiles), LDG double buffer.
// mode 0: A=g_xt, W=g_wt[z]; out -> g_q/g_k/g_v with elu+1 (q,k), (b,h,l,d) layout
// mode 1: A=g_attn (tf32 bits), W=g_wt[3]; out -> OutPlain [Mrows,Dmod] fp32
// ---------------------------------------------------------------------------
#define BK 32
#define LDP 36
#define TILE_FLOATS (128 * LDP)
#define STAGE_FLOATS (2 * TILE_FLOATS)
#define GEMM_SMEM_BYTES (2 * STAGE_FLOATS * 4)   // 73728

__global__ __launch_bounds__(256, 2) void mma_gemm(float* __restrict__ OutPlain,
                                                   int mode) {
    extern __shared__ __align__(16) uint32_t smu[];

    const int tid  = threadIdx.x;
    const int wid  = tid >> 5;
    const int lane = tid & 31;
    const int g    = lane >> 2;
    const int t    = lane & 3;

    const int w = blockIdx.z;
    const uint32_t* A  = (mode == 1) ? (const uint32_t*)g_attn : (const uint32_t*)g_xt;
    const uint32_t* Wm = (const uint32_t*)g_wt
                       + (size_t)((mode == 1) ? 3 : w) * Dmod * Dmod;
    float* outp = (w == 0) ? g_q : (w == 1) ? g_k : g_v;

    const int rowBase = blockIdx.y * 128;
    const int colBase = blockIdx.x * 128;
    const int mBase = (wid >> 2) * 64;
    const int nBase = (wid & 3) * 32;

    const int ldRow = tid >> 3;
    const int ldC4  = tid & 7;
    const uint32_t* aG = A  + (size_t)(rowBase + ldRow) * Dmod + ldC4 * 4;
    const uint32_t* bG = Wm + (size_t)(colBase + ldRow) * Dmod + ldC4 * 4;

    float acc[4][4][4];
    #pragma unroll
    for (int mi = 0; mi < 4; ++mi)
        #pragma unroll
        for (int ni = 0; ni < 4; ++ni)
            #pragma unroll
            for (int j = 0; j < 4; ++j) acc[mi][ni][j] = 0.f;

    uint4 pA[4], pB[4];
    #pragma unroll
    for (int i = 0; i < 4; ++i) {
        pA[i] = __ldg((const uint4*)(aG + (size_t)(32 * i) * Dmod));
        pB[i] = __ldg((const uint4*)(bG + (size_t)(32 * i) * Dmod));
    }

    const int NKT = Dmod / BK;
    for (int kt = 0; kt < NKT; ++kt) {
        const int cur = kt & 1;
        uint32_t* stA = smu + cur * STAGE_FLOATS;
        uint32_t* stB = stA + TILE_FLOATS;

        #pragma unroll
        for (int i = 0; i < 4; ++i) {
            const uint32_t soff = (uint32_t)(ldRow + 32 * i) * LDP + ldC4 * 4;
            *(uint4*)(stA + soff) = pA[i];
            *(uint4*)(stB + soff) = pB[i];
        }
        if (kt + 1 < NKT) {
            #pragma unroll
            for (int i = 0; i < 4; ++i) {
                pA[i] = __ldg((const uint4*)(aG + (size_t)(32 * i) * Dmod + (kt + 1) * BK));
                pB[i] = __ldg((const uint4*)(bG + (size_t)(32 * i) * Dmod + (kt + 1) * BK));
            }
        }
        __syncthreads();

        const uint32_t* As = smu + cur * STAGE_FLOATS;
        const uint32_t* Bs = As + TILE_FLOATS;

        #pragma unroll
        for (int k8 = 0; k8 < 4; ++k8) {
            const int kk = k8 * 8;
            uint32_t af[4][4], bf[4][2];
            #pragma unroll
            for (int mi = 0; mi < 4; ++mi) {
                const uint32_t* ar = As + (mBase + mi * 16 + g) * LDP + kk + t;
                af[mi][0] = ar[0];
                af[mi][2] = ar[4];
                af[mi][1] = ar[8 * LDP];
                af[mi][3] = ar[8 * LDP + 4];
            }
            #pragma unroll
            for (int ni = 0; ni < 4; ++ni) {
                const uint32_t* br = Bs + (nBase + ni * 8 + g) * LDP + kk + t;
                bf[ni][0] = br[0];
                bf[ni][1] = br[4];
            }
            #pragma unroll
            for (int mi = 0; mi < 4; ++mi)
                #pragma unroll
                for (int ni = 0; ni < 4; ++ni)
                    mma_tf32(acc[mi][ni][0], acc[mi][ni][1], acc[mi][ni][2], acc[mi][ni][3],
                             af[mi][0], af[mi][1], af[mi][2], af[mi][3],
                             bf[ni][0], bf[ni][1]);
        }
        __syncthreads();
    }

    const bool do_elu = (mode == 0) && (w < 2);
    #pragma unroll
    for (int mi = 0; mi < 4; ++mi) {
        #pragma unroll
        for (int ni = 0; ni < 4; ++ni) {
            const int m0 = rowBase + mBase + mi * 16 + g;
            const int n  = colBase + nBase + ni * 8 + 2 * t;
            #pragma unroll
            for (int half = 0; half < 2; ++half) {
                const int m = m0 + half * 8;
                float v0 = acc[mi][ni][2 * half + 0];
                float v1 = acc[mi][ni][2 * half + 1];
                if (do_elu) {
                    v0 = (v0 > 0.f) ? (v0 + 1.f) : expf(v0);
                    v1 = (v1 > 0.f) ? (v1 + 1.f) : expf(v1);
                }
                if (mode == 0) {
                    const int hh = n >> 6;
                    const int dd = n & 63;
                    const int bb = m >> 12;
                    const int ll = m & (Lseq - 1);
                    float* dst = outp + (((size_t)(bb * Hn + hh) * Lseq + ll) * HDim + dd);
                    *(float2*)dst = make_float2(v0, v1);
                } else {
                    float* dst = OutPlain + (size_t)m * Dmod + n;
                    *(float2*)dst = make_float2(v0, v1);
                }
            }
        }
    }
}

// ---------------------------------------------------------------------------
// Pass 1 (tensor cores): SlocT[e][d] = sum_s V[s,e] K[s,d], zloc[d] = sum_s K[s,d]
// 128 threads = 4 warps; warp w owns e-rows [16w, 16w+16). mma 64x64x128.
// ---------------------------------------------------------------------------
#define LT 132
#define P1_SMEM_BYTES (2 * 64 * LT * 4)   // 67584

__global__ __launch_bounds__(128) void attn_local() {
    extern __shared__ __align__(16) uint32_t smu[];
    uint32_t* Vt = smu;             // [e][s] 64 x 132
    uint32_t* Kt = smu + 64 * LT;   // [d][s] 64 x 132
    float* smf = (float*)smu;

    const int tid  = threadIdx.x;
    const int w    = tid >> 5;
    const int lane = tid & 31;
    const int g    = lane >> 2;
    const int t    = lane & 3;

    const int bc = blockIdx.x;
    const int bh = bc >> 5;
    const int c  = bc & 31;

    const float* gk = g_k + ((size_t)bh * Lseq + (size_t)c * CH) * HDim;
    const float* gv = g_v + ((size_t)bh * Lseq + (size_t)c * CH) * HDim;

    // transpose-stage K and V as tf32 bits
    #pragma unroll
    for (int it = 0; it < 16; ++it) {
        int task = tid + 128 * it;           // 0..2047
        int e = task & 63, s4 = task >> 6;   // s4: 0..31
        uint32_t v0 = f2tf32(__ldg(gv + (size_t)(s4 * 4 + 0) * HDim + e));
        uint32_t v1 = f2tf32(__ldg(gv + (size_t)(s4 * 4 + 1) * HDim + e));
        uint32_t v2 = f2tf32(__ldg(gv + (size_t)(s4 * 4 + 2) * HDim + e));
        uint32_t v3 = f2tf32(__ldg(gv + (size_t)(s4 * 4 + 3) * HDim + e));
        *(uint4*)(Vt + e * LT + s4 * 4) = make_uint4(v0, v1, v2, v3);
        uint32_t k0 = f2tf32(__ldg(gk + (size_t)(s4 * 4 + 0) * HDim + e));
        uint32_t k1 = f2tf32(__ldg(gk + (size_t)(s4 * 4 + 1) * HDim + e));
        uint32_t k2 = f2tf32(__ldg(gk + (size_t)(s4 * 4 + 2) * HDim + e));
        uint32_t k3 = f2tf32(__ldg(gk + (size_t)(s4 * 4 + 3) * HDim + e));
        *(uint4*)(Kt + e * LT + s4 * 4) = make_uint4(k0, k1, k2, k3);
    }
    __syncthreads();

    // zloc: 2 threads per d over Kt rows
    {
        const int d = tid >> 1, hf = tid & 1;
        const float* kr = smf + (Kt - smu) + d * LT + hf * 64;
        float zs = 0.f;
        #pragma unroll
        for (int s = 0; s < 64; ++s) zs += kr[s];
        zs += __shfl_xor_sync(0xffffffffu, zs, 1);
        if (hf == 0) g_zloc[(size_t)bc * HDim + d] = zs;
    }

    const int r0 = w * 16 + g;   // e-row
    const int r1 = r0 + 8;

    float acc[8][4];
    #pragma unroll
    for (int ni = 0; ni < 8; ++ni)
        #pragma unroll
        for (int j = 0; j < 4; ++j) acc[ni][j] = 0.f;

    #pragma unroll
    for (int k8 = 0; k8 < 16; ++k8) {
        uint32_t av[4];
        const uint32_t* ap = Vt + r0 * LT + k8 * 8 + t;
        av[0] = ap[0];
        av[2] = ap[4];
        av[1] = ap[8 * LT];
        av[3] = ap[8 * LT + 4];
        #pragma unroll
        for (int ni = 0; ni < 8; ++ni) {
            const uint32_t* bp = Kt + (ni * 8 + g) * LT + k8 * 8 + t;
            mma_tf32(acc[ni][0], acc[ni][1], acc[ni][2], acc[ni][3],
                     av[0], av[1], av[2], av[3], bp[0], bp[4]);
        }
    }

    float* So = g_Sloc + (size_t)bc * (HDim * HDim);
    #pragma unroll
    for (int ni = 0; ni < 8; ++ni) {
        const int d0 = ni * 8 + 2 * t;
        *(float2*)(So + (size_t)r0 * HDim + d0) = make_float2(acc[ni][0], acc[ni][1]);
        *(float2*)(So + (size_t)r1 * HDim + d0) = make_float2(acc[ni][2], acc[ni][3]);
    }
}

// ---------------------------------------------------------------------------
// Pass 2: exclusive prefix over 32 chunks, split 4-way across S elements.
// grid = NBH*4; block handles 1024 floats of S (one float4/thread/step).
// ---------------------------------------------------------------------------
__global__ __launch_bounds__(256) void attn_scan() {
    const int tid = threadIdx.x;
    const int bh  = blockIdx.x >> 2;
    const int qt  = blockIdx.x & 3;
    const int eoff = qt * 1024 + tid * 4;
    const bool doz = (qt == 0) && (tid < HDim);

    float4 acc = make_float4(0.f, 0.f, 0.f, 0.f);
    float accz = 0.f;

    for (int c = 0; c < NCH; ++c) {
        const size_t base = ((size_t)bh * NCH + c) * (HDim * HDim);
        *(float4*)(g_Spre + base + eoff) = acc;
        float4 lv = *(const float4*)(g_Sloc + base + eoff);
        acc.x += lv.x; acc.y += lv.y; acc.z += lv.z; acc.w += lv.w;
        if (doz) {
            const size_t zb = ((size_t)bh * NCH + c) * HDim + tid;
            g_zpre[zb] = accz;
            accz += g_zloc[zb];
        }
    }
}

// ---------------------------------------------------------------------------
// Pass 3: per-(bh,chunk) output on tensor cores (tf32 mma.sync).
// Output stored tf32-rounded (feeds the tf32 Wo GEMM directly).
// ---------------------------------------------------------------------------
#define LQK 68
#define LSV 132
#define AOQ  0
#define AOK  (AOQ + 128*LQK)
#define AOS  (AOK + 128*LQK)
#define AOV  (AOS + 128*LSV)
#define AOP  (AOV + 64*LSV)
#define AOZ  (AOP + 64*LQK)
#define AODN (AOZ + 64)
#define AO_FLOATS (AODN + 128)
#define AO_SMEM_BYTES (AO_FLOATS * 4)   // 189184

__global__ __launch_bounds__(256) void attn_out() {
    extern __shared__ __align__(16) uint32_t smu[];
    float* smf = (float*)smu;

    const int tid  = threadIdx.x;
    const int w    = tid >> 5;
    const int lane = tid & 31;
    const int g    = lane >> 2;
    const int t    = lane & 3;

    const int bc = blockIdx.x;
    const int bh = bc >> 5;
    const int c  = bc & 31;

    const float* gq = g_q + ((size_t)bh * Lseq + (size_t)c * CH) * HDim;
    const float* gk = g_k + ((size_t)bh * Lseq + (size_t)c * CH) * HDim;
    const float* gv = g_v + ((size_t)bh * Lseq + (size_t)c * CH) * HDim;
    const float* Sp = g_Spre + (size_t)bc * HDim * HDim;   // S^T: [e][d]
    const float* zp = g_zpre + (size_t)bc * HDim;
    float* ga = g_attn + (size_t)(bh >> 4) * Lseq * Dmod
                       + ((size_t)c * CH) * Dmod + (size_t)(bh & 15) * HDim;

    #pragma unroll
    for (int it = 0; it < 8; ++it) {
        int idx = tid + 256 * it;
        int row = idx >> 4, c4 = idx & 15;
        float4 a = __ldg((const float4*)gq + idx);
        float4 b = __ldg((const float4*)gk + idx);
        *(uint4*)(smu + AOQ + row * LQK + c4 * 4) =
            make_uint4(f2tf32(a.x), f2tf32(a.y), f2tf32(a.z), f2tf32(a.w));
        *(uint4*)(smu + AOK + row * LQK + c4 * 4) =
            make_uint4(f2tf32(b.x), f2tf32(b.y), f2tf32(b.z), f2tf32(b.w));
    }
    #pragma unroll
    for (int it = 0; it < 8; ++it) {
        int task = tid + 256 * it;
        int e = task & 63, s4 = task >> 6;
        uint32_t v0 = f2tf32(__ldg(gv + (size_t)(s4 * 4 + 0) * HDim + e));
        uint32_t v1 = f2tf32(__ldg(gv + (size_t)(s4 * 4 + 1) * HDim + e));
        uint32_t v2 = f2tf32(__ldg(gv + (size_t)(s4 * 4 + 2) * HDim + e));
        uint32_t v3 = f2tf32(__ldg(gv + (size_t)(s4 * 4 + 3) * HDim + e));
        *(uint4*)(smu + AOV + e * LSV + s4 * 4) = make_uint4(v0, v1, v2, v3);
    }
    #pragma unroll
    for (int it = 0; it < 4; ++it) {
        int idx = tid + 256 * it;
        int row = idx >> 4, c4 = idx & 15;
        float4 p = __ldg((const float4*)Sp + idx);
        *(uint4*)(smu + AOP + row * LQK + c4 * 4) =
            make_uint4(f2tf32(p.x), f2tf32(p.y), f2tf32(p.z), f2tf32(p.w));
    }
    if (tid < HDim) smf[AOZ + tid] = __ldg(zp + tid);
    __syncthreads();

    {
        const int r = tid >> 1, hf = tid & 1;
        const float* qrow = smf + AOQ + r * LQK + hf * 32;
        const float* zz   = smf + AOZ + hf * 32;
        float s = 0.f;
        #pragma unroll
        for (int d = 0; d < 32; ++d) s += qrow[d] * zz[d];
        s += __shfl_xor_sync(0xffffffffu, s, 1);
        if (hf == 0) smf[AODN + r] = s;
    }

    const int r0 = w * 16 + g;
    const int r1 = r0 + 8;

    uint32_t aq[8][4];
    #pragma unroll
    for (int k8 = 0; k8 < 8; ++k8) {
        const uint32_t* p = smu + AOQ + r0 * LQK + k8 * 8 + t;
        aq[k8][0] = p[0];
        aq[k8][2] = p[4];
        aq[k8][1] = p[8 * LQK];
        aq[k8][3] = p[8 * LQK + 4];
    }

    float acc1[16][4];
    #pragma unroll
    for (int ni = 0; ni < 16; ++ni)
        #pragma unroll
        for (int j = 0; j < 4; ++j) acc1[ni][j] = 0.f;

    #pragma unroll
    for (int k8 = 0; k8 < 8; ++k8) {
        #pragma unroll
        for (int ni = 0; ni < 16; ++ni) {
            const uint32_t* p = smu + AOK + (ni * 8 + g) * LQK + k8 * 8 + t;
            mma_tf32(acc1[ni][0], acc1[ni][1], acc1[ni][2], acc1[ni][3],
                     aq[k8][0], aq[k8][1], aq[k8][2], aq[k8][3], p[0], p[4]);
        }
    }

    float rs0 = 0.f, rs1 = 0.f;
    #pragma unroll
    for (int ni = 0; ni < 16; ++ni) {
        const int cb = ni * 8 + 2 * t;
        float m0 = (cb     <= r0) ? acc1[ni][0] : 0.f;
        float m1 = (cb + 1 <= r0) ? acc1[ni][1] : 0.f;
        float m2 = (cb     <= r1) ? acc1[ni][2] : 0.f;
        float m3 = (cb + 1 <= r1) ? acc1[ni][3] : 0.f;
        rs0 += m0 + m1;
        rs1 += m2 + m3;
        *(uint2*)(smu + AOS + r0 * LSV + cb) = make_uint2(f2tf32(m0), f2tf32(m1));
        *(uint2*)(smu + AOS + r1 * LSV + cb) = make_uint2(f2tf32(m2), f2tf32(m3));
    }
    rs0 += __shfl_xor_sync(0xffffffffu, rs0, 1);
    rs0 += __shfl_xor_sync(0xffffffffu, rs0, 2);
    rs1 += __shfl_xor_sync(0xffffffffu, rs1, 1);
    rs1 += __shfl_xor_sync(0xffffffffu, rs1, 2);
    __syncwarp();
    if (t == 0) {
        smf[AODN + r0] = 1.f / (smf[AODN + r0] + rs0);
        smf[AODN + r1] = 1.f / (smf[AODN + r1] + rs1);
    }
    __syncwarp();
    const float inv0 = smf[AODN + r0];
    const float inv1 = smf[AODN + r1];

    float accO[8][4];
    #pragma unroll
    for (int ni = 0; ni < 8; ++ni)
        #pragma unroll
        for (int j = 0; j < 4; ++j) accO[ni][j] = 0.f;

    #pragma unroll
    for (int k8 = 0; k8 < 8; ++k8) {
        #pragma unroll
        for (int ni = 0; ni < 8; ++ni) {
            const uint32_t* p = smu + AOP + (ni * 8 + g) * LQK + k8 * 8 + t;
            mma_tf32(accO[ni][0], accO[ni][1], accO[ni][2], accO[ni][3],
                     aq[k8][0], aq[k8][1], aq[k8][2], aq[k8][3], p[0], p[4]);
        }
    }

    #pragma unroll
    for (int k8 = 0; k8 < 16; ++k8) {
        uint32_t as[4];
        const uint32_t* ap = smu + AOS + r0 * LSV + k8 * 8 + t;
        as[0] = ap[0];
        as[2] = ap[4];
        as[1] = ap[8 * LSV];
        as[3] = ap[8 * LSV + 4];
        #pragma unroll
        for (int ni = 0; ni < 8; ++ni) {
            const uint32_t* p = smu + AOV + (ni * 8 + g) * LSV + k8 * 8 + t;
            mma_tf32(accO[ni][0], accO[ni][1], accO[ni][2], accO[ni][3],
                     as[0], as[1], as[2], as[3], p[0], p[4]);
        }
    }

    // epilogue: store tf32-rounded outputs (Wo GEMM consumes raw tf32 bits)
    #pragma unroll
    for (int ni = 0; ni < 8; ++ni) {
        const int e0 = ni * 8 + 2 * t;
        uint2 o0 = make_uint2(f2tf32(accO[ni][0] * inv0 + EPSC),
                              f2tf32(accO[ni][1] * inv0 + EPSC));
        uint2 o1 = make_uint2(f2tf32(accO[ni][2] * inv1 + EPSC),
                              f2tf32(accO[ni][3] * inv1 + EPSC));
        *(uint2*)(ga + (size_t)r0 * Dmod + e0) = o0;
        *(uint2*)(ga + (size_t)r1 * Dmod + e0) = o1;
    }
}

// ---------------------------------------------------------------------------
extern "C" void kernel_launch(void* const* d_in, const int* in_sizes, int n_in,
                              void* d_out, int out_size) {
    const float* x  = (const float*)d_in[0];
    const float* Wq = (const float*)d_in[1];
    const float* Wk = (const float*)d_in[2];
    const float* Wv = (const float*)d_in[3];
    const float* Wo = (const float*)d_in[4];
    float* out = (float*)d_out;

    cudaFuncSetAttribute(mma_gemm, cudaFuncAttributeMaxDynamicSharedMemorySize,
                         GEMM_SMEM_BYTES);
    cudaFuncSetAttribute(attn_local, cudaFuncAttributeMaxDynamicSharedMemorySize,
                         P1_SMEM_BYTES);
    cudaFuncSetAttribute(attn_out, cudaFuncAttributeMaxDynamicSharedMemorySize,
                         AO_SMEM_BYTES);

    // 0) one-time tf32 rounding of X and weights
    conv_tf32<<<2048, 256>>>((const float4*)x, (const float4*)Wq,
                             (const float4*)Wk, (const float4*)Wv,
                             (const float4*)Wo);
    // 1) Q/K/V projections (pure tf32 mma.sync) + elu+1 + (b,h,l,d) relayout
    mma_gemm<<<dim3(Dmod / 128, Mrows / 128, 3), 256, GEMM_SMEM_BYTES>>>(nullptr, 0);
    // 2) attention: mma local states -> 4-way split scan -> mma outputs
    attn_local<<<NBH * NCH, 128, P1_SMEM_BYTES>>>();
    attn_scan<<<NBH * 4, 256>>>();
    attn_out<<<NBH * NCH, 256, AO_SMEM_BYTES>>>();
    // 3) output projection
    mma_gemm<<<dim3(Dmod / 128, Mrows / 128, 1), 256, GEMM_SMEM_BYTES>>>(out, 1);
}

// round 8
// speedup vs baseline: 4.8135x; 1.0512x over previous
#include <cuda_runtime.h>
#include <math.h>
#include <stdint.h>

// Problem constants
#define Bsz   4
#define Lseq  4096
#define Dmod  1024
#define Hn    16
#define HDim  64
#define CH    128
#define NCH   32
#define Mrows (Bsz*Lseq)          // 16384
#define NBH   (Bsz*Hn)            // 64
#define EPSC  1e-12f

// Scratch (device globals — allocation-free per harness rules)
__device__ float g_q[(size_t)NBH*Lseq*HDim];        // (b,h,l,d) fp32
__device__ float g_k[(size_t)NBH*Lseq*HDim];
__device__ float g_v[(size_t)NBH*Lseq*HDim];
__device__ float g_attn[(size_t)Bsz*Lseq*Dmod];     // (b,l,D), tf32-rounded values
__device__ float g_xt[(size_t)Mrows*Dmod];          // X pre-rounded to tf32
__device__ float g_wt[(size_t)4*Dmod*Dmod];         // Wq,Wk,Wv,Wo tf32
// chunk-scan state (stored TRANSPOSED, e-major: S^T[e][d])
__device__ float g_Sloc[(size_t)NBH*NCH*HDim*HDim];
__device__ float g_Spre[(size_t)NBH*NCH*HDim*HDim];
__device__ float g_zloc[(size_t)NBH*NCH*HDim];
__device__ float g_zpre[(size_t)NBH*NCH*HDim];

// ---------------------------------------------------------------------------
// PTX helpers
// ---------------------------------------------------------------------------
__device__ __forceinline__ uint32_t smem_u32(const void* p) {
    uint32_t a;
    asm("{ .reg .u64 t; cvta.to.shared.u64 t, %1; cvt.u32.u64 %0, t; }" : "=r"(a) : "l"(p));
    return a;
}
__device__ __forceinline__ uint32_t f2tf32(float x) {
    uint32_t r;
    asm("cvt.rna.tf32.f32 %0, %1;" : "=r"(r) : "f"(x));
    return r;
}
__device__ __forceinline__ void mma_tf32(float& c0, float& c1, float& c2, float& c3,
                                         uint32_t a0, uint32_t a1, uint32_t a2, uint32_t a3,
                                         uint32_t b0, uint32_t b1) {
    asm volatile(
        "mma.sync.aligned.m16n8k8.row.col.f32.tf32.tf32.f32 "
        "{%0,%1,%2,%3}, {%4,%5,%6,%7}, {%8,%9}, {%0,%1,%2,%3};"
        : "+f"(c0), "+f"(c1), "+f"(c2), "+f"(c3)
        : "r"(a0), "r"(a1), "r"(a2), "r"(a3), "r"(b0), "r"(b1));
}
// ldmatrix: x4 -> full m16k8 tf32 A fragment; x2 -> n8k8 tf32 B fragment.
__device__ __forceinline__ void ldsm4(uint32_t* r, uint32_t addr) {
    asm volatile("ldmatrix.sync.aligned.m8n8.x4.shared.b16 {%0,%1,%2,%3}, [%4];"
                 : "=r"(r[0]), "=r"(r[1]), "=r"(r[2]), "=r"(r[3]) : "r"(addr));
}
__device__ __forceinline__ void ldsm2(uint32_t* r, uint32_t addr) {
    asm volatile("ldmatrix.sync.aligned.m8n8.x2.shared.b16 {%0,%1}, [%2];"
                 : "=r"(r[0]), "=r"(r[1]) : "r"(addr));
}

// ---------------------------------------------------------------------------
// One-time tf32 conversion of X and the four weight matrices.
// ---------------------------------------------------------------------------
#define XN4 (Mrows*Dmod/4)
#define WN4 (Dmod*Dmod/4)
#define TOTN4 (XN4 + 4*WN4)

__global__ __launch_bounds__(256) void conv_tf32(const float4* __restrict__ x,
                                                 const float4* __restrict__ wq,
                                                 const float4* __restrict__ wk,
                                                 const float4* __restrict__ wv,
                                                 const float4* __restrict__ wo) {
    const int stride = gridDim.x * blockDim.x;
    for (int i = blockIdx.x * blockDim.x + threadIdx.x; i < TOTN4; i += stride) {
        float4 v;
        uint4* dst;
        if (i < XN4) {
            v = __ldg(x + i);
            dst = (uint4*)g_xt + i;
        } else {
            const int r = i - XN4;
            const int w = r >> 18;
            const int off = r & (WN4 - 1);
            const float4* src = (w == 0) ? wq : (w == 1) ? wk : (w == 2) ? wv : wo;
            v = __ldg(src + off);
            dst = (uint4*)g_wt + (size_t)w * WN4 + off;
        }
        *dst = make_uint4(f2tf32(v.x), f2tf32(v.y), f2tf32(v.z), f2tf32(v.w));
    }
}

// ---------------------------------------------------------------------------
// tf32 mma.sync GEMM with ldmatrix fragment loads.
// CTA 128x128, BK=32, 8 warps (2x4 -> 64x32 warp tiles), LDG double buffer.
// ---------------------------------------------------------------------------
#define BK 32
#define LDP 36
#define TILE_FLOATS (128 * LDP)
#define STAGE_FLOATS (2 * TILE_FLOATS)
#define GEMM_SMEM_BYTES (2 * STAGE_FLOATS * 4)   // 73728

__global__ __launch_bounds__(256, 2) void mma_gemm(float* __restrict__ OutPlain,
                                                   int mode) {
    extern __shared__ __align__(16) uint32_t smu[];
    const uint32_t smb = smem_u32(smu);

    const int tid  = threadIdx.x;
    const int wid  = tid >> 5;
    const int lane = tid & 31;
    const int g    = lane >> 2;
    const int t    = lane & 3;

    const int w = blockIdx.z;
    const uint32_t* A  = (mode == 1) ? (const uint32_t*)g_attn : (const uint32_t*)g_xt;
    const uint32_t* Wm = (const uint32_t*)g_wt
                       + (size_t)((mode == 1) ? 3 : w) * Dmod * Dmod;
    float* outp = (w == 0) ? g_q : (w == 1) ? g_k : g_v;

    const int rowBase = blockIdx.y * 128;
    const int colBase = blockIdx.x * 128;
    const int mBase = (wid >> 2) * 64;
    const int nBase = (wid & 3) * 32;

    const int ldRow = tid >> 3;
    const int ldC4  = tid & 7;
    const uint32_t* aG = A  + (size_t)(rowBase + ldRow) * Dmod + ldC4 * 4;
    const uint32_t* bG = Wm + (size_t)(colBase + ldRow) * Dmod + ldC4 * 4;

    // ldmatrix per-thread base addresses (stage 0, kk = 0)
    const int l15 = lane & 15;
    const int hi4 = (lane >> 4) * 4;       // col offset for A x4
    const int l7  = lane & 7;
    const int b4  = ((lane >> 3) & 1) * 4; // col offset for B x2
    uint32_t aAddr[4], bAddr[4];
    #pragma unroll
    for (int mi = 0; mi < 4; ++mi)
        aAddr[mi] = smb + 4u * ((uint32_t)(mBase + mi * 16 + l15) * LDP + hi4);
    #pragma unroll
    for (int ni = 0; ni < 4; ++ni)
        bAddr[ni] = smb + 4u * ((uint32_t)TILE_FLOATS
                                + (uint32_t)(nBase + ni * 8 + l7) * LDP + b4);

    float acc[4][4][4];
    #pragma unroll
    for (int mi = 0; mi < 4; ++mi)
        #pragma unroll
        for (int ni = 0; ni < 4; ++ni)
            #pragma unroll
            for (int j = 0; j < 4; ++j) acc[mi][ni][j] = 0.f;

    uint4 pA[4], pB[4];
    #pragma unroll
    for (int i = 0; i < 4; ++i) {
        pA[i] = __ldg((const uint4*)(aG + (size_t)(32 * i) * Dmod));
        pB[i] = __ldg((const uint4*)(bG + (size_t)(32 * i) * Dmod));
    }

    const int NKT = Dmod / BK;
    for (int kt = 0; kt < NKT; ++kt) {
        const int cur = kt & 1;
        const uint32_t stageB = (uint32_t)cur * (STAGE_FLOATS * 4);
        uint32_t* stA = smu + cur * STAGE_FLOATS;
        uint32_t* stB = stA + TILE_FLOATS;

        #pragma unroll
        for (int i = 0; i < 4; ++i) {
            const uint32_t soff = (uint32_t)(ldRow + 32 * i) * LDP + ldC4 * 4;
            *(uint4*)(stA + soff) = pA[i];
            *(uint4*)(stB + soff) = pB[i];
        }
        if (kt + 1 < NKT) {
            #pragma unroll
            for (int i = 0; i < 4; ++i) {
                pA[i] = __ldg((const uint4*)(aG + (size_t)(32 * i) * Dmod + (kt + 1) * BK));
                pB[i] = __ldg((const uint4*)(bG + (size_t)(32 * i) * Dmod + (kt + 1) * BK));
            }
        }
        __syncthreads();

        #pragma unroll
        for (int k8 = 0; k8 < 4; ++k8) {
            const uint32_t kb = stageB + k8 * 32;   // 8 floats = 32 bytes
            uint32_t af[4][4], bf[4][2];
            #pragma unroll
            for (int mi = 0; mi < 4; ++mi) ldsm4(af[mi], aAddr[mi] + kb);
            #pragma unroll
            for (int ni = 0; ni < 4; ++ni) ldsm2(bf[ni], bAddr[ni] + kb);
            #pragma unroll
            for (int mi = 0; mi < 4; ++mi)
                #pragma unroll
                for (int ni = 0; ni < 4; ++ni)
                    mma_tf32(acc[mi][ni][0], acc[mi][ni][1], acc[mi][ni][2], acc[mi][ni][3],
                             af[mi][0], af[mi][1], af[mi][2], af[mi][3],
                             bf[ni][0], bf[ni][1]);
        }
        __syncthreads();
    }

    const bool do_elu = (mode == 0) && (w < 2);
    #pragma unroll
    for (int mi = 0; mi < 4; ++mi) {
        #pragma unroll
        for (int ni = 0; ni < 4; ++ni) {
            const int m0 = rowBase + mBase + mi * 16 + g;
            const int n  = colBase + nBase + ni * 8 + 2 * t;
            #pragma unroll
            for (int half = 0; half < 2; ++half) {
                const int m = m0 + half * 8;
                float v0 = acc[mi][ni][2 * half + 0];
                float v1 = acc[mi][ni][2 * half + 1];
                if (do_elu) {
                    v0 = (v0 > 0.f) ? (v0 + 1.f) : expf(v0);
                    v1 = (v1 > 0.f) ? (v1 + 1.f) : expf(v1);
                }
                if (mode == 0) {
                    const int hh = n >> 6;
                    const int dd = n & 63;
                    const int bb = m >> 12;
                    const int ll = m & (Lseq - 1);
                    float* dst = outp + (((size_t)(bb * Hn + hh) * Lseq + ll) * HDim + dd);
                    *(float2*)dst = make_float2(v0, v1);
                } else {
                    float* dst = OutPlain + (size_t)m * Dmod + n;
                    *(float2*)dst = make_float2(v0, v1);
                }
            }
        }
    }
}

// ---------------------------------------------------------------------------
// Pass 1 (tensor cores): SlocT[e][d] = sum_s V[s,e] K[s,d], zloc[d] = sum_s K[s,d]
// ---------------------------------------------------------------------------
#define LT 132
#define P1_SMEM_BYTES (2 * 64 * LT * 4)   // 67584

__global__ __launch_bounds__(128) void attn_local() {
    extern __shared__ __align__(16) uint32_t smu[];
    const uint32_t smb = smem_u32(smu);
    uint32_t* Vt = smu;             // [e][s] 64 x 132
    uint32_t* Kt = smu + 64 * LT;   // [d][s] 64 x 132
    float* smf = (float*)smu;

    const int tid  = threadIdx.x;
    const int w    = tid >> 5;
    const int lane = tid & 31;
    const int g    = lane >> 2;
    const int t    = lane & 3;
    const int l15 = lane & 15;
    const int hi4 = (lane >> 4) * 4;
    const int l7  = lane & 7;
    const int b4  = ((lane >> 3) & 1) * 4;

    const int bc = blockIdx.x;
    const int bh = bc >> 5;
    const int c  = bc & 31;

    const float* gk = g_k + ((size_t)bh * Lseq + (size_t)c * CH) * HDim;
    const float* gv = g_v + ((size_t)bh * Lseq + (size_t)c * CH) * HDim;

    #pragma unroll
    for (int it = 0; it < 16; ++it) {
        int task = tid + 128 * it;
        int e = task & 63, s4 = task >> 6;
        uint32_t v0 = f2tf32(__ldg(gv + (size_t)(s4 * 4 + 0) * HDim + e));
        uint32_t v1 = f2tf32(__ldg(gv + (size_t)(s4 * 4 + 1) * HDim + e));
        uint32_t v2 = f2tf32(__ldg(gv + (size_t)(s4 * 4 + 2) * HDim + e));
        uint32_t v3 = f2tf32(__ldg(gv + (size_t)(s4 * 4 + 3) * HDim + e));
        *(uint4*)(Vt + e * LT + s4 * 4) = make_uint4(v0, v1, v2, v3);
        uint32_t k0 = f2tf32(__ldg(gk + (size_t)(s4 * 4 + 0) * HDim + e));
        uint32_t k1 = f2tf32(__ldg(gk + (size_t)(s4 * 4 + 1) * HDim + e));
        uint32_t k2 = f2tf32(__ldg(gk + (size_t)(s4 * 4 + 2) * HDim + e));
        uint32_t k3 = f2tf32(__ldg(gk + (size_t)(s4 * 4 + 3) * HDim + e));
        *(uint4*)(Kt + e * LT + s4 * 4) = make_uint4(k0, k1, k2, k3);
    }
    __syncthreads();

    {
        const int d = tid >> 1, hf = tid & 1;
        const float* kr = smf + 64 * LT + d * LT + hf * 64;
        float zs = 0.f;
        #pragma unroll
        for (int s = 0; s < 64; ++s) zs += kr[s];
        zs += __shfl_xor_sync(0xffffffffu, zs, 1);
        if (hf == 0) g_zloc[(size_t)bc * HDim + d] = zs;
    }

    const int r0 = w * 16 + g;
    const int r1 = r0 + 8;
    const uint32_t avBase = smb + 4u * ((uint32_t)(w * 16 + l15) * LT + hi4);
    const uint32_t bkBase = smb + 4u * ((uint32_t)(64 * LT) + (uint32_t)l7 * LT + b4);

    float acc[8][4];
    #pragma unroll
    for (int ni = 0; ni < 8; ++ni)
        #pragma unroll
        for (int j = 0; j < 4; ++j) acc[ni][j] = 0.f;

    #pragma unroll
    for (int k8 = 0; k8 < 16; ++k8) {
        uint32_t av[4];
        ldsm4(av, avBase + k8 * 32);
        #pragma unroll
        for (int ni = 0; ni < 8; ++ni) {
            uint32_t bk[2];
            ldsm2(bk, bkBase + (uint32_t)(ni * 8 * LT) * 4 + k8 * 32);
            mma_tf32(acc[ni][0], acc[ni][1], acc[ni][2], acc[ni][3],
                     av[0], av[1], av[2], av[3], bk[0], bk[1]);
        }
    }

    float* So = g_Sloc + (size_t)bc * (HDim * HDim);
    #pragma unroll
    for (int ni = 0; ni < 8; ++ni) {
        const int d0 = ni * 8 + 2 * t;
        *(float2*)(So + (size_t)r0 * HDim + d0) = make_float2(acc[ni][0], acc[ni][1]);
        *(float2*)(So + (size_t)r1 * HDim + d0) = make_float2(acc[ni][2], acc[ni][3]);
    }
}

// ---------------------------------------------------------------------------
// Pass 2: exclusive prefix over 32 chunks, split 4-way across S elements.
// ---------------------------------------------------------------------------
__global__ __launch_bounds__(256) void attn_scan() {
    const int tid = threadIdx.x;
    const int bh  = blockIdx.x >> 2;
    const int qt  = blockIdx.x & 3;
    const int eoff = qt * 1024 + tid * 4;
    const bool doz = (qt == 0) && (tid < HDim);

    float4 acc = make_float4(0.f, 0.f, 0.f, 0.f);
    float accz = 0.f;

    for (int c = 0; c < NCH; ++c) {
        const size_t base = ((size_t)bh * NCH + c) * (HDim * HDim);
        *(float4*)(g_Spre + base + eoff) = acc;
        float4 lv = *(const float4*)(g_Sloc + base + eoff);
        acc.x += lv.x; acc.y += lv.y; acc.z += lv.z; acc.w += lv.w;
        if (doz) {
            const size_t zb = ((size_t)bh * NCH + c) * HDim + tid;
            g_zpre[zb] = accz;
            accz += g_zloc[zb];
        }
    }
}

// ---------------------------------------------------------------------------
// Pass 3: per-(bh,chunk) output on tensor cores, ldmatrix fragment loads.
// ---------------------------------------------------------------------------
#define LQK 68
#define LSV 132
#define AOQ  0
#define AOK  (AOQ + 128*LQK)
#define AOS  (AOK + 128*LQK)
#define AOV  (AOS + 128*LSV)
#define AOP  (AOV + 64*LSV)
#define AOZ  (AOP + 64*LQK)
#define AODN (AOZ + 64)
#define AO_FLOATS (AODN + 128)
#define AO_SMEM_BYTES (AO_FLOATS * 4)   // 189184

__global__ __launch_bounds__(256) void attn_out() {
    extern __shared__ __align__(16) uint32_t smu[];
    const uint32_t smb = smem_u32(smu);
    float* smf = (float*)smu;

    const int tid  = threadIdx.x;
    const int w    = tid >> 5;
    const int lane = tid & 31;
    const int g    = lane >> 2;
    const int t    = lane & 3;
    const int l15 = lane & 15;
    const int hi4 = (lane >> 4) * 4;
    const int l7  = lane & 7;
    const int b4  = ((lane >> 3) & 1) * 4;

    const int bc = blockIdx.x;
    const int bh = bc >> 5;
    const int c  = bc & 31;

    const float* gq = g_q + ((size_t)bh * Lseq + (size_t)c * CH) * HDim;
    const float* gk = g_k + ((size_t)bh * Lseq + (size_t)c * CH) * HDim;
    const float* gv = g_v + ((size_t)bh * Lseq + (size_t)c * CH) * HDim;
    const float* Sp = g_Spre + (size_t)bc * HDim * HDim;   // S^T: [e][d]
    const float* zp = g_zpre + (size_t)bc * HDim;
    float* ga = g_attn + (size_t)(bh >> 4) * Lseq * Dmod
                       + ((size_t)c * CH) * Dmod + (size_t)(bh & 15) * HDim;

    #pragma unroll
    for (int it = 0; it < 8; ++it) {
        int idx = tid + 256 * it;
        int row = idx >> 4, c4 = idx & 15;
        float4 a = __ldg((const float4*)gq + idx);
        float4 b = __ldg((const float4*)gk + idx);
        *(uint4*)(smu + AOQ + row * LQK + c4 * 4) =
            make_uint4(f2tf32(a.x), f2tf32(a.y), f2tf32(a.z), f2tf32(a.w));
        *(uint4*)(smu + AOK + row * LQK + c4 * 4) =
            make_uint4(f2tf32(b.x), f2tf32(b.y), f2tf32(b.z), f2tf32(b.w));
    }
    #pragma unroll
    for (int it = 0; it < 8; ++it) {
        int task = tid + 256 * it;
        int e = task & 63, s4 = task >> 6;
        uint32_t v0 = f2tf32(__ldg(gv + (size_t)(s4 * 4 + 0) * HDim + e));
        uint32_t v1 = f2tf32(__ldg(gv + (size_t)(s4 * 4 + 1) * HDim + e));
        uint32_t v2 = f2tf32(__ldg(gv + (size_t)(s4 * 4 + 2) * HDim + e));
        uint32_t v3 = f2tf32(__ldg(gv + (size_t)(s4 * 4 + 3) * HDim + e));
        *(uint4*)(smu + AOV + e * LSV + s4 * 4) = make_uint4(v0, v1, v2, v3);
    }
    #pragma unroll
    for (int it = 0; it < 4; ++it) {
        int idx = tid + 256 * it;
        int row = idx >> 4, c4 = idx & 15;
        float4 p = __ldg((const float4*)Sp + idx);
        *(uint4*)(smu + AOP + row * LQK + c4 * 4) =
            make_uint4(f2tf32(p.x), f2tf32(p.y), f2tf32(p.z), f2tf32(p.w));
    }
    if (tid < HDim) smf[AOZ + tid] = __ldg(zp + tid);
    __syncthreads();

    {
        const int r = tid >> 1, hf = tid & 1;
        const float* qrow = smf + AOQ + r * LQK + hf * 32;
        const float* zz   = smf + AOZ + hf * 32;
        float s = 0.f;
        #pragma unroll
        for (int d = 0; d < 32; ++d) s += qrow[d] * zz[d];
        s += __shfl_xor_sync(0xffffffffu, s, 1);
        if (hf == 0) smf[AODN + r] = s;
    }

    const int r0 = w * 16 + g;
    const int r1 = r0 + 8;

    const uint32_t aqBase = smb + 4u * ((uint32_t)AOQ + (uint32_t)(w * 16 + l15) * LQK + hi4);
    const uint32_t bkBase = smb + 4u * ((uint32_t)AOK + (uint32_t)l7 * LQK + b4);
    const uint32_t bpBase = smb + 4u * ((uint32_t)AOP + (uint32_t)l7 * LQK + b4);
    const uint32_t asBase = smb + 4u * ((uint32_t)AOS + (uint32_t)(w * 16 + l15) * LSV + hi4);
    const uint32_t bvBase = smb + 4u * ((uint32_t)AOV + (uint32_t)l7 * LSV + b4);

    uint32_t aq[8][4];
    #pragma unroll
    for (int k8 = 0; k8 < 8; ++k8) ldsm4(aq[k8], aqBase + k8 * 32);

    float acc1[16][4];
    #pragma unroll
    for (int ni = 0; ni < 16; ++ni)
        #pragma unroll
        for (int j = 0; j < 4; ++j) acc1[ni][j] = 0.f;

    #pragma unroll
    for (int k8 = 0; k8 < 8; ++k8) {
        #pragma unroll
        for (int ni = 0; ni < 16; ++ni) {
            uint32_t bk[2];
            ldsm2(bk, bkBase + (uint32_t)(ni * 8 * LQK) * 4 + k8 * 32);
            mma_tf32(acc1[ni][0], acc1[ni][1], acc1[ni][2], acc1[ni][3],
                     aq[k8][0], aq[k8][1], aq[k8][2], aq[k8][3], bk[0], bk[1]);
        }
    }

    float rs0 = 0.f, rs1 = 0.f;
    #pragma unroll
    for (int ni = 0; ni < 16; ++ni) {
        const int cb = ni * 8 + 2 * t;
        float m0 = (cb     <= r0) ? acc1[ni][0] : 0.f;
        float m1 = (cb + 1 <= r0) ? acc1[ni][1] : 0.f;
        float m2 = (cb     <= r1) ? acc1[ni][2] : 0.f;
        float m3 = (cb + 1 <= r1) ? acc1[ni][3] : 0.f;
        rs0 += m0 + m1;
        rs1 += m2 + m3;
        *(uint2*)(smu + AOS + r0 * LSV + cb) = make_uint2(f2tf32(m0), f2tf32(m1));
        *(uint2*)(smu + AOS + r1 * LSV + cb) = make_uint2(f2tf32(m2), f2tf32(m3));
    }
    rs0 += __shfl_xor_sync(0xffffffffu, rs0, 1);
    rs0 += __shfl_xor_sync(0xffffffffu, rs0, 2);
    rs1 += __shfl_xor_sync(0xffffffffu, rs1, 1);
    rs1 += __shfl_xor_sync(0xffffffffu, rs1, 2);
    __syncwarp();
    if (t == 0) {
        smf[AODN + r0] = 1.f / (smf[AODN + r0] + rs0);
        smf[AODN + r1] = 1.f / (smf[AODN + r1] + rs1);
    }
    __syncwarp();
    const float inv0 = smf[AODN + r0];
    const float inv1 = smf[AODN + r1];

    float accO[8][4];
    #pragma unroll
    for (int ni = 0; ni < 8; ++ni)
        #pragma unroll
        for (int j = 0; j < 4; ++j) accO[ni][j] = 0.f;

    #pragma unroll
    for (int k8 = 0; k8 < 8; ++k8) {
        #pragma unroll
        for (int ni = 0; ni < 8; ++ni) {
            uint32_t bp[2];
            ldsm2(bp, bpBase + (uint32_t)(ni * 8 * LQK) * 4 + k8 * 32);
            mma_tf32(accO[ni][0], accO[ni][1], accO[ni][2], accO[ni][3],
                     aq[k8][0], aq[k8][1], aq[k8][2], aq[k8][3], bp[0], bp[1]);
        }
    }

    #pragma unroll
    for (int k8 = 0; k8 < 16; ++k8) {
        uint32_t as[4];
        ldsm4(as, asBase + k8 * 32);
        #pragma unroll
        for (int ni = 0; ni < 8; ++ni) {
            uint32_t bv[2];
            ldsm2(bv, bvBase + (uint32_t)(ni * 8 * LSV) * 4 + k8 * 32);
            mma_tf32(accO[ni][0], accO[ni][1], accO[ni][2], accO[ni][3],
                     as[0], as[1], as[2], as[3], bv[0], bv[1]);
        }
    }

    #pragma unroll
    for (int ni = 0; ni < 8; ++ni) {
        const int e0 = ni * 8 + 2 * t;
        uint2 o0 = make_uint2(f2tf32(accO[ni][0] * inv0 + EPSC),
                              f2tf32(accO[ni][1] * inv0 + EPSC));
        uint2 o1 = make_uint2(f2tf32(accO[ni][2] * inv1 + EPSC),
                              f2tf32(accO[ni][3] * inv1 + EPSC));
        *(uint2*)(ga + (size_t)r0 * Dmod + e0) = o0;
        *(uint2*)(ga + (size_t)r1 * Dmod + e0) = o1;
    }
}

// ---------------------------------------------------------------------------
extern "C" void kernel_launch(void* const* d_in, const int* in_sizes, int n_in,
                              void* d_out, int out_size) {
    const float* x  = (const float*)d_in[0];
    const float* Wq = (const float*)d_in[1];
    const float* Wk = (const float*)d_in[2];
    const float* Wv = (const float*)d_in[3];
    const float* Wo = (const float*)d_in[4];
    float* out = (float*)d_out;

    cudaFuncSetAttribute(mma_gemm, cudaFuncAttributeMaxDynamicSharedMemorySize,
                         GEMM_SMEM_BYTES);
    cudaFuncSetAttribute(attn_local, cudaFuncAttributeMaxDynamicSharedMemorySize,
                         P1_SMEM_BYTES);
    cudaFuncSetAttribute(attn_out, cudaFuncAttributeMaxDynamicSharedMemorySize,
                         AO_SMEM_BYTES);

    conv_tf32<<<2048, 256>>>((const float4*)x, (const float4*)Wq,
                             (const float4*)Wk, (const float4*)Wv,
                             (const float4*)Wo);
    mma_gemm<<<dim3(Dmod / 128, Mrows / 128, 3), 256, GEMM_SMEM_BYTES>>>(nullptr, 0);
    attn_local<<<NBH * NCH, 128, P1_SMEM_BYTES>>>();
    attn_scan<<<NBH * 4, 256>>>();
    attn_out<<<NBH * NCH, 256, AO_SMEM_BYTES>>>();
    mma_gemm<<<dim3(Dmod / 128, Mrows / 128, 1), 256, GEMM_SMEM_BYTES>>>(out, 1);
}

// round 9
// speedup vs baseline: 7.5950x; 1.5779x over previous
#include <cuda_runtime.h>
#include <cuda_fp16.h>
#include <math.h>
#include <stdint.h>

// Problem constants
#define Bsz   4
#define Lseq  4096
#define Dmod  1024
#define Hn    16
#define HDim  64
#define CH    128
#define NCH   32
#define Mrows (Bsz*Lseq)          // 16384
#define NBH   (Bsz*Hn)            // 64
#define EPSC  1e-12f

// Scratch (device globals — allocation-free per harness rules)
__device__ float  g_q[(size_t)NBH*Lseq*HDim];        // (b,h,l,d) fp32
__device__ float  g_k[(size_t)NBH*Lseq*HDim];
__device__ float  g_v[(size_t)NBH*Lseq*HDim];
__device__ __half g_attn[(size_t)Bsz*Lseq*Dmod];     // (b,l,D) fp16
__device__ __half g_xt[(size_t)Mrows*Dmod];          // X in fp16
__device__ __half g_wt[(size_t)4*Dmod*Dmod];         // Wq,Wk,Wv,Wo fp16
// chunk-scan state (stored TRANSPOSED, e-major: S^T[e][d])
__device__ float g_Sloc[(size_t)NBH*NCH*HDim*HDim];
__device__ float g_Spre[(size_t)NBH*NCH*HDim*HDim];
__device__ float g_zloc[(size_t)NBH*NCH*HDim];
__device__ float g_zpre[(size_t)NBH*NCH*HDim];

// ---------------------------------------------------------------------------
// PTX helpers
// ---------------------------------------------------------------------------
__device__ __forceinline__ uint32_t smem_u32(const void* p) {
    uint32_t a;
    asm("{ .reg .u64 t; cvta.to.shared.u64 t, %1; cvt.u32.u64 %0, t; }" : "=r"(a) : "l"(p));
    return a;
}
__device__ __forceinline__ uint32_t f2tf32(float x) {
    uint32_t r;
    asm("cvt.rna.tf32.f32 %0, %1;" : "=r"(r) : "f"(x));
    return r;
}
__device__ __forceinline__ uint32_t pack_h2(float a, float b) {
    __half2 h = __floats2half2_rn(a, b);
    return *(uint32_t*)&h;
}
__device__ __forceinline__ void mma_tf32(float& c0, float& c1, float& c2, float& c3,
                                         uint32_t a0, uint32_t a1, uint32_t a2, uint32_t a3,
                                         uint32_t b0, uint32_t b1) {
    asm volatile(
        "mma.sync.aligned.m16n8k8.row.col.f32.tf32.tf32.f32 "
        "{%0,%1,%2,%3}, {%4,%5,%6,%7}, {%8,%9}, {%0,%1,%2,%3};"
        : "+f"(c0), "+f"(c1), "+f"(c2), "+f"(c3)
        : "r"(a0), "r"(a1), "r"(a2), "r"(a3), "r"(b0), "r"(b1));
}
__device__ __forceinline__ void mma_f16(float& c0, float& c1, float& c2, float& c3,
                                        uint32_t a0, uint32_t a1, uint32_t a2, uint32_t a3,
                                        uint32_t b0, uint32_t b1) {
    asm volatile(
        "mma.sync.aligned.m16n8k16.row.col.f32.f16.f16.f32 "
        "{%0,%1,%2,%3}, {%4,%5,%6,%7}, {%8,%9}, {%0,%1,%2,%3};"
        : "+f"(c0), "+f"(c1), "+f"(c2), "+f"(c3)
        : "r"(a0), "r"(a1), "r"(a2), "r"(a3), "r"(b0), "r"(b1));
}
__device__ __forceinline__ void ldsm4(uint32_t* r, uint32_t addr) {
    asm volatile("ldmatrix.sync.aligned.m8n8.x4.shared.b16 {%0,%1,%2,%3}, [%4];"
                 : "=r"(r[0]), "=r"(r[1]), "=r"(r[2]), "=r"(r[3]) : "r"(addr));
}
__device__ __forceinline__ void ldsm2(uint32_t* r, uint32_t addr) {
    asm volatile("ldmatrix.sync.aligned.m8n8.x2.shared.b16 {%0,%1}, [%2];"
                 : "=r"(r[0]), "=r"(r[1]) : "r"(addr));
}

// ---------------------------------------------------------------------------
// One-time fp16 conversion of X and the four weight matrices.
// Each task converts 8 floats -> 8 halves (one uint4 store).
// ---------------------------------------------------------------------------
#define XN8 (Mrows*Dmod/8)        // 2,097,152
#define WN8 (Dmod*Dmod/8)         // 131,072 (= 2^17)
#define TOTN8 (XN8 + 4*WN8)

__global__ __launch_bounds__(256) void conv_fp16(const float4* __restrict__ x,
                                                 const float4* __restrict__ wq,
                                                 const float4* __restrict__ wk,
                                                 const float4* __restrict__ wv,
                                                 const float4* __restrict__ wo) {
    const int stride = gridDim.x * blockDim.x;
    for (int i = blockIdx.x * blockDim.x + threadIdx.x; i < TOTN8; i += stride) {
        const float4* src;
        uint4* dst;
        if (i < XN8) {
            src = x + (size_t)i * 2;
            dst = (uint4*)g_xt + i;
        } else {
            const int r = i - XN8;
            const int w = r >> 17;
            const int off = r & (WN8 - 1);
            const float4* s = (w == 0) ? wq : (w == 1) ? wk : (w == 2) ? wv : wo;
            src = s + (size_t)off * 2;
            dst = (uint4*)g_wt + (size_t)w * WN8 + off;
        }
        float4 lo = __ldg(src);
        float4 hi = __ldg(src + 1);
        *dst = make_uint4(pack_h2(lo.x, lo.y), pack_h2(lo.z, lo.w),
                          pack_h2(hi.x, hi.y), pack_h2(hi.z, hi.w));
    }
}

// ---------------------------------------------------------------------------
// fp16 m16n8k16 GEMM: C[m][n] = sum_k A[m][k] * W[n][k]
// CTA 128x128, BK=64, 8 warps (2x4 -> 64x32 warp tiles), LDG double buffer.
// mode 0: A=g_xt; out -> g_q/g_k/g_v with elu+1 (q,k), (b,h,l,d) layout (fp32)
// mode 1: A=g_attn; out -> OutPlain [Mrows,Dmod] fp32
// ---------------------------------------------------------------------------
#define BKH 64
#define LDPH 72                          // halves per row (64 data + 8 pad)
#define TILE_HALVES (128 * LDPH)         // 9216
#define STAGE_HALVES (2 * TILE_HALVES)   // 18432
#define STAGE_BYTES (STAGE_HALVES * 2)   // 36864
#define GEMM_SMEM_BYTES (2 * STAGE_BYTES)  // 73728

__global__ __launch_bounds__(256, 2) void mma_gemm(float* __restrict__ OutPlain,
                                                   int mode) {
    extern __shared__ __align__(16) __half smh[];
    const uint32_t smb = smem_u32(smh);

    const int tid  = threadIdx.x;
    const int wid  = tid >> 5;
    const int lane = tid & 31;
    const int g    = lane >> 2;
    const int t    = lane & 3;

    const int w = blockIdx.z;
    const __half* A  = (mode == 1) ? g_attn : g_xt;
    const __half* Wm = g_wt + (size_t)((mode == 1) ? 3 : w) * Dmod * Dmod;
    float* outp = (w == 0) ? g_q : (w == 1) ? g_k : g_v;

    const int rowBase = blockIdx.y * 128;
    const int colBase = blockIdx.x * 128;
    const int mBase = (wid >> 2) * 64;
    const int nBase = (wid & 3) * 32;

    // loader: 4 rows (stride 32) x one 8-half group per thread per matrix
    const int ldRow = tid >> 3;          // 0..31
    const int ldC8  = tid & 7;           // 8-half group
    const __half* aG = A  + (size_t)(rowBase + ldRow) * Dmod + ldC8 * 8;
    const __half* bG = Wm + (size_t)(colBase + ldRow) * Dmod + ldC8 * 8;

    // ldmatrix per-thread base addresses (stage 0, k16 = 0), byte units
    const int l15 = lane & 15;
    const int hi8 = (lane >> 4) * 8;       // half offset for A x4
    const int l7  = lane & 7;
    const int b8  = ((lane >> 3) & 1) * 8; // half offset for B x2
    uint32_t aAddr[4], bAddr[4];
    #pragma unroll
    for (int mi = 0; mi < 4; ++mi)
        aAddr[mi] = smb + 2u * ((uint32_t)(mBase + mi * 16 + l15) * LDPH + hi8);
    #pragma unroll
    for (int ni = 0; ni < 4; ++ni)
        bAddr[ni] = smb + (uint32_t)TILE_HALVES * 2u
                  + 2u * ((uint32_t)(nBase + ni * 8 + l7) * LDPH + b8);

    float acc[4][4][4];
    #pragma unroll
    for (int mi = 0; mi < 4; ++mi)
        #pragma unroll
        for (int ni = 0; ni < 4; ++ni)
            #pragma unroll
            for (int j = 0; j < 4; ++j) acc[mi][ni][j] = 0.f;

    uint4 pA[4], pB[4];
    #pragma unroll
    for (int i = 0; i < 4; ++i) {
        pA[i] = __ldg((const uint4*)(aG + (size_t)(32 * i) * Dmod));
        pB[i] = __ldg((const uint4*)(bG + (size_t)(32 * i) * Dmod));
    }

    const int NKT = Dmod / BKH;   // 16
    for (int kt = 0; kt < NKT; ++kt) {
        const int cur = kt & 1;
        const uint32_t stageByte = (uint32_t)cur * STAGE_BYTES;
        __half* stA = smh + (size_t)cur * STAGE_HALVES;
        __half* stB = stA + TILE_HALVES;

        #pragma unroll
        for (int i = 0; i < 4; ++i) {
            const uint32_t soff = (uint32_t)(ldRow + 32 * i) * LDPH + ldC8 * 8;
            *(uint4*)(stA + soff) = pA[i];
            *(uint4*)(stB + soff) = pB[i];
        }
        if (kt + 1 < NKT) {
            #pragma unroll
            for (int i = 0; i < 4; ++i) {
                pA[i] = __ldg((const uint4*)(aG + (size_t)(32 * i) * Dmod + (kt + 1) * BKH));
                pB[i] = __ldg((const uint4*)(bG + (size_t)(32 * i) * Dmod + (kt + 1) * BKH));
            }
        }
        __syncthreads();

        #pragma unroll
        for (int k16 = 0; k16 < 4; ++k16) {
            const uint32_t kb = stageByte + k16 * 32;   // 16 halves = 32 bytes
            uint32_t af[4][4], bf[4][2];
            #pragma unroll
            for (int mi = 0; mi < 4; ++mi) ldsm4(af[mi], aAddr[mi] + kb);
            #pragma unroll
            for (int ni = 0; ni < 4; ++ni) ldsm2(bf[ni], bAddr[ni] + kb);
            #pragma unroll
            for (int mi = 0; mi < 4; ++mi)
                #pragma unroll
                for (int ni = 0; ni < 4; ++ni)
                    mma_f16(acc[mi][ni][0], acc[mi][ni][1], acc[mi][ni][2], acc[mi][ni][3],
                            af[mi][0], af[mi][1], af[mi][2], af[mi][3],
                            bf[ni][0], bf[ni][1]);
        }
        __syncthreads();
    }

    const bool do_elu = (mode == 0) && (w < 2);
    #pragma unroll
    for (int mi = 0; mi < 4; ++mi) {
        #pragma unroll
        for (int ni = 0; ni < 4; ++ni) {
            const int m0 = rowBase + mBase + mi * 16 + g;
            const int n  = colBase + nBase + ni * 8 + 2 * t;
            #pragma unroll
            for (int half_ = 0; half_ < 2; ++half_) {
                const int m = m0 + half_ * 8;
                float v0 = acc[mi][ni][2 * half_ + 0];
                float v1 = acc[mi][ni][2 * half_ + 1];
                if (do_elu) {
                    v0 = (v0 > 0.f) ? (v0 + 1.f) : expf(v0);
                    v1 = (v1 > 0.f) ? (v1 + 1.f) : expf(v1);
                }
                if (mode == 0) {
                    const int hh = n >> 6;
                    const int dd = n & 63;
                    const int bb = m >> 12;
                    const int ll = m & (Lseq - 1);
                    float* dst = outp + (((size_t)(bb * Hn + hh) * Lseq + ll) * HDim + dd);
                    *(float2*)dst = make_float2(v0, v1);
                } else {
                    float* dst = OutPlain + (size_t)m * Dmod + n;
                    *(float2*)dst = make_float2(v0, v1);
                }
            }
        }
    }
}

// ---------------------------------------------------------------------------
// Pass 1 (tensor cores, tf32): SlocT[e][d] = sum_s V[s,e] K[s,d]
// ---------------------------------------------------------------------------
#define LT 132
#define P1_SMEM_BYTES (2 * 64 * LT * 4)   // 67584

__global__ __launch_bounds__(128) void attn_local() {
    extern __shared__ __align__(16) uint32_t smu[];
    const uint32_t smb = smem_u32(smu);
    uint32_t* Vt = smu;
    uint32_t* Kt = smu + 64 * LT;
    float* smf = (float*)smu;

    const int tid  = threadIdx.x;
    const int w    = tid >> 5;
    const int lane = tid & 31;
    const int g    = lane >> 2;
    const int t    = lane & 3;
    const int l15 = lane & 15;
    const int hi4 = (lane >> 4) * 4;
    const int l7  = lane & 7;
    const int b4  = ((lane >> 3) & 1) * 4;

    const int bc = blockIdx.x;
    const int bh = bc >> 5;
    const int c  = bc & 31;

    const float* gk = g_k + ((size_t)bh * Lseq + (size_t)c * CH) * HDim;
    const float* gv = g_v + ((size_t)bh * Lseq + (size_t)c * CH) * HDim;

    #pragma unroll
    for (int it = 0; it < 16; ++it) {
        int task = tid + 128 * it;
        int e = task & 63, s4 = task >> 6;
        uint32_t v0 = f2tf32(__ldg(gv + (size_t)(s4 * 4 + 0) * HDim + e));
        uint32_t v1 = f2tf32(__ldg(gv + (size_t)(s4 * 4 + 1) * HDim + e));
        uint32_t v2 = f2tf32(__ldg(gv + (size_t)(s4 * 4 + 2) * HDim + e));
        uint32_t v3 = f2tf32(__ldg(gv + (size_t)(s4 * 4 + 3) * HDim + e));
        *(uint4*)(Vt + e * LT + s4 * 4) = make_uint4(v0, v1, v2, v3);
        uint32_t k0 = f2tf32(__ldg(gk + (size_t)(s4 * 4 + 0) * HDim + e));
        uint32_t k1 = f2tf32(__ldg(gk + (size_t)(s4 * 4 + 1) * HDim + e));
        uint32_t k2 = f2tf32(__ldg(gk + (size_t)(s4 * 4 + 2) * HDim + e));
        uint32_t k3 = f2tf32(__ldg(gk + (size_t)(s4 * 4 + 3) * HDim + e));
        *(uint4*)(Kt + e * LT + s4 * 4) = make_uint4(k0, k1, k2, k3);
    }
    __syncthreads();

    {
        const int d = tid >> 1, hf = tid & 1;
        const float* kr = smf + 64 * LT + d * LT + hf * 64;
        float zs = 0.f;
        #pragma unroll
        for (int s = 0; s < 64; ++s) zs += kr[s];
        zs += __shfl_xor_sync(0xffffffffu, zs, 1);
        if (hf == 0) g_zloc[(size_t)bc * HDim + d] = zs;
    }

    const int r0 = w * 16 + g;
    const int r1 = r0 + 8;
    const uint32_t avBase = smb + 4u * ((uint32_t)(w * 16 + l15) * LT + hi4);
    const uint32_t bkBase = smb + 4u * ((uint32_t)(64 * LT) + (uint32_t)l7 * LT + b4);

    float acc[8][4];
    #pragma unroll
    for (int ni = 0; ni < 8; ++ni)
        #pragma unroll
        for (int j = 0; j < 4; ++j) acc[ni][j] = 0.f;

    #pragma unroll
    for (int k8 = 0; k8 < 16; ++k8) {
        uint32_t av[4];
        ldsm4(av, avBase + k8 * 32);
        #pragma unroll
        for (int ni = 0; ni < 8; ++ni) {
            uint32_t bk[2];
            ldsm2(bk, bkBase + (uint32_t)(ni * 8 * LT) * 4 + k8 * 32);
            mma_tf32(acc[ni][0], acc[ni][1], acc[ni][2], acc[ni][3],
                     av[0], av[1], av[2], av[3], bk[0], bk[1]);
        }
    }

    float* So = g_Sloc + (size_t)bc * (HDim * HDim);
    #pragma unroll
    for (int ni = 0; ni < 8; ++ni) {
        const int d0 = ni * 8 + 2 * t;
        *(float2*)(So + (size_t)r0 * HDim + d0) = make_float2(acc[ni][0], acc[ni][1]);
        *(float2*)(So + (size_t)r1 * HDim + d0) = make_float2(acc[ni][2], acc[ni][3]);
    }
}

// ---------------------------------------------------------------------------
// Pass 2: exclusive prefix over 32 chunks, split 4-way across S elements.
// ---------------------------------------------------------------------------
__global__ __launch_bounds__(256) void attn_scan() {
    const int tid = threadIdx.x;
    const int bh  = blockIdx.x >> 2;
    const int qt  = blockIdx.x & 3;
    const int eoff = qt * 1024 + tid * 4;
    const bool doz = (qt == 0) && (tid < HDim);

    float4 acc = make_float4(0.f, 0.f, 0.f, 0.f);
    float accz = 0.f;

    for (int c = 0; c < NCH; ++c) {
        const size_t base = ((size_t)bh * NCH + c) * (HDim * HDim);
        *(float4*)(g_Spre + base + eoff) = acc;
        float4 lv = *(const float4*)(g_Sloc + base + eoff);
        acc.x += lv.x; acc.y += lv.y; acc.z += lv.z; acc.w += lv.w;
        if (doz) {
            const size_t zb = ((size_t)bh * NCH + c) * HDim + tid;
            g_zpre[zb] = accz;
            accz += g_zloc[zb];
        }
    }
}

// ---------------------------------------------------------------------------
// Pass 3: per-(bh,chunk) output on tensor cores (tf32), fp16 output to g_attn.
// ---------------------------------------------------------------------------
#define LQK 68
#define LSV 132
#define AOQ  0
#define AOK  (AOQ + 128*LQK)
#define AOS  (AOK + 128*LQK)
#define AOV  (AOS + 128*LSV)
#define AOP  (AOV + 64*LSV)
#define AOZ  (AOP + 64*LQK)
#define AODN (AOZ + 64)
#define AO_FLOATS (AODN + 128)
#define AO_SMEM_BYTES (AO_FLOATS * 4)   // 189184

__global__ __launch_bounds__(256) void attn_out() {
    extern __shared__ __align__(16) uint32_t smu[];
    const uint32_t smb = smem_u32(smu);
    float* smf = (float*)smu;

    const int tid  = threadIdx.x;
    const int w    = tid >> 5;
    const int lane = tid & 31;
    const int g    = lane >> 2;
    const int t    = lane & 3;
    const int l15 = lane & 15;
    const int hi4 = (lane >> 4) * 4;
    const int l7  = lane & 7;
    const int b4  = ((lane >> 3) & 1) * 4;

    const int bc = blockIdx.x;
    const int bh = bc >> 5;
    const int c  = bc & 31;

    const float* gq = g_q + ((size_t)bh * Lseq + (size_t)c * CH) * HDim;
    const float* gk = g_k + ((size_t)bh * Lseq + (size_t)c * CH) * HDim;
    const float* gv = g_v + ((size_t)bh * Lseq + (size_t)c * CH) * HDim;
    const float* Sp = g_Spre + (size_t)bc * HDim * HDim;
    const float* zp = g_zpre + (size_t)bc * HDim;
    __half* ga = g_attn + (size_t)(bh >> 4) * Lseq * Dmod
                        + ((size_t)c * CH) * Dmod + (size_t)(bh & 15) * HDim;

    #pragma unroll
    for (int it = 0; it < 8; ++it) {
        int idx = tid + 256 * it;
        int row = idx >> 4, c4 = idx & 15;
        float4 a = __ldg((const float4*)gq + idx);
        float4 b = __ldg((const float4*)gk + idx);
        *(uint4*)(smu + AOQ + row * LQK + c4 * 4) =
            make_uint4(f2tf32(a.x), f2tf32(a.y), f2tf32(a.z), f2tf32(a.w));
        *(uint4*)(smu + AOK + row * LQK + c4 * 4) =
            make_uint4(f2tf32(b.x), f2tf32(b.y), f2tf32(b.z), f2tf32(b.w));
    }
    #pragma unroll
    for (int it = 0; it < 8; ++it) {
        int task = tid + 256 * it;
        int e = task & 63, s4 = task >> 6;
        uint32_t v0 = f2tf32(__ldg(gv + (size_t)(s4 * 4 + 0) * HDim + e));
        uint32_t v1 = f2tf32(__ldg(gv + (size_t)(s4 * 4 + 1) * HDim + e));
        uint32_t v2 = f2tf32(__ldg(gv + (size_t)(s4 * 4 + 2) * HDim + e));
        uint32_t v3 = f2tf32(__ldg(gv + (size_t)(s4 * 4 + 3) * HDim + e));
        *(uint4*)(smu + AOV + e * LSV + s4 * 4) = make_uint4(v0, v1, v2, v3);
    }
    #pragma unroll
    for (int it = 0; it < 4; ++it) {
        int idx = tid + 256 * it;
        int row = idx >> 4, c4 = idx & 15;
        float4 p = __ldg((const float4*)Sp + idx);
        *(uint4*)(smu + AOP + row * LQK + c4 * 4) =
            make_uint4(f2tf32(p.x), f2tf32(p.y), f2tf32(p.z), f2tf32(p.w));
    }
    if (tid < HDim) smf[AOZ + tid] = __ldg(zp + tid);
    __syncthreads();

    {
        const int r = tid >> 1, hf = tid & 1;
        const float* qrow = smf + AOQ + r * LQK + hf * 32;
        const float* zz   = smf + AOZ + hf * 32;
        float s = 0.f;
        #pragma unroll
        for (int d = 0; d < 32; ++d) s += qrow[d] * zz[d];
        s += __shfl_xor_sync(0xffffffffu, s, 1);
        if (hf == 0) smf[AODN + r] = s;
    }

    const int r0 = w * 16 + g;
    const int r1 = r0 + 8;

    const uint32_t aqBase = smb + 4u * ((uint32_t)AOQ + (uint32_t)(w * 16 + l15) * LQK + hi4);
    const uint32_t bkBase = smb + 4u * ((uint32_t)AOK + (uint32_t)l7 * LQK + b4);
    const uint32_t bpBase = smb + 4u * ((uint32_t)AOP + (uint32_t)l7 * LQK + b4);
    const uint32_t asBase = smb + 4u * ((uint32_t)AOS + (uint32_t)(w * 16 + l15) * LSV + hi4);
    const uint32_t bvBase = smb + 4u * ((uint32_t)AOV + (uint32_t)l7 * LSV + b4);

    uint32_t aq[8][4];
    #pragma unroll
    for (int k8 = 0; k8 < 8; ++k8) ldsm4(aq[k8], aqBase + k8 * 32);

    float acc1[16][4];
    #pragma unroll
    for (int ni = 0; ni < 16; ++ni)
        #pragma unroll
        for (int j = 0; j < 4; ++j) acc1[ni][j] = 0.f;

    #pragma unroll
    for (int k8 = 0; k8 < 8; ++k8) {
        #pragma unroll
        for (int ni = 0; ni < 16; ++ni) {
            uint32_t bk[2];
            ldsm2(bk, bkBase + (uint32_t)(ni * 8 * LQK) * 4 + k8 * 32);
            mma_tf32(acc1[ni][0], acc1[ni][1], acc1[ni][2], acc1[ni][3],
                     aq[k8][0], aq[k8][1], aq[k8][2], aq[k8][3], bk[0], bk[1]);
        }
    }

    float rs0 = 0.f, rs1 = 0.f;
    #pragma unroll
    for (int ni = 0; ni < 16; ++ni) {
        const int cb = ni * 8 + 2 * t;
        float m0 = (cb     <= r0) ? acc1[ni][0] : 0.f;
        float m1 = (cb + 1 <= r0) ? acc1[ni][1] : 0.f;
        float m2 = (cb     <= r1) ? acc1[ni][2] : 0.f;
        float m3 = (cb + 1 <= r1) ? acc1[ni][3] : 0.f;
        rs0 += m0 + m1;
        rs1 += m2 + m3;
        *(uint2*)(smu + AOS + r0 * LSV + cb) = make_uint2(f2tf32(m0), f2tf32(m1));
        *(uint2*)(smu + AOS + r1 * LSV + cb) = make_uint2(f2tf32(m2), f2tf32(m3));
    }
    rs0 += __shfl_xor_sync(0xffffffffu, rs0, 1);
    rs0 += __shfl_xor_sync(0xffffffffu, rs0, 2);
    rs1 += __shfl_xor_sync(0xffffffffu, rs1, 1);
    rs1 += __shfl_xor_sync(0xffffffffu, rs1, 2);
    __syncwarp();
    if (t == 0) {
        smf[AODN + r0] = 1.f / (smf[AODN + r0] + rs0);
        smf[AODN + r1] = 1.f / (smf[AODN + r1] + rs1);
    }
    __syncwarp();
    const float inv0 = smf[AODN + r0];
    const float inv1 = smf[AODN + r1];

    float accO[8][4];
    #pragma unroll
    for (int ni = 0; ni < 8; ++ni)
        #pragma unroll
        for (int j = 0; j < 4; ++j) accO[ni][j] = 0.f;

    #pragma unroll
    for (int k8 = 0; k8 < 8; ++k8) {
        #pragma unroll
        for (int ni = 0; ni < 8; ++ni) {
            uint32_t bp[2];
            ldsm2(bp, bpBase + (uint32_t)(ni * 8 * LQK) * 4 + k8 * 32);
            mma_tf32(accO[ni][0], accO[ni][1], accO[ni][2], accO[ni][3],
                     aq[k8][0], aq[k8][1], aq[k8][2], aq[k8][3], bp[0], bp[1]);
        }
    }

    #pragma unroll
    for (int k8 = 0; k8 < 16; ++k8) {
        uint32_t as[4];
        ldsm4(as, asBase + k8 * 32);
        #pragma unroll
        for (int ni = 0; ni < 8; ++ni) {
            uint32_t bv[2];
            ldsm2(bv, bvBase + (uint32_t)(ni * 8 * LSV) * 4 + k8 * 32);
            mma_tf32(accO[ni][0], accO[ni][1], accO[ni][2], accO[ni][3],
                     as[0], as[1], as[2], as[3], bv[0], bv[1]);
        }
    }

    // epilogue: store fp16 outputs (Wo fp16 GEMM consumes g_attn directly)
    #pragma unroll
    for (int ni = 0; ni < 8; ++ni) {
        const int e0 = ni * 8 + 2 * t;
        uint32_t o0 = pack_h2(accO[ni][0] * inv0 + EPSC, accO[ni][1] * inv0 + EPSC);
        uint32_t o1 = pack_h2(accO[ni][2] * inv1 + EPSC, accO[ni][3] * inv1 + EPSC);
        *(uint32_t*)(ga + (size_t)r0 * Dmod + e0) = o0;
        *(uint32_t*)(ga + (size_t)r1 * Dmod + e0) = o1;
    }
}

// ---------------------------------------------------------------------------
extern "C" void kernel_launch(void* const* d_in, const int* in_sizes, int n_in,
                              void* d_out, int out_size) {
    const float* x  = (const float*)d_in[0];
    const float* Wq = (const float*)d_in[1];
    const float* Wk = (const float*)d_in[2];
    const float* Wv = (const float*)d_in[3];
    const float* Wo = (const float*)d_in[4];
    float* out = (float*)d_out;

    cudaFuncSetAttribute(mma_gemm, cudaFuncAttributeMaxDynamicSharedMemorySize,
                         GEMM_SMEM_BYTES);
    cudaFuncSetAttribute(attn_local, cudaFuncAttributeMaxDynamicSharedMemorySize,
                         P1_SMEM_BYTES);
    cudaFuncSetAttribute(attn_out, cudaFuncAttributeMaxDynamicSharedMemorySize,
                         AO_SMEM_BYTES);

    conv_fp16<<<2048, 256>>>((const float4*)x, (const float4*)Wq,
                             (const float4*)Wk, (const float4*)Wv,
                             (const float4*)Wo);
    mma_gemm<<<dim3(Dmod / 128, Mrows / 128, 3), 256, GEMM_SMEM_BYTES>>>(nullptr, 0);
    attn_local<<<NBH * NCH, 128, P1_SMEM_BYTES>>>();
    attn_scan<<<NBH * 4, 256>>>();
    attn_out<<<NBH * NCH, 256, AO_SMEM_BYTES>>>();
    mma_gemm<<<dim3(Dmod / 128, Mrows / 128, 1), 256, GEMM_SMEM_BYTES>>>(out, 1);
}

// round 10
// speedup vs baseline: 8.8772x; 1.1688x over previous
#include <cuda_runtime.h>
#include <cuda_fp16.h>
#include <math.h>
#include <stdint.h>

// Problem constants
#define Bsz   4
#define Lseq  4096
#define Dmod  1024
#define Hn    16
#define HDim  64
#define CH    128
#define NCH   32
#define Mrows (Bsz*Lseq)          // 16384
#define NBH   (Bsz*Hn)            // 64
#define EPSC  1e-12f

// Scratch (device globals — allocation-free per harness rules)
__device__ __half g_q[(size_t)NBH*Lseq*HDim];        // (b,h,l,d) fp16
__device__ __half g_k[(size_t)NBH*Lseq*HDim];
__device__ __half g_v[(size_t)NBH*Lseq*HDim];
__device__ __half g_attn[(size_t)Bsz*Lseq*Dmod];     // (b,l,D) fp16
__device__ __half g_xt[(size_t)Mrows*Dmod];          // X in fp16
__device__ __half g_wt[(size_t)4*Dmod*Dmod];         // Wq,Wk,Wv,Wo fp16
// chunk-scan state (fp32, TRANSPOSED e-major: S^T[e][d])
__device__ float g_Sloc[(size_t)NBH*NCH*HDim*HDim];
__device__ float g_Spre[(size_t)NBH*NCH*HDim*HDim];
__device__ float g_zloc[(size_t)NBH*NCH*HDim];
__device__ float g_zpre[(size_t)NBH*NCH*HDim];

// ---------------------------------------------------------------------------
// PTX helpers
// ---------------------------------------------------------------------------
__device__ __forceinline__ uint32_t smem_u32(const void* p) {
    uint32_t a;
    asm("{ .reg .u64 t; cvta.to.shared.u64 t, %1; cvt.u32.u64 %0, t; }" : "=r"(a) : "l"(p));
    return a;
}
__device__ __forceinline__ uint32_t pack_h2(float a, float b) {
    __half2 h = __floats2half2_rn(a, b);
    return *(uint32_t*)&h;
}
__device__ __forceinline__ void mma_f16(float& c0, float& c1, float& c2, float& c3,
                                        uint32_t a0, uint32_t a1, uint32_t a2, uint32_t a3,
                                        uint32_t b0, uint32_t b1) {
    asm volatile(
        "mma.sync.aligned.m16n8k16.row.col.f32.f16.f16.f32 "
        "{%0,%1,%2,%3}, {%4,%5,%6,%7}, {%8,%9}, {%0,%1,%2,%3};"
        : "+f"(c0), "+f"(c1), "+f"(c2), "+f"(c3)
        : "r"(a0), "r"(a1), "r"(a2), "r"(a3), "r"(b0), "r"(b1));
}
__device__ __forceinline__ void ldsm4(uint32_t* r, uint32_t addr) {
    asm volatile("ldmatrix.sync.aligned.m8n8.x4.shared.b16 {%0,%1,%2,%3}, [%4];"
                 : "=r"(r[0]), "=r"(r[1]), "=r"(r[2]), "=r"(r[3]) : "r"(addr));
}
__device__ __forceinline__ void ldsm2(uint32_t* r, uint32_t addr) {
    asm volatile("ldmatrix.sync.aligned.m8n8.x2.shared.b16 {%0,%1}, [%2];"
                 : "=r"(r[0]), "=r"(r[1]) : "r"(addr));
}

// ---------------------------------------------------------------------------
// One-time fp16 conversion of X and the four weight matrices.
// ---------------------------------------------------------------------------
#define XN8 (Mrows*Dmod/8)
#define WN8 (Dmod*Dmod/8)
#define TOTN8 (XN8 + 4*WN8)

__global__ __launch_bounds__(256) void conv_fp16(const float4* __restrict__ x,
                                                 const float4* __restrict__ wq,
                                                 const float4* __restrict__ wk,
                                                 const float4* __restrict__ wv,
                                                 const float4* __restrict__ wo) {
    const int stride = gridDim.x * blockDim.x;
    for (int i = blockIdx.x * blockDim.x + threadIdx.x; i < TOTN8; i += stride) {
        const float4* src;
        uint4* dst;
        if (i < XN8) {
            src = x + (size_t)i * 2;
            dst = (uint4*)g_xt + i;
        } else {
            const int r = i - XN8;
            const int w = r >> 17;
            const int off = r & (WN8 - 1);
            const float4* s = (w == 0) ? wq : (w == 1) ? wk : (w == 2) ? wv : wo;
            src = s + (size_t)off * 2;
            dst = (uint4*)g_wt + (size_t)w * WN8 + off;
        }
        float4 lo = __ldg(src);
        float4 hi = __ldg(src + 1);
        *dst = make_uint4(pack_h2(lo.x, lo.y), pack_h2(lo.z, lo.w),
                          pack_h2(hi.x, hi.y), pack_h2(hi.z, hi.w));
    }
}

// ---------------------------------------------------------------------------
// fp16 m16n8k16 GEMM: C[m][n] = sum_k A[m][k] * W[n][k]
// CTA 128x128, BK=64, 8 warps (2x4 -> 64x32 warp tiles), LDG double buffer.
// mode 0: A=g_xt; out -> g_q/g_k/g_v fp16 with elu+1 (q,k), (b,h,l,d) layout
// mode 1: A=g_attn; out -> OutPlain [Mrows,Dmod] fp32
// ---------------------------------------------------------------------------
#define BKH 64
#define LDPH 72
#define TILE_HALVES (128 * LDPH)
#define STAGE_HALVES (2 * TILE_HALVES)
#define STAGE_BYTES (STAGE_HALVES * 2)
#define GEMM_SMEM_BYTES (2 * STAGE_BYTES)  // 73728

__global__ __launch_bounds__(256, 2) void mma_gemm(float* __restrict__ OutPlain,
                                                   int mode) {
    extern __shared__ __align__(16) __half smh[];
    const uint32_t smb = smem_u32(smh);

    const int tid  = threadIdx.x;
    const int wid  = tid >> 5;
    const int lane = tid & 31;
    const int g    = lane >> 2;
    const int t    = lane & 3;

    const int w = blockIdx.z;
    const __half* A  = (mode == 1) ? g_attn : g_xt;
    const __half* Wm = g_wt + (size_t)((mode == 1) ? 3 : w) * Dmod * Dmod;
    __half* outp = (w == 0) ? g_q : (w == 1) ? g_k : g_v;

    const int rowBase = blockIdx.y * 128;
    const int colBase = blockIdx.x * 128;
    const int mBase = (wid >> 2) * 64;
    const int nBase = (wid & 3) * 32;

    const int ldRow = tid >> 3;
    const int ldC8  = tid & 7;
    const __half* aG = A  + (size_t)(rowBase + ldRow) * Dmod + ldC8 * 8;
    const __half* bG = Wm + (size_t)(colBase + ldRow) * Dmod + ldC8 * 8;

    const int l15 = lane & 15;
    const int hi8 = (lane >> 4) * 8;
    const int l7  = lane & 7;
    const int b8  = ((lane >> 3) & 1) * 8;
    uint32_t aAddr[4], bAddr[4];
    #pragma unroll
    for (int mi = 0; mi < 4; ++mi)
        aAddr[mi] = smb + 2u * ((uint32_t)(mBase + mi * 16 + l15) * LDPH + hi8);
    #pragma unroll
    for (int ni = 0; ni < 4; ++ni)
        bAddr[ni] = smb + (uint32_t)TILE_HALVES * 2u
                  + 2u * ((uint32_t)(nBase + ni * 8 + l7) * LDPH + b8);

    float acc[4][4][4];
    #pragma unroll
    for (int mi = 0; mi < 4; ++mi)
        #pragma unroll
        for (int ni = 0; ni < 4; ++ni)
            #pragma unroll
            for (int j = 0; j < 4; ++j) acc[mi][ni][j] = 0.f;

    uint4 pA[4], pB[4];
    #pragma unroll
    for (int i = 0; i < 4; ++i) {
        pA[i] = __ldg((const uint4*)(aG + (size_t)(32 * i) * Dmod));
        pB[i] = __ldg((const uint4*)(bG + (size_t)(32 * i) * Dmod));
    }

    const int NKT = Dmod / BKH;   // 16
    for (int kt = 0; kt < NKT; ++kt) {
        const int cur = kt & 1;
        const uint32_t stageByte = (uint32_t)cur * STAGE_BYTES;
        __half* stA = smh + (size_t)cur * STAGE_HALVES;
        __half* stB = stA + TILE_HALVES;

        #pragma unroll
        for (int i = 0; i < 4; ++i) {
            const uint32_t soff = (uint32_t)(ldRow + 32 * i) * LDPH + ldC8 * 8;
            *(uint4*)(stA + soff) = pA[i];
            *(uint4*)(stB + soff) = pB[i];
        }
        if (kt + 1 < NKT) {
            #pragma unroll
            for (int i = 0; i < 4; ++i) {
                pA[i] = __ldg((const uint4*)(aG + (size_t)(32 * i) * Dmod + (kt + 1) * BKH));
                pB[i] = __ldg((const uint4*)(bG + (size_t)(32 * i) * Dmod + (kt + 1) * BKH));
            }
        }
        __syncthreads();

        #pragma unroll
        for (int k16 = 0; k16 < 4; ++k16) {
            const uint32_t kb = stageByte + k16 * 32;
            uint32_t af[4][4], bf[4][2];
            #pragma unroll
            for (int mi = 0; mi < 4; ++mi) ldsm4(af[mi], aAddr[mi] + kb);
            #pragma unroll
            for (int ni = 0; ni < 4; ++ni) ldsm2(bf[ni], bAddr[ni] + kb);
            #pragma unroll
            for (int mi = 0; mi < 4; ++mi)
                #pragma unroll
                for (int ni = 0; ni < 4; ++ni)
                    mma_f16(acc[mi][ni][0], acc[mi][ni][1], acc[mi][ni][2], acc[mi][ni][3],
                            af[mi][0], af[mi][1], af[mi][2], af[mi][3],
                            bf[ni][0], bf[ni][1]);
        }
        __syncthreads();
    }

    const bool do_elu = (mode == 0) && (w < 2);
    #pragma unroll
    for (int mi = 0; mi < 4; ++mi) {
        #pragma unroll
        for (int ni = 0; ni < 4; ++ni) {
            const int m0 = rowBase + mBase + mi * 16 + g;
            const int n  = colBase + nBase + ni * 8 + 2 * t;
            #pragma unroll
            for (int half_ = 0; half_ < 2; ++half_) {
                const int m = m0 + half_ * 8;
                float v0 = acc[mi][ni][2 * half_ + 0];
                float v1 = acc[mi][ni][2 * half_ + 1];
                if (do_elu) {
                    v0 = (v0 > 0.f) ? (v0 + 1.f) : expf(v0);
                    v1 = (v1 > 0.f) ? (v1 + 1.f) : expf(v1);
                }
                if (mode == 0) {
                    const int hh = n >> 6;
                    const int dd = n & 63;
                    const int bb = m >> 12;
                    const int ll = m & (Lseq - 1);
                    __half* dst = outp + (((size_t)(bb * Hn + hh) * Lseq + ll) * HDim + dd);
                    *(uint32_t*)dst = pack_h2(v0, v1);
                } else {
                    float* dst = OutPlain + (size_t)m * Dmod + n;
                    *(float2*)dst = make_float2(v0, v1);
                }
            }
        }
    }
}

// ---------------------------------------------------------------------------
// Pass 1 (fp16 tensor cores): SlocT[e][d] = sum_s V[s,e] K[s,d], zloc from K.
// 128 threads = 4 warps; warp w owns e-rows [16w, 16w+16). mma 64x64x128.
// ---------------------------------------------------------------------------
#define LTH 136
#define P1_SMEM_BYTES (2 * 64 * LTH * 2)   // 34816

__global__ __launch_bounds__(128) void attn_local() {
    extern __shared__ __align__(16) __half smh[];
    const uint32_t smb = smem_u32(smh);
    __half* Vt = smh;               // [e][s] 64 x 136
    __half* Kt = smh + 64 * LTH;    // [d][s] 64 x 136

    const int tid  = threadIdx.x;
    const int w    = tid >> 5;
    const int lane = tid & 31;
    const int g    = lane >> 2;
    const int t    = lane & 3;
    const int l15 = lane & 15;
    const int hi8 = (lane >> 4) * 8;
    const int l7  = lane & 7;
    const int b8  = ((lane >> 3) & 1) * 8;

    const int bc = blockIdx.x;
    const int bh = bc >> 5;
    const int c  = bc & 31;

    const __half* gk = g_k + ((size_t)bh * Lseq + (size_t)c * CH) * HDim;
    const __half* gv = g_v + ((size_t)bh * Lseq + (size_t)c * CH) * HDim;

    // transpose-stage: task = (e, s8-group); 8 strided fp16 loads -> uint4
    #pragma unroll
    for (int it = 0; it < 8; ++it) {
        int task = tid + 128 * it;           // 0..1023
        int e = task & 63, s8 = task >> 6;   // s8: 0..15
        uint32_t p[4];
        #pragma unroll
        for (int j = 0; j < 4; ++j) {
            __half a = __ldg(gv + (size_t)(s8 * 8 + 2 * j + 0) * HDim + e);
            __half b = __ldg(gv + (size_t)(s8 * 8 + 2 * j + 1) * HDim + e);
            p[j] = *(uint16_t*)&a | ((uint32_t)*(uint16_t*)&b << 16);
        }
        *(uint4*)(Vt + e * LTH + s8 * 8) = make_uint4(p[0], p[1], p[2], p[3]);
        #pragma unroll
        for (int j = 0; j < 4; ++j) {
            __half a = __ldg(gk + (size_t)(s8 * 8 + 2 * j + 0) * HDim + e);
            __half b = __ldg(gk + (size_t)(s8 * 8 + 2 * j + 1) * HDim + e);
            p[j] = *(uint16_t*)&a | ((uint32_t)*(uint16_t*)&b << 16);
        }
        *(uint4*)(Kt + e * LTH + s8 * 8) = make_uint4(p[0], p[1], p[2], p[3]);
    }
    __syncthreads();

    // zloc: 2 threads per d over Kt row (fp16 -> fp32 sum)
    {
        const int d = tid >> 1, hf = tid & 1;
        const __half2* kr = (const __half2*)(Kt + d * LTH + hf * 64);
        float zs = 0.f;
        #pragma unroll
        for (int s = 0; s < 32; ++s) {
            float2 f = __half22float2(kr[s]);
            zs += f.x + f.y;
        }
        zs += __shfl_xor_sync(0xffffffffu, zs, 1);
        if (hf == 0) g_zloc[(size_t)bc * HDim + d] = zs;
    }

    const int r0 = w * 16 + g;
    const int r1 = r0 + 8;
    const uint32_t avBase = smb + 2u * ((uint32_t)(w * 16 + l15) * LTH + hi8);
    const uint32_t bkBase = smb + 2u * ((uint32_t)(64 * LTH) + (uint32_t)l7 * LTH + b8);

    float acc[8][4];
    #pragma unroll
    for (int ni = 0; ni < 8; ++ni)
        #pragma unroll
        for (int j = 0; j < 4; ++j) acc[ni][j] = 0.f;

    #pragma unroll
    for (int k16 = 0; k16 < 8; ++k16) {
        uint32_t av[4];
        ldsm4(av, avBase + k16 * 32);
        #pragma unroll
        for (int ni = 0; ni < 8; ++ni) {
            uint32_t bk[2];
            ldsm2(bk, bkBase + (uint32_t)(ni * 8 * LTH) * 2 + k16 * 32);
            mma_f16(acc[ni][0], acc[ni][1], acc[ni][2], acc[ni][3],
                    av[0], av[1], av[2], av[3], bk[0], bk[1]);
        }
    }

    float* So = g_Sloc + (size_t)bc * (HDim * HDim);
    #pragma unroll
    for (int ni = 0; ni < 8; ++ni) {
        const int d0 = ni * 8 + 2 * t;
        *(float2*)(So + (size_t)r0 * HDim + d0) = make_float2(acc[ni][0], acc[ni][1]);
        *(float2*)(So + (size_t)r1 * HDim + d0) = make_float2(acc[ni][2], acc[ni][3]);
    }
}

// ---------------------------------------------------------------------------
// Pass 2: exclusive prefix over 32 chunks, split 4-way across S elements.
// ---------------------------------------------------------------------------
__global__ __launch_bounds__(256) void attn_scan() {
    const int tid = threadIdx.x;
    const int bh  = blockIdx.x >> 2;
    const int qt  = blockIdx.x & 3;
    const int eoff = qt * 1024 + tid * 4;
    const bool doz = (qt == 0) && (tid < HDim);

    float4 acc = make_float4(0.f, 0.f, 0.f, 0.f);
    float accz = 0.f;

    for (int c = 0; c < NCH; ++c) {
        const size_t base = ((size_t)bh * NCH + c) * (HDim * HDim);
        *(float4*)(g_Spre + base + eoff) = acc;
        float4 lv = *(const float4*)(g_Sloc + base + eoff);
        acc.x += lv.x; acc.y += lv.y; acc.z += lv.z; acc.w += lv.w;
        if (doz) {
            const size_t zb = ((size_t)bh * NCH + c) * HDim + tid;
            g_zpre[zb] = accz;
            accz += g_zloc[zb];
        }
    }
}

// ---------------------------------------------------------------------------
// Pass 3: per-(bh,chunk) output, all-fp16 mma. 256 threads = 8 warps.
// SMEM (halves): Q 128x72 | K 128x72 | S 128x136 | V 64x136 | P 64x72,
// then fp32: z[64], dn[128].
// ---------------------------------------------------------------------------
#define LQH 72
#define LSH 136
#define HQ  0
#define HK  (HQ + 128*LQH)       // 9216
#define HS  (HK + 128*LQH)       // 18432
#define HV  (HS + 128*LSH)       // 35840
#define HP  (HV + 64*LSH)        // 44544
#define HEND (HP + 64*LQH)       // 49152 halves
#define FZ  (HEND/2)             // float index 24576
#define FDN (FZ + 64)
#define AO_SMEM_BYTES ((FDN + 128) * 4)   // 99072

__global__ __launch_bounds__(256) void attn_out() {
    extern __shared__ __align__(16) __half smh[];
    const uint32_t smb = smem_u32(smh);
    float* smf = (float*)smh;

    const int tid  = threadIdx.x;
    const int w    = tid >> 5;
    const int lane = tid & 31;
    const int g    = lane >> 2;
    const int t    = lane & 3;
    const int l15 = lane & 15;
    const int hi8 = (lane >> 4) * 8;
    const int l7  = lane & 7;
    const int b8  = ((lane >> 3) & 1) * 8;

    const int bc = blockIdx.x;
    const int bh = bc >> 5;
    const int c  = bc & 31;

    const __half* gq = g_q + ((size_t)bh * Lseq + (size_t)c * CH) * HDim;
    const __half* gk = g_k + ((size_t)bh * Lseq + (size_t)c * CH) * HDim;
    const __half* gv = g_v + ((size_t)bh * Lseq + (size_t)c * CH) * HDim;
    const float* Sp = g_Spre + (size_t)bc * HDim * HDim;   // S^T: [e][d]
    const float* zp = g_zpre + (size_t)bc * HDim;
    __half* ga = g_attn + (size_t)(bh >> 4) * Lseq * Dmod
                        + ((size_t)c * CH) * Dmod + (size_t)(bh & 15) * HDim;

    // ---- stage Q, K (direct fp16 copy, 8 uint4 per row) ----
    #pragma unroll
    for (int it = 0; it < 4; ++it) {
        int idx = tid + 256 * it;            // 0..1023
        int row = idx >> 3, c8 = idx & 7;
        *(uint4*)(smh + HQ + row * LQH + c8 * 8) = __ldg((const uint4*)gq + idx);
        *(uint4*)(smh + HK + row * LQH + c8 * 8) = __ldg((const uint4*)gk + idx);
    }
    // ---- stage V transposed: Vt[e][s] ----
    #pragma unroll
    for (int it = 0; it < 4; ++it) {
        int task = tid + 256 * it;           // 0..1023
        int e = task & 63, s8 = task >> 6;   // s8: 0..15
        uint32_t p[4];
        #pragma unroll
        for (int j = 0; j < 4; ++j) {
            __half a = __ldg(gv + (size_t)(s8 * 8 + 2 * j + 0) * HDim + e);
            __half b = __ldg(gv + (size_t)(s8 * 8 + 2 * j + 1) * HDim + e);
            p[j] = *(uint16_t*)&a | ((uint32_t)*(uint16_t*)&b << 16);
        }
        *(uint4*)(smh + HV + e * LSH + s8 * 8) = make_uint4(p[0], p[1], p[2], p[3]);
    }
    // ---- stage S_pre^T (fp32 -> fp16) ----
    #pragma unroll
    for (int it = 0; it < 4; ++it) {
        int idx = tid + 256 * it;            // float4 idx 0..1023
        int row = idx >> 4, c4 = idx & 15;
        float4 p = __ldg((const float4*)Sp + idx);
        *(uint2*)(smh + HP + row * LQH + c4 * 4) =
            make_uint2(pack_h2(p.x, p.y), pack_h2(p.z, p.w));
    }
    if (tid < HDim) smf[FZ + tid] = __ldg(zp + tid);
    __syncthreads();

    // ---- qz = q . z_pre (partial den), 2 threads per row ----
    {
        const int r = tid >> 1, hf = tid & 1;
        const __half2* qrow = (const __half2*)(smh + HQ + r * LQH + hf * 32);
        const float* zz = smf + FZ + hf * 32;
        float s = 0.f;
        #pragma unroll
        for (int d = 0; d < 16; ++d) {
            float2 q2 = __half22float2(qrow[d]);
            s += q2.x * zz[2 * d] + q2.y * zz[2 * d + 1];
        }
        s += __shfl_xor_sync(0xffffffffu, s, 1);
        if (hf == 0) smf[FDN + r] = s;
    }

    const int r0 = w * 16 + g;
    const int r1 = r0 + 8;

    const uint32_t aqBase = smb + 2u * ((uint32_t)HQ + (uint32_t)(w * 16 + l15) * LQH + hi8);
    const uint32_t bkBase = smb + 2u * ((uint32_t)HK + (uint32_t)l7 * LQH + b8);
    const uint32_t bpBase = smb + 2u * ((uint32_t)HP + (uint32_t)l7 * LQH + b8);
    const uint32_t asBase = smb + 2u * ((uint32_t)HS + (uint32_t)(w * 16 + l15) * LSH + hi8);
    const uint32_t bvBase = smb + 2u * ((uint32_t)HV + (uint32_t)l7 * LSH + b8);

    // Q fragments (k = 64 -> 4 k16 steps), reused by mma1 and mma-pre
    uint32_t aq[4][4];
    #pragma unroll
    for (int k16 = 0; k16 < 4; ++k16) ldsm4(aq[k16], aqBase + k16 * 32);

    // ---- mma1: scores = Q K^T (16 x 128 per warp) ----
    float acc1[16][4];
    #pragma unroll
    for (int ni = 0; ni < 16; ++ni)
        #pragma unroll
        for (int j = 0; j < 4; ++j) acc1[ni][j] = 0.f;

    #pragma unroll
    for (int k16 = 0; k16 < 4; ++k16) {
        #pragma unroll
        for (int ni = 0; ni < 16; ++ni) {
            uint32_t bk[2];
            ldsm2(bk, bkBase + (uint32_t)(ni * 8 * LQH) * 2 + k16 * 32);
            mma_f16(acc1[ni][0], acc1[ni][1], acc1[ni][2], acc1[ni][3],
                    aq[k16][0], aq[k16][1], aq[k16][2], aq[k16][3], bk[0], bk[1]);
        }
    }

    // ---- mask (col <= row), rowsum, store fp16 scores ----
    float rs0 = 0.f, rs1 = 0.f;
    #pragma unroll
    for (int ni = 0; ni < 16; ++ni) {
        const int cb = ni * 8 + 2 * t;
        float m0 = (cb     <= r0) ? acc1[ni][0] : 0.f;
        float m1 = (cb + 1 <= r0) ? acc1[ni][1] : 0.f;
        float m2 = (cb     <= r1) ? acc1[ni][2] : 0.f;
        float m3 = (cb + 1 <= r1) ? acc1[ni][3] : 0.f;
        rs0 += m0 + m1;
        rs1 += m2 + m3;
        *(uint32_t*)(smh + HS + r0 * LSH + cb) = pack_h2(m0, m1);
        *(uint32_t*)(smh + HS + r1 * LSH + cb) = pack_h2(m2, m3);
    }
    rs0 += __shfl_xor_sync(0xffffffffu, rs0, 1);
    rs0 += __shfl_xor_sync(0xffffffffu, rs0, 2);
    rs1 += __shfl_xor_sync(0xffffffffu, rs1, 1);
    rs1 += __shfl_xor_sync(0xffffffffu, rs1, 2);
    __syncwarp();
    if (t == 0) {
        smf[FDN + r0] = 1.f / (smf[FDN + r0] + rs0);
        smf[FDN + r1] = 1.f / (smf[FDN + r1] + rs1);
    }
    __syncwarp();
    const float inv0 = smf[FDN + r0];
    const float inv1 = smf[FDN + r1];

    // ---- mma-pre: accO = Q S_pre (16 x 64 per warp) ----
    float accO[8][4];
    #pragma unroll
    for (int ni = 0; ni < 8; ++ni)
        #pragma unroll
        for (int j = 0; j < 4; ++j) accO[ni][j] = 0.f;

    #pragma unroll
    for (int k16 = 0; k16 < 4; ++k16) {
        #pragma unroll
        for (int ni = 0; ni < 8; ++ni) {
            uint32_t bp[2];
            ldsm2(bp, bpBase + (uint32_t)(ni * 8 * LQH) * 2 + k16 * 32);
            mma_f16(accO[ni][0], accO[ni][1], accO[ni][2], accO[ni][3],
                    aq[k16][0], aq[k16][1], aq[k16][2], aq[k16][3], bp[0], bp[1]);
        }
    }

    // ---- mma2: accO += scores V (k = 128 -> 8 k16 steps) ----
    #pragma unroll
    for (int k16 = 0; k16 < 8; ++k16) {
        uint32_t as[4];
        ldsm4(as, asBase + k16 * 32);
        #pragma unroll
        for (int ni = 0; ni < 8; ++ni) {
            uint32_t bv[2];
            ldsm2(bv, bvBase + (uint32_t)(ni * 8 * LSH) * 2 + k16 * 32);
            mma_f16(accO[ni][0], accO[ni][1], accO[ni][2], accO[ni][3],
                    as[0], as[1], as[2], as[3], bv[0], bv[1]);
        }
    }

    // ---- epilogue: fp16 store to g_attn ----
    #pragma unroll
    for (int ni = 0; ni < 8; ++ni) {
        const int e0 = ni * 8 + 2 * t;
        uint32_t o0 = pack_h2(accO[ni][0] * inv0 + EPSC, accO[ni][1] * inv0 + EPSC);
        uint32_t o1 = pack_h2(accO[ni][2] * inv1 + EPSC, accO[ni][3] * inv1 + EPSC);
        *(uint32_t*)(ga + (size_t)r0 * Dmod + e0) = o0;
        *(uint32_t*)(ga + (size_t)r1 * Dmod + e0) = o1;
    }
}

// ---------------------------------------------------------------------------
extern "C" void kernel_launch(void* const* d_in, const int* in_sizes, int n_in,
                              void* d_out, int out_size) {
    const float* x  = (const float*)d_in[0];
    const float* Wq = (const float*)d_in[1];
    const float* Wk = (const float*)d_in[2];
    const float* Wv = (const float*)d_in[3];
    const float* Wo = (const float*)d_in[4];
    float* out = (float*)d_out;

    cudaFuncSetAttribute(mma_gemm, cudaFuncAttributeMaxDynamicSharedMemorySize,
                         GEMM_SMEM_BYTES);
    cudaFuncSetAttribute(attn_local, cudaFuncAttributeMaxDynamicSharedMemorySize,
                         P1_SMEM_BYTES);
    cudaFuncSetAttribute(attn_out, cudaFuncAttributeMaxDynamicSharedMemorySize,
                         AO_SMEM_BYTES);

    conv_fp16<<<2048, 256>>>((const float4*)x, (const float4*)Wq,
                             (const float4*)Wk, (const float4*)Wv,
                             (const float4*)Wo);
    mma_gemm<<<dim3(Dmod / 128, Mrows / 128, 3), 256, GEMM_SMEM_BYTES>>>(nullptr, 0);
    attn_local<<<NBH * NCH, 128, P1_SMEM_BYTES>>>();
    attn_scan<<<NBH * 4, 256>>>();
    attn_out<<<NBH * NCH, 256, AO_SMEM_BYTES>>>();
    mma_gemm<<<dim3(Dmod / 128, Mrows / 128, 1), 256, GEMM_SMEM_BYTES>>>(out, 1);
}

// round 11
// speedup vs baseline: 9.7421x; 1.0974x over previous
#include <cuda_runtime.h>
#include <cuda_fp16.h>
#include <math.h>
#include <stdint.h>

// Problem constants
#define Bsz   4
#define Lseq  4096
#define Dmod  1024
#define Hn    16
#define HDim  64
#define CH    128
#define NCH   32
#define Mrows (Bsz*Lseq)          // 16384
#define NBH   (Bsz*Hn)            // 64
#define EPSC  1e-12f

// Scratch (device globals — allocation-free per harness rules)
__device__ __half g_q[(size_t)NBH*Lseq*HDim];        // (b,h,l,d) fp16
__device__ __half g_k[(size_t)NBH*Lseq*HDim];
__device__ __half g_v[(size_t)NBH*Lseq*HDim];
__device__ __half g_attn[(size_t)Bsz*Lseq*Dmod];     // (b,l,D) fp16
__device__ __half g_xt[(size_t)Mrows*Dmod];          // X in fp16
__device__ __half g_wt[(size_t)4*Dmod*Dmod];         // Wq,Wk,Wv,Wo fp16
// chunk-scan state (fp32, TRANSPOSED e-major: S^T[e][d])
__device__ float g_Sloc[(size_t)NBH*NCH*HDim*HDim];
__device__ float g_Spre[(size_t)NBH*NCH*HDim*HDim];
__device__ float g_zloc[(size_t)NBH*NCH*HDim];
__device__ float g_zpre[(size_t)NBH*NCH*HDim];

// ---------------------------------------------------------------------------
// PTX helpers
// ---------------------------------------------------------------------------
__device__ __forceinline__ uint32_t smem_u32(const void* p) {
    uint32_t a;
    asm("{ .reg .u64 t; cvta.to.shared.u64 t, %1; cvt.u32.u64 %0, t; }" : "=r"(a) : "l"(p));
    return a;
}
__device__ __forceinline__ uint32_t pack_h2(float a, float b) {
    __half2 h = __floats2half2_rn(a, b);
    return *(uint32_t*)&h;
}
__device__ __forceinline__ void cp_async16(uint32_t smem, const void* g) {
    asm volatile("cp.async.cg.shared.global [%0], [%1], 16;" :: "r"(smem), "l"(g));
}
#define CP_COMMIT() asm volatile("cp.async.commit_group;" ::: "memory")
#define CP_WAIT1()  asm volatile("cp.async.wait_group 1;" ::: "memory")

__device__ __forceinline__ void mma_f16(float& c0, float& c1, float& c2, float& c3,
                                        uint32_t a0, uint32_t a1, uint32_t a2, uint32_t a3,
                                        uint32_t b0, uint32_t b1) {
    asm volatile(
        "mma.sync.aligned.m16n8k16.row.col.f32.f16.f16.f32 "
        "{%0,%1,%2,%3}, {%4,%5,%6,%7}, {%8,%9}, {%0,%1,%2,%3};"
        : "+f"(c0), "+f"(c1), "+f"(c2), "+f"(c3)
        : "r"(a0), "r"(a1), "r"(a2), "r"(a3), "r"(b0), "r"(b1));
}
__device__ __forceinline__ void ldsm4(uint32_t* r, uint32_t addr) {
    asm volatile("ldmatrix.sync.aligned.m8n8.x4.shared.b16 {%0,%1,%2,%3}, [%4];"
                 : "=r"(r[0]), "=r"(r[1]), "=r"(r[2]), "=r"(r[3]) : "r"(addr));
}
__device__ __forceinline__ void ldsm2(uint32_t* r, uint32_t addr) {
    asm volatile("ldmatrix.sync.aligned.m8n8.x2.shared.b16 {%0,%1}, [%2];"
                 : "=r"(r[0]), "=r"(r[1]) : "r"(addr));
}

// ---------------------------------------------------------------------------
// One-time fp16 conversion of X and the four weight matrices.
// ---------------------------------------------------------------------------
#define XN8 (Mrows*Dmod/8)
#define WN8 (Dmod*Dmod/8)
#define TOTN8 (XN8 + 4*WN8)

__global__ __launch_bounds__(256) void conv_fp16(const float4* __restrict__ x,
                                                 const float4* __restrict__ wq,
                                                 const float4* __restrict__ wk,
                                                 const float4* __restrict__ wv,
                                                 const float4* __restrict__ wo) {
    const int stride = gridDim.x * blockDim.x;
    for (int i = blockIdx.x * blockDim.x + threadIdx.x; i < TOTN8; i += stride) {
        const float4* src;
        uint4* dst;
        if (i < XN8) {
            src = x + (size_t)i * 2;
            dst = (uint4*)g_xt + i;
        } else {
            const int r = i - XN8;
            const int w = r >> 17;
            const int off = r & (WN8 - 1);
            const float4* s = (w == 0) ? wq : (w == 1) ? wk : (w == 2) ? wv : wo;
            src = s + (size_t)off * 2;
            dst = (uint4*)g_wt + (size_t)w * WN8 + off;
        }
        float4 lo = __ldg(src);
        float4 hi = __ldg(src + 1);
        *dst = make_uint4(pack_h2(lo.x, lo.y), pack_h2(lo.z, lo.w),
                          pack_h2(hi.x, hi.y), pack_h2(hi.z, hi.w));
    }
}

// ---------------------------------------------------------------------------
// fp16 m16n8k16 GEMM: C[m][n] = sum_k A[m][k] * W[n][k]
// CTA 128x128, BK=64, 8 warps (2x4 -> 64x32 warp tiles).
// cp.async 3-stage pipeline, ONE sync + ONE wait per K-tile.
// ---------------------------------------------------------------------------
#define BKH 64
#define LDPH 72
#define TILE_HALVES (128 * LDPH)
#define STAGE_HALVES (2 * TILE_HALVES)
#define STAGE_BYTES (STAGE_HALVES * 2)      // 36864
#define NSTAGE 3
#define GEMM_SMEM_BYTES (NSTAGE * STAGE_BYTES)  // 110592

__global__ __launch_bounds__(256, 2) void mma_gemm(float* __restrict__ OutPlain,
                                                   int mode) {
    extern __shared__ __align__(16) __half smh[];
    const uint32_t smb = smem_u32(smh);

    const int tid  = threadIdx.x;
    const int wid  = tid >> 5;
    const int lane = tid & 31;
    const int g    = lane >> 2;
    const int t    = lane & 3;

    const int w = blockIdx.z;
    const __half* A  = (mode == 1) ? g_attn : g_xt;
    const __half* Wm = g_wt + (size_t)((mode == 1) ? 3 : w) * Dmod * Dmod;
    __half* outp = (w == 0) ? g_q : (w == 1) ? g_k : g_v;

    const int rowBase = blockIdx.y * 128;
    const int colBase = blockIdx.x * 128;
    const int mBase = (wid >> 2) * 64;
    const int nBase = (wid & 3) * 32;

    // loader: 4 rows (stride 32) x one 16B group per thread per matrix
    const int ldRow = tid >> 3;
    const int ldC8  = tid & 7;
    const __half* aG = A  + (size_t)(rowBase + ldRow) * Dmod + ldC8 * 8;
    const __half* bG = Wm + (size_t)(colBase + ldRow) * Dmod + ldC8 * 8;
    uint32_t stDst[4];
    #pragma unroll
    for (int i = 0; i < 4; ++i)
        stDst[i] = smb + 2u * ((uint32_t)(ldRow + 32 * i) * LDPH + ldC8 * 8);

    // ldmatrix per-thread base addresses (stage 0)
    const int l15 = lane & 15;
    const int hi8 = (lane >> 4) * 8;
    const int l7  = lane & 7;
    const int b8  = ((lane >> 3) & 1) * 8;
    uint32_t aAddr[4], bAddr[4];
    #pragma unroll
    for (int mi = 0; mi < 4; ++mi)
        aAddr[mi] = smb + 2u * ((uint32_t)(mBase + mi * 16 + l15) * LDPH + hi8);
    #pragma unroll
    for (int ni = 0; ni < 4; ++ni)
        bAddr[ni] = smb + (uint32_t)TILE_HALVES * 2u
                  + 2u * ((uint32_t)(nBase + ni * 8 + l7) * LDPH + b8);

    float acc[4][4][4];
    #pragma unroll
    for (int mi = 0; mi < 4; ++mi)
        #pragma unroll
        for (int ni = 0; ni < 4; ++ni)
            #pragma unroll
            for (int j = 0; j < 4; ++j) acc[mi][ni][j] = 0.f;

    const int NKT = Dmod / BKH;   // 16

    auto issue_stage = [&](int kt) {
        const uint32_t sb = (uint32_t)(kt % NSTAGE) * STAGE_BYTES;
        #pragma unroll
        for (int i = 0; i < 4; ++i) {
            cp_async16(stDst[i] + sb, aG + (size_t)(32 * i) * Dmod + kt * BKH);
            cp_async16(stDst[i] + sb + TILE_HALVES * 2, bG + (size_t)(32 * i) * Dmod + kt * BKH);
        }
        CP_COMMIT();
    };

    issue_stage(0);
    issue_stage(1);

    for (int kt = 0; kt < NKT; ++kt) {
        CP_WAIT1();
        __syncthreads();

        const uint32_t sb = (uint32_t)(kt % NSTAGE) * STAGE_BYTES;
        #pragma unroll
        for (int k16 = 0; k16 < 4; ++k16) {
            const uint32_t kb = sb + k16 * 32;
            uint32_t af[4][4], bf[4][2];
            #pragma unroll
            for (int mi = 0; mi < 4; ++mi) ldsm4(af[mi], aAddr[mi] + kb);
            #pragma unroll
            for (int ni = 0; ni < 4; ++ni) ldsm2(bf[ni], bAddr[ni] + kb);
            #pragma unroll
            for (int mi = 0; mi < 4; ++mi)
                #pragma unroll
                for (int ni = 0; ni < 4; ++ni)
                    mma_f16(acc[mi][ni][0], acc[mi][ni][1], acc[mi][ni][2], acc[mi][ni][3],
                            af[mi][0], af[mi][1], af[mi][2], af[mi][3],
                            bf[ni][0], bf[ni][1]);
        }
        if (kt + 2 < NKT) issue_stage(kt + 2);
        else CP_COMMIT();   // empty group keeps wait_group count invariant
    }

    const bool do_elu = (mode == 0) && (w < 2);
    #pragma unroll
    for (int mi = 0; mi < 4; ++mi) {
        #pragma unroll
        for (int ni = 0; ni < 4; ++ni) {
            const int m0 = rowBase + mBase + mi * 16 + g;
            const int n  = colBase + nBase + ni * 8 + 2 * t;
            #pragma unroll
            for (int half_ = 0; half_ < 2; ++half_) {
                const int m = m0 + half_ * 8;
                float v0 = acc[mi][ni][2 * half_ + 0];
                float v1 = acc[mi][ni][2 * half_ + 1];
                if (do_elu) {
                    v0 = (v0 > 0.f) ? (v0 + 1.f) : expf(v0);
                    v1 = (v1 > 0.f) ? (v1 + 1.f) : expf(v1);
                }
                if (mode == 0) {
                    const int hh = n >> 6;
                    const int dd = n & 63;
                    const int bb = m >> 12;
                    const int ll = m & (Lseq - 1);
                    __half* dst = outp + (((size_t)(bb * Hn + hh) * Lseq + ll) * HDim + dd);
                    *(uint32_t*)dst = pack_h2(v0, v1);
                } else {
                    float* dst = OutPlain + (size_t)m * Dmod + n;
                    *(float2*)dst = make_float2(v0, v1);
                }
            }
        }
    }
}

// ---------------------------------------------------------------------------
// Pass 1 (fp16 tensor cores): SlocT[e][d] = sum_s V[s,e] K[s,d], zloc from K.
// ---------------------------------------------------------------------------
#define LTH 136
#define P1_SMEM_BYTES (2 * 64 * LTH * 2)   // 34816

__global__ __launch_bounds__(128) void attn_local() {
    extern __shared__ __align__(16) __half smh[];
    const uint32_t smb = smem_u32(smh);
    __half* Vt = smh;               // [e][s] 64 x 136
    __half* Kt = smh + 64 * LTH;    // [d][s] 64 x 136

    const int tid  = threadIdx.x;
    const int w    = tid >> 5;
    const int lane = tid & 31;
    const int g    = lane >> 2;
    const int t    = lane & 3;
    const int l15 = lane & 15;
    const int hi8 = (lane >> 4) * 8;
    const int l7  = lane & 7;
    const int b8  = ((lane >> 3) & 1) * 8;

    const int bc = blockIdx.x;
    const int bh = bc >> 5;
    const int c  = bc & 31;

    const __half* gk = g_k + ((size_t)bh * Lseq + (size_t)c * CH) * HDim;
    const __half* gv = g_v + ((size_t)bh * Lseq + (size_t)c * CH) * HDim;

    #pragma unroll
    for (int it = 0; it < 8; ++it) {
        int task = tid + 128 * it;           // 0..1023
        int e = task & 63, s8 = task >> 6;   // s8: 0..15
        uint32_t p[4];
        #pragma unroll
        for (int j = 0; j < 4; ++j) {
            __half a = __ldg(gv + (size_t)(s8 * 8 + 2 * j + 0) * HDim + e);
            __half b = __ldg(gv + (size_t)(s8 * 8 + 2 * j + 1) * HDim + e);
            p[j] = *(uint16_t*)&a | ((uint32_t)*(uint16_t*)&b << 16);
        }
        *(uint4*)(Vt + e * LTH + s8 * 8) = make_uint4(p[0], p[1], p[2], p[3]);
        #pragma unroll
        for (int j = 0; j < 4; ++j) {
            __half a = __ldg(gk + (size_t)(s8 * 8 + 2 * j + 0) * HDim + e);
            __half b = __ldg(gk + (size_t)(s8 * 8 + 2 * j + 1) * HDim + e);
            p[j] = *(uint16_t*)&a | ((uint32_t)*(uint16_t*)&b << 16);
        }
        *(uint4*)(Kt + e * LTH + s8 * 8) = make_uint4(p[0], p[1], p[2], p[3]);
    }
    __syncthreads();

    {
        const int d = tid >> 1, hf = tid & 1;
        const __half2* kr = (const __half2*)(Kt + d * LTH + hf * 64);
        float zs = 0.f;
        #pragma unroll
        for (int s = 0; s < 32; ++s) {
            float2 f = __half22float2(kr[s]);
            zs += f.x + f.y;
        }
        zs += __shfl_xor_sync(0xffffffffu, zs, 1);
        if (hf == 0) g_zloc[(size_t)bc * HDim + d] = zs;
    }

    const int r0 = w * 16 + g;
    const int r1 = r0 + 8;
    const uint32_t avBase = smb + 2u * ((uint32_t)(w * 16 + l15) * LTH + hi8);
    const uint32_t bkBase = smb + 2u * ((uint32_t)(64 * LTH) + (uint32_t)l7 * LTH + b8);

    float acc[8][4];
    #pragma unroll
    for (int ni = 0; ni < 8; ++ni)
        #pragma unroll
        for (int j = 0; j < 4; ++j) acc[ni][j] = 0.f;

    #pragma unroll
    for (int k16 = 0; k16 < 8; ++k16) {
        uint32_t av[4];
        ldsm4(av, avBase + k16 * 32);
        #pragma unroll
        for (int ni = 0; ni < 8; ++ni) {
            uint32_t bk[2];
            ldsm2(bk, bkBase + (uint32_t)(ni * 8 * LTH) * 2 + k16 * 32);
            mma_f16(acc[ni][0], acc[ni][1], acc[ni][2], acc[ni][3],
                    av[0], av[1], av[2], av[3], bk[0], bk[1]);
        }
    }

    float* So = g_Sloc + (size_t)bc * (HDim * HDim);
    #pragma unroll
    for (int ni = 0; ni < 8; ++ni) {
        const int d0 = ni * 8 + 2 * t;
        *(float2*)(So + (size_t)r0 * HDim + d0) = make_float2(acc[ni][0], acc[ni][1]);
        *(float2*)(So + (size_t)r1 * HDim + d0) = make_float2(acc[ni][2], acc[ni][3]);
    }
}

// ---------------------------------------------------------------------------
// Pass 2: exclusive prefix over 32 chunks, 4-way split, software-pipelined.
// ---------------------------------------------------------------------------
__global__ __launch_bounds__(256) void attn_scan() {
    const int tid = threadIdx.x;
    const int bh  = blockIdx.x >> 2;
    const int qt  = blockIdx.x & 3;
    const int eoff = qt * 1024 + tid * 4;
    const bool doz = (qt == 0) && (tid < HDim);

    const size_t base0 = (size_t)bh * NCH * (HDim * HDim);
    const size_t zb0   = (size_t)bh * NCH * HDim + tid;

    float4 acc = make_float4(0.f, 0.f, 0.f, 0.f);
    float accz = 0.f;
    float4 nxt = *(const float4*)(g_Sloc + base0 + eoff);
    float nz = doz ? g_zloc[zb0] : 0.f;

    for (int c = 0; c < NCH; ++c) {
        const size_t base = base0 + (size_t)c * (HDim * HDim);
        float4 cur = nxt;
        float cz = nz;
        if (c + 1 < NCH) {
            nxt = *(const float4*)(g_Sloc + base + (HDim * HDim) + eoff);
            if (doz) nz = g_zloc[zb0 + (size_t)(c + 1) * HDim];
        }
        *(float4*)(g_Spre + base + eoff) = acc;
        acc.x += cur.x; acc.y += cur.y; acc.z += cur.z; acc.w += cur.w;
        if (doz) {
            g_zpre[zb0 + (size_t)c * HDim] = accz;
            accz += cz;
        }
    }
}

// ---------------------------------------------------------------------------
// Pass 3: per-(bh,chunk) output, all-fp16 mma. 256 threads = 8 warps, 2 CTAs/SM.
// ---------------------------------------------------------------------------
#define LQH 72
#define LSH 136
#define HQ  0
#define HK  (HQ + 128*LQH)
#define HS  (HK + 128*LQH)
#define HV  (HS + 128*LSH)
#define HP  (HV + 64*LSH)
#define HEND (HP + 64*LQH)
#define FZ  (HEND/2)
#define FDN (FZ + 64)
#define AO_SMEM_BYTES ((FDN + 128) * 4)   // 99072

__global__ __launch_bounds__(256, 2) void attn_out() {
    extern __shared__ __align__(16) __half smh[];
    const uint32_t smb = smem_u32(smh);
    float* smf = (float*)smh;

    const int tid  = threadIdx.x;
    const int w    = tid >> 5;
    const int lane = tid & 31;
    const int g    = lane >> 2;
    const int t    = lane & 3;
    const int l15 = lane & 15;
    const int hi8 = (lane >> 4) * 8;
    const int l7  = lane & 7;
    const int b8  = ((lane >> 3) & 1) * 8;

    const int bc = blockIdx.x;
    const int bh = bc >> 5;
    const int c  = bc & 31;

    const __half* gq = g_q + ((size_t)bh * Lseq + (size_t)c * CH) * HDim;
    const __half* gk = g_k + ((size_t)bh * Lseq + (size_t)c * CH) * HDim;
    const __half* gv = g_v + ((size_t)bh * Lseq + (size_t)c * CH) * HDim;
    const float* Sp = g_Spre + (size_t)bc * HDim * HDim;
    const float* zp = g_zpre + (size_t)bc * HDim;
    __half* ga = g_attn + (size_t)(bh >> 4) * Lseq * Dmod
                        + ((size_t)c * CH) * Dmod + (size_t)(bh & 15) * HDim;

    #pragma unroll
    for (int it = 0; it < 4; ++it) {
        int idx = tid + 256 * it;
        int row = idx >> 3, c8 = idx & 7;
        *(uint4*)(smh + HQ + row * LQH + c8 * 8) = __ldg((const uint4*)gq + idx);
        *(uint4*)(smh + HK + row * LQH + c8 * 8) = __ldg((const uint4*)gk + idx);
    }
    #pragma unroll
    for (int it = 0; it < 4; ++it) {
        int task = tid + 256 * it;
        int e = task & 63, s8 = task >> 6;
        uint32_t p[4];
        #pragma unroll
        for (int j = 0; j < 4; ++j) {
            __half a = __ldg(gv + (size_t)(s8 * 8 + 2 * j + 0) * HDim + e);
            __half b = __ldg(gv + (size_t)(s8 * 8 + 2 * j + 1) * HDim + e);
            p[j] = *(uint16_t*)&a | ((uint32_t)*(uint16_t*)&b << 16);
        }
        *(uint4*)(smh + HV + e * LSH + s8 * 8) = make_uint4(p[0], p[1], p[2], p[3]);
    }
    #pragma unroll
    for (int it = 0; it < 4; ++it) {
        int idx = tid + 256 * it;
        int row = idx >> 4, c4 = idx & 15;
        float4 p = __ldg((const float4*)Sp + idx);
        *(uint2*)(smh + HP + row * LQH + c4 * 4) =
            make_uint2(pack_h2(p.x, p.y), pack_h2(p.z, p.w));
    }
    if (tid < HDim) smf[FZ + tid] = __ldg(zp + tid);
    __syncthreads();

    {
        const int r = tid >> 1, hf = tid & 1;
        const __half2* qrow = (const __half2*)(smh + HQ + r * LQH + hf * 32);
        const float* zz = smf + FZ + hf * 32;
        float s = 0.f;
        #pragma unroll
        for (int d = 0; d < 16; ++d) {
            float2 q2 = __half22float2(qrow[d]);
            s += q2.x * zz[2 * d] + q2.y * zz[2 * d + 1];
        }
        s += __shfl_xor_sync(0xffffffffu, s, 1);
        if (hf == 0) smf[FDN + r] = s;
    }

    const int r0 = w * 16 + g;
    const int r1 = r0 + 8;

    const uint32_t aqBase = smb + 2u * ((uint32_t)HQ + (uint32_t)(w * 16 + l15) * LQH + hi8);
    const uint32_t bkBase = smb + 2u * ((uint32_t)HK + (uint32_t)l7 * LQH + b8);
    const uint32_t bpBase = smb + 2u * ((uint32_t)HP + (uint32_t)l7 * LQH + b8);
    const uint32_t asBase = smb + 2u * ((uint32_t)HS + (uint32_t)(w * 16 + l15) * LSH + hi8);
    const uint32_t bvBase = smb + 2u * ((uint32_t)HV + (uint32_t)l7 * LSH + b8);

    uint32_t aq[4][4];
    #pragma unroll
    for (int k16 = 0; k16 < 4; ++k16) ldsm4(aq[k16], aqBase + k16 * 32);

    float acc1[16][4];
    #pragma unroll
    for (int ni = 0; ni < 16; ++ni)
        #pragma unroll
        for (int j = 0; j < 4; ++j) acc1[ni][j] = 0.f;

    #pragma unroll
    for (int k16 = 0; k16 < 4; ++k16) {
        #pragma unroll
        for (int ni = 0; ni < 16; ++ni) {
            uint32_t bk[2];
            ldsm2(bk, bkBase + (uint32_t)(ni * 8 * LQH) * 2 + k16 * 32);
            mma_f16(acc1[ni][0], acc1[ni][1], acc1[ni][2], acc1[ni][3],
                    aq[k16][0], aq[k16][1], aq[k16][2], aq[k16][3], bk[0], bk[1]);
        }
    }

    float rs0 = 0.f, rs1 = 0.f;
    #pragma unroll
    for (int ni = 0; ni < 16; ++ni) {
        const int cb = ni * 8 + 2 * t;
        float m0 = (cb     <= r0) ? acc1[ni][0] : 0.f;
        float m1 = (cb + 1 <= r0) ? acc1[ni][1] : 0.f;
        float m2 = (cb     <= r1) ? acc1[ni][2] : 0.f;
        float m3 = (cb + 1 <= r1) ? acc1[ni][3] : 0.f;
        rs0 += m0 + m1;
        rs1 += m2 + m3;
        *(uint32_t*)(smh + HS + r0 * LSH + cb) = pack_h2(m0, m1);
        *(uint32_t*)(smh + HS + r1 * LSH + cb) = pack_h2(m2, m3);
    }
    rs0 += __shfl_xor_sync(0xffffffffu, rs0, 1);
    rs0 += __shfl_xor_sync(0xffffffffu, rs0, 2);
    rs1 += __shfl_xor_sync(0xffffffffu, rs1, 1);
    rs1 += __shfl_xor_sync(0xffffffffu, rs1, 2);
    __syncwarp();
    if (t == 0) {
        smf[FDN + r0] = 1.f / (smf[FDN + r0] + rs0);
        smf[FDN + r1] = 1.f / (smf[FDN + r1] + rs1);
    }
    __syncwarp();
    const float inv0 = smf[FDN + r0];
    const float inv1 = smf[FDN + r1];

    float accO[8][4];
    #pragma unroll
    for (int ni = 0; ni < 8; ++ni)
        #pragma unroll
        for (int j = 0; j < 4; ++j) accO[ni][j] = 0.f;

    #pragma unroll
    for (int k16 = 0; k16 < 4; ++k16) {
        #pragma unroll
        for (int ni = 0; ni < 8; ++ni) {
            uint32_t bp[2];
            ldsm2(bp, bpBase + (uint32_t)(ni * 8 * LQH) * 2 + k16 * 32);
            mma_f16(accO[ni][0], accO[ni][1], accO[ni][2], accO[ni][3],
                    aq[k16][0], aq[k16][1], aq[k16][2], aq[k16][3], bp[0], bp[1]);
        }
    }

    #pragma unroll
    for (int k16 = 0; k16 < 8; ++k16) {
        uint32_t as[4];
        ldsm4(as, asBase + k16 * 32);
        #pragma unroll
        for (int ni = 0; ni < 8; ++ni) {
            uint32_t bv[2];
            ldsm2(bv, bvBase + (uint32_t)(ni * 8 * LSH) * 2 + k16 * 32);
            mma_f16(accO[ni][0], accO[ni][1], accO[ni][2], accO[ni][3],
                    as[0], as[1], as[2], as[3], bv[0], bv[1]);
        }
    }

    #pragma unroll
    for (int ni = 0; ni < 8; ++ni) {
        const int e0 = ni * 8 + 2 * t;
        uint32_t o0 = pack_h2(accO[ni][0] * inv0 + EPSC, accO[ni][1] * inv0 + EPSC);
        uint32_t o1 = pack_h2(accO[ni][2] * inv1 + EPSC, accO[ni][3] * inv1 + EPSC);
        *(uint32_t*)(ga + (size_t)r0 * Dmod + e0) = o0;
        *(uint32_t*)(ga + (size_t)r1 * Dmod + e0) = o1;
    }
}

// ---------------------------------------------------------------------------
extern "C" void kernel_launch(void* const* d_in, const int* in_sizes, int n_in,
                              void* d_out, int out_size) {
    const float* x  = (const float*)d_in[0];
    const float* Wq = (const float*)d_in[1];
    const float* Wk = (const float*)d_in[2];
    const float* Wv = (const float*)d_in[3];
    const float* Wo = (const float*)d_in[4];
    float* out = (float*)d_out;

    cudaFuncSetAttribute(mma_gemm, cudaFuncAttributeMaxDynamicSharedMemorySize,
                         GEMM_SMEM_BYTES);
    cudaFuncSetAttribute(attn_local, cudaFuncAttributeMaxDynamicSharedMemorySize,
                         P1_SMEM_BYTES);
    cudaFuncSetAttribute(attn_out, cudaFuncAttributeMaxDynamicSharedMemorySize,
                         AO_SMEM_BYTES);

    conv_fp16<<<2048, 256>>>((const float4*)x, (const float4*)Wq,
                             (const float4*)Wk, (const float4*)Wv,
                             (const float4*)Wo);
    mma_gemm<<<dim3(Dmod / 128, Mrows / 128, 3), 256, GEMM_SMEM_BYTES>>>(nullptr, 0);
    attn_local<<<NBH * NCH, 128, P1_SMEM_BYTES>>>();
    attn_scan<<<NBH * 4, 256>>>();
    attn_out<<<NBH * NCH, 256, AO_SMEM_BYTES>>>();
    mma_gemm<<<dim3(Dmod / 128, Mrows / 128, 1), 256, GEMM_SMEM_BYTES>>>(out, 1);
}